// round 5
// baseline (speedup 1.0000x reference)
#include <cuda_runtime.h>
#include <cuda_bf16.h>
#include <math.h>
#include <stdint.h>

#define Bb 4096
#define Tt 32
#define Cc 180
#define Hh 6
#define HDd 30
#define Ff 720
#define EPS 1e-5f
#define ROWS (Bb*Tt)
#define NQ 576                 // padded 3*C for QKV GEMM (9 tiles of 64)

// ============================================================================
// Device scratch
// ============================================================================
__device__ float g_X2[(size_t)ROWS * Cc];
__device__ float g_QKVS[(size_t)ROWS * NQ];       // [row][ q(180) k(180) v(180) pad ]
__device__ __nv_bfloat16 g_WQHI[NQ * 192];        // QKV^T [n][k]
__device__ __nv_bfloat16 g_WQLO[NQ * 192];
__device__ __nv_bfloat16 g_W1HI[768 * 192];
__device__ __nv_bfloat16 g_W1LO[768 * 192];
__device__ __nv_bfloat16 g_W2HI[192 * 768];
__device__ __nv_bfloat16 g_W2LO[192 * 768];

// ============================================================================
// helpers
// ============================================================================
__device__ __forceinline__ unsigned smem_u32(const void* p) {
    unsigned a;
    asm("{ .reg .u64 t; cvta.to.shared.u64 t, %1; cvt.u32.u64 %0, t; }" : "=r"(a) : "l"(p));
    return a;
}
__device__ __forceinline__ void ldsm_x4(unsigned* r, unsigned addr) {
    asm volatile("ldmatrix.sync.aligned.m8n8.x4.shared.b16 {%0,%1,%2,%3}, [%4];"
                 : "=r"(r[0]), "=r"(r[1]), "=r"(r[2]), "=r"(r[3]) : "r"(addr));
}
__device__ __forceinline__ void mma16816(float* c, const unsigned* a, const unsigned* b) {
    asm volatile(
        "mma.sync.aligned.m16n8k16.row.col.f32.bf16.bf16.f32 "
        "{%0,%1,%2,%3}, {%4,%5,%6,%7}, {%8,%9}, {%0,%1,%2,%3};"
        : "+f"(c[0]), "+f"(c[1]), "+f"(c[2]), "+f"(c[3])
        : "r"(a[0]), "r"(a[1]), "r"(a[2]), "r"(a[3]), "r"(b[0]), "r"(b[1]));
}
__device__ __forceinline__ void split2(float v0, float v1, unsigned& hp, unsigned& lp) {
    __nv_bfloat16 h0 = __float2bfloat16(v0);
    __nv_bfloat16 l0 = __float2bfloat16(v0 - __bfloat162float(h0));
    __nv_bfloat16 h1 = __float2bfloat16(v1);
    __nv_bfloat16 l1 = __float2bfloat16(v1 - __bfloat162float(h1));
    __nv_bfloat162 hh = __halves2bfloat162(h0, h1);
    __nv_bfloat162 ll = __halves2bfloat162(l0, l1);
    hp = *reinterpret_cast<unsigned*>(&hh);
    lp = *reinterpret_cast<unsigned*>(&ll);
}

// ============================================================================
// Prep kernels
// ============================================================================
__global__ void prep_wqkv(const float* __restrict__ wq, const float* __restrict__ wk,
                          const float* __restrict__ wv) {
    for (int i = blockIdx.x * blockDim.x + threadIdx.x; i < NQ * 192; i += gridDim.x * blockDim.x) {
        int n = i / 192, k = i % 192;
        float v = 0.f;
        if (n < 540 && k < Cc) {
            int mat = n / Cc, m = n % Cc;
            int hh = m / HDd, d = m % HDd;
            const float* W = (mat == 0 ? wq : (mat == 1 ? wk : wv));
            v = W[(size_t)hh * (Cc*HDd) + (size_t)k * HDd + d];
        }
        __nv_bfloat16 h = __float2bfloat16(v);
        g_WQHI[i] = h;
        g_WQLO[i] = __float2bfloat16(v - __bfloat162float(h));
    }
}
__global__ void prep_w1(const float* __restrict__ w1) {
    for (int i = blockIdx.x * blockDim.x + threadIdx.x; i < 768 * 192; i += gridDim.x * blockDim.x) {
        int n = i / 192, k = i % 192;
        float v = (n < Ff && k < Cc) ? w1[(size_t)k * Ff + n] : 0.f;
        __nv_bfloat16 h = __float2bfloat16(v);
        g_W1HI[i] = h;
        g_W1LO[i] = __float2bfloat16(v - __bfloat162float(h));
    }
}
__global__ void prep_w2(const float* __restrict__ w2) {
    for (int i = blockIdx.x * blockDim.x + threadIdx.x; i < 192 * 768; i += gridDim.x * blockDim.x) {
        int n = i / 768, k = i % 768;
        float v = (n < Cc && k < Ff) ? w2[(size_t)k * Cc + n] : 0.f;
        __nv_bfloat16 h = __float2bfloat16(v);
        g_W2HI[i] = h;
        g_W2LO[i] = __float2bfloat16(v - __bfloat162float(h));
    }
}

// ============================================================================
// Kernel 1: LN1 + QKV GEMM (HMMA split-3) -> g_QKVS
// ============================================================================
#define NT2 256
#define A1HI  0
#define A1LO  51200
#define B1HI  102400
#define B1LO  128000
#define SMQ_TOTAL 153600

__global__ void __launch_bounds__(NT2, 1) ln1qkv_kernel(
    const float* __restrict__ x,
    const float* __restrict__ g1, const float* __restrict__ be1)
{
    extern __shared__ char sm2[];
    const unsigned sb = smem_u32(sm2);
    const int tid = threadIdx.x;
    const int w   = tid >> 5;
    const int ln  = tid & 31;
    const int g   = ln >> 2;
    const int ti  = ln & 3;
    const size_t row0 = (size_t)blockIdx.x * 128;

    // ---- LN1 + hi/lo split -> A1 [128][192 bf16, stride 400B] ----
    for (int r = w; r < 128; r += 8) {
        const float* xr = x + (row0 + r) * Cc;
        float s = 0.f, s2 = 0.f;
        for (int c = ln; c < Cc; c += 32) { float v = xr[c]; s += v; s2 += v*v; }
        #pragma unroll
        for (int o = 16; o; o >>= 1) {
            s  += __shfl_xor_sync(0xffffffffu, s,  o);
            s2 += __shfl_xor_sync(0xffffffffu, s2, o);
        }
        float mu = s * (1.f/Cc);
        float inv = rsqrtf(s2 * (1.f/Cc) - mu*mu + EPS);
        for (int cp = ln; cp < 96; cp += 32) {
            int c0 = cp * 2;
            float v0 = (c0   < Cc) ? (xr[c0]  -mu)*inv*g1[c0]   + be1[c0]   : 0.f;
            float v1 = (c0+1 < Cc) ? (xr[c0+1]-mu)*inv*g1[c0+1] + be1[c0+1] : 0.f;
            unsigned hp, lp;
            split2(v0, v1, hp, lp);
            unsigned off = (unsigned)(r*400 + c0*2);
            *(unsigned*)(sm2 + A1HI + off) = hp;
            *(unsigned*)(sm2 + A1LO + off) = lp;
        }
    }
    __syncthreads();

    const unsigned a1addr = sb + A1HI + (unsigned)((w*16 + (ln & 15))*400 + (ln >> 4)*16);
    const int brow = ln & 7;
    const int bk   = ((ln >> 3) & 1) * 16;
    const int bsel = (ln >> 4);

    for (int nt = 0; nt < 9; nt++) {
        for (int i = tid; i < 1536; i += NT2) {
            int nn = i / 24, k8 = i % 24;
            unsigned so = (unsigned)(nn*400 + k8*16);
            size_t go = (size_t)(nt*64 + nn)*192 + k8*8;
            *(uint4*)(sm2 + B1HI + so) = *(const uint4*)(g_WQHI + go);
            *(uint4*)(sm2 + B1LO + so) = *(const uint4*)(g_WQLO + go);
        }
        __syncthreads();

        float C1[32];
        #pragma unroll
        for (int i = 0; i < 32; i++) C1[i] = 0.f;
        for (int ka = 0; ka < 12; ka++) {
            unsigned ahi[4], alo[4];
            ldsm_x4(ahi, a1addr + ka*32);
            ldsm_x4(alo, a1addr + (A1LO - A1HI) + ka*32);
            #pragma unroll
            for (int na = 0; na < 8; na++) {
                unsigned bf[4];
                unsigned baddr = sb + B1HI + (unsigned)((na*8 + brow)*400 + ka*32 + bk)
                               + (unsigned)(bsel * (B1LO - B1HI));
                ldsm_x4(bf, baddr);
                mma16816(C1 + na*4, ahi, bf);
                mma16816(C1 + na*4, alo, bf);
                mma16816(C1 + na*4, ahi, bf + 2);
            }
        }

        // epilogue: C fragments -> g_QKVS (f32)
        {
            size_t rA = row0 + w*16 + g;
            size_t rB = rA + 8;
            #pragma unroll
            for (int na = 0; na < 8; na++) {
                int col = nt*64 + na*8 + 2*ti;
                *(float2*)(g_QKVS + rA*NQ + col) = make_float2(C1[na*4+0], C1[na*4+1]);
                *(float2*)(g_QKVS + rB*NQ + col) = make_float2(C1[na*4+2], C1[na*4+3]);
            }
        }
        __syncthreads();
    }
}

// ============================================================================
// Kernel 2: scores + softmax + A@V + residual -> g_X2  (scalar)
// ============================================================================
#define NT3 256
#define SMA_QKV 0
#define SMA_X   (Tt*NQ)                 // 18432
#define SMA_S   (SMA_X + Tt*Cc)         // 24192
#define SMA_TOTAL (SMA_S + Hh*Tt*Tt)    // 30336 floats

__global__ void __launch_bounds__(NT3, 1) attn2_kernel(const float* __restrict__ x)
{
    extern __shared__ float sm[];
    float* qkv = sm + SMA_QKV;
    float* xs  = sm + SMA_X;
    float* ss  = sm + SMA_S;

    const int b   = blockIdx.x;
    const int tid = threadIdx.x;
    const int w   = tid >> 5;
    const int ln  = tid & 31;

    // load qkv rows (32 x 576) and x (32 x 180)
    {
        const float4* src = reinterpret_cast<const float4*>(g_QKVS + (size_t)b * (Tt*NQ));
        float4* dst = reinterpret_cast<float4*>(qkv);
        for (int i = tid; i < (Tt*NQ)/4; i += NT3) dst[i] = src[i];
        const float4* xg4 = reinterpret_cast<const float4*>(x + (size_t)b * (Tt*Cc));
        float4* xs4 = reinterpret_cast<float4*>(xs);
        for (int i = tid; i < (Tt*Cc)/4; i += NT3) xs4[i] = xg4[i];
    }
    __syncthreads();

    // scores + causal softmax
    for (int row = w; row < Hh*Tt; row += 8) {
        int hh = row >> 5, ti = row & 31;
        const float* qp = qkv + ti*NQ + hh*HDd;
        const float* kp = qkv + ln*NQ + Cc + hh*HDd;
        float dot = 0.f;
        #pragma unroll
        for (int d = 0; d < HDd; d++) dot += qp[d] * kp[d];
        dot *= 0.18257418583505537f;
        float val = (ln <= ti) ? dot : -1e30f;
        float m = val;
        #pragma unroll
        for (int o = 16; o; o >>= 1) m = fmaxf(m, __shfl_xor_sync(0xffffffffu, m, o));
        float e = (ln <= ti) ? __expf(val - m) : 0.f;
        float sum = e;
        #pragma unroll
        for (int o = 16; o; o >>= 1) sum += __shfl_xor_sync(0xffffffffu, sum, o);
        ss[hh*(Tt*Tt) + ti*Tt + ln] = e / sum;
    }
    __syncthreads();

    // attn @ V + residual
    for (int job = tid; job < 2*Cc; job += NT3) {
        int tg = job / Cc, n = job % Cc;
        int hh = n / HDd, d = n % HDd;
        int t0 = tg * 16;
        const float* vp = qkv + 2*Cc + hh*HDd + d;
        const float* sp = ss + hh*(Tt*Tt) + t0*Tt;
        float a[16];
        #pragma unroll
        for (int i = 0; i < 16; i++) a[i] = 0.f;
        #pragma unroll 4
        for (int tj = 0; tj < Tt; tj++) {
            float vv = vp[tj*NQ];
            #pragma unroll
            for (int i = 0; i < 16; i++) a[i] += sp[i*Tt + tj] * vv;
        }
        #pragma unroll
        for (int i = 0; i < 16; i++) xs[(t0+i)*Cc + n] += a[i];
    }
    __syncthreads();

    float* og = g_X2 + (size_t)b * (Tt*Cc);
    for (int i = tid; i < Tt*Cc; i += NT3) og[i] = xs[i];
}

// ============================================================================
// Kernel 3: LN2 + MLP (HMMA split-3) + residual -> out   (R4, proven)
// ============================================================================
#define B2HI  153600
#define B2LO  181248
#define SM2_TOTAL 208896

__global__ void __launch_bounds__(NT2, 1) mlp_kernel(
    const float* __restrict__ g2, const float* __restrict__ be2,
    const float* __restrict__ b1, const float* __restrict__ b2,
    float* __restrict__ out)
{
    extern __shared__ char sm2[];
    const unsigned sb = smem_u32(sm2);
    const int tid = threadIdx.x;
    const int w   = tid >> 5;
    const int ln  = tid & 31;
    const int g   = ln >> 2;
    const int ti  = ln & 3;
    const size_t row0 = (size_t)blockIdx.x * 128;

    for (int r = w; r < 128; r += 8) {
        const float* xr = g_X2 + (row0 + r) * Cc;
        float s = 0.f, s2 = 0.f;
        for (int c = ln; c < Cc; c += 32) { float v = xr[c]; s += v; s2 += v*v; }
        #pragma unroll
        for (int o = 16; o; o >>= 1) {
            s  += __shfl_xor_sync(0xffffffffu, s,  o);
            s2 += __shfl_xor_sync(0xffffffffu, s2, o);
        }
        float mu = s * (1.f/Cc);
        float inv = rsqrtf(s2 * (1.f/Cc) - mu*mu + EPS);
        for (int cp = ln; cp < 96; cp += 32) {
            int c0 = cp * 2;
            float v0 = (c0   < Cc) ? (xr[c0]  -mu)*inv*g2[c0]   + be2[c0]   : 0.f;
            float v1 = (c0+1 < Cc) ? (xr[c0+1]-mu)*inv*g2[c0+1] + be2[c0+1] : 0.f;
            unsigned hp, lp;
            split2(v0, v1, hp, lp);
            unsigned off = (unsigned)(r*400 + c0*2);
            *(unsigned*)(sm2 + A1HI + off) = hp;
            *(unsigned*)(sm2 + A1LO + off) = lp;
        }
    }
    __syncthreads();

    float C2[96];
    #pragma unroll
    for (int i = 0; i < 96; i++) C2[i] = 0.f;

    const unsigned a1addr = sb + A1HI + (unsigned)((w*16 + (ln & 15))*400 + (ln >> 4)*16);
    const int brow = ln & 7;
    const int bk   = ((ln >> 3) & 1) * 16;
    const int bsel = (ln >> 4);

    for (int nt = 0; nt < 12; nt++) {
        for (int i = tid; i < 1536; i += NT2) {
            int nn = i / 24, k8 = i % 24;
            unsigned so = (unsigned)(nn*400 + k8*16);
            size_t go = (size_t)(nt*64 + nn)*192 + k8*8;
            *(uint4*)(sm2 + B1HI + so) = *(const uint4*)(g_W1HI + go);
            *(uint4*)(sm2 + B1LO + so) = *(const uint4*)(g_W1LO + go);
        }
        for (int i = tid; i < 1536; i += NT2) {
            int nn = i / 8, k8 = i % 8;
            unsigned so = (unsigned)(nn*144 + k8*16);
            size_t go = (size_t)nn*768 + nt*64 + k8*8;
            *(uint4*)(sm2 + B2HI + so) = *(const uint4*)(g_W2HI + go);
            *(uint4*)(sm2 + B2LO + so) = *(const uint4*)(g_W2LO + go);
        }
        __syncthreads();

        float C1[32];
        #pragma unroll
        for (int i = 0; i < 32; i++) C1[i] = 0.f;
        for (int ka = 0; ka < 12; ka++) {
            unsigned ahi[4], alo[4];
            ldsm_x4(ahi, a1addr + ka*32);
            ldsm_x4(alo, a1addr + (A1LO - A1HI) + ka*32);
            #pragma unroll
            for (int na = 0; na < 8; na++) {
                unsigned bf[4];
                unsigned baddr = sb + B1HI + (unsigned)((na*8 + brow)*400 + ka*32 + bk)
                               + (unsigned)(bsel * (B1LO - B1HI));
                ldsm_x4(bf, baddr);
                mma16816(C1 + na*4, ahi, bf);
                mma16816(C1 + na*4, alo, bf);
                mma16816(C1 + na*4, ahi, bf + 2);
            }
        }

        unsigned a2hi[16], a2lo[16];
        #pragma unroll
        for (int j = 0; j < 4; j++) {
            const float* cA = C1 + (2*j)*4;
            const float* cB = C1 + (2*j+1)*4;
            int colA = nt*64 + 16*j + 2*ti;
            int colB = colA + 8;
            float bA0 = (colA   < Ff) ? __ldg(b1 + colA)     : 0.f;
            float bA1 = (colA+1 < Ff) ? __ldg(b1 + colA + 1) : 0.f;
            float bB0 = (colB   < Ff) ? __ldg(b1 + colB)     : 0.f;
            float bB1 = (colB+1 < Ff) ? __ldg(b1 + colB + 1) : 0.f;
            split2(fmaxf(cA[0]+bA0, 0.f), fmaxf(cA[1]+bA1, 0.f), a2hi[j*4+0], a2lo[j*4+0]);
            split2(fmaxf(cA[2]+bA0, 0.f), fmaxf(cA[3]+bA1, 0.f), a2hi[j*4+1], a2lo[j*4+1]);
            split2(fmaxf(cB[0]+bB0, 0.f), fmaxf(cB[1]+bB1, 0.f), a2hi[j*4+2], a2lo[j*4+2]);
            split2(fmaxf(cB[2]+bB0, 0.f), fmaxf(cB[3]+bB1, 0.f), a2hi[j*4+3], a2lo[j*4+3]);
        }

        #pragma unroll
        for (int ka = 0; ka < 4; ka++) {
            #pragma unroll
            for (int na = 0; na < 24; na++) {
                unsigned bf[4];
                unsigned baddr = sb + B2HI + (unsigned)((na*8 + brow)*144 + ka*32 + bk)
                               + (unsigned)(bsel * (B2LO - B2HI));
                ldsm_x4(bf, baddr);
                mma16816(C2 + na*4, a2hi + ka*4, bf);
                mma16816(C2 + na*4, a2lo + ka*4, bf);
                mma16816(C2 + na*4, a2hi + ka*4, bf + 2);
            }
        }
        __syncthreads();
    }

    {
        size_t rA = row0 + w*16 + g;
        size_t rB = rA + 8;
        #pragma unroll
        for (int na = 0; na < 24; na++) {
            int col = na*8 + 2*ti;
            if (col < Cc) {
                float b20 = __ldg(b2 + col), b21 = __ldg(b2 + col + 1);
                out[rA*Cc + col]     = C2[na*4+0] + b20 + g_X2[rA*Cc + col];
                out[rA*Cc + col + 1] = C2[na*4+1] + b21 + g_X2[rA*Cc + col + 1];
                out[rB*Cc + col]     = C2[na*4+2] + b20 + g_X2[rB*Cc + col];
                out[rB*Cc + col + 1] = C2[na*4+3] + b21 + g_X2[rB*Cc + col + 1];
            }
        }
    }
}

// ============================================================================
// Launch
// ============================================================================
extern "C" void kernel_launch(void* const* d_in, const int* in_sizes, int n_in,
                              void* d_out, int out_size) {
    const float* x   = (const float*)d_in[0];
    const float* wq  = (const float*)d_in[1];
    const float* wk  = (const float*)d_in[2];
    const float* wv  = (const float*)d_in[3];
    const float* g1  = (const float*)d_in[4];
    const float* be1 = (const float*)d_in[5];
    const float* g2  = (const float*)d_in[6];
    const float* be2 = (const float*)d_in[7];
    const float* w1  = (const float*)d_in[8];
    const float* b1  = (const float*)d_in[9];
    const float* w2  = (const float*)d_in[10];
    const float* b2  = (const float*)d_in[11];
    float* out = (float*)d_out;

    cudaFuncSetAttribute(ln1qkv_kernel, cudaFuncAttributeMaxDynamicSharedMemorySize, SMQ_TOTAL);
    cudaFuncSetAttribute(attn2_kernel, cudaFuncAttributeMaxDynamicSharedMemorySize,
                         SMA_TOTAL * (int)sizeof(float));
    cudaFuncSetAttribute(mlp_kernel, cudaFuncAttributeMaxDynamicSharedMemorySize, SM2_TOTAL);

    prep_wqkv<<<148, 256>>>(wq, wk, wv);
    prep_w1<<<148, 256>>>(w1);
    prep_w2<<<148, 256>>>(w2);
    ln1qkv_kernel<<<ROWS / 128, NT2, SMQ_TOTAL>>>(x, g1, be1);
    attn2_kernel<<<Bb, NT3, SMA_TOTAL * sizeof(float)>>>(x);
    mlp_kernel<<<ROWS / 128, NT2, SM2_TOTAL>>>(g2, be2, b1, b2, out);
}

// round 6
// speedup vs baseline: 1.6094x; 1.6094x over previous
#include <cuda_runtime.h>
#include <cuda_bf16.h>
#include <math.h>
#include <stdint.h>

#define Bb 4096
#define Tt 32
#define Cc 180
#define Hh 6
#define HDd 30
#define Ff 720
#define EPS 1e-5f
#define ROWS (Bb*Tt)
#define NQ 576                 // padded 3*C for QKV GEMM (9 tiles of 64)

// ============================================================================
// Device scratch
// ============================================================================
__device__ float g_X2[(size_t)ROWS * Cc];
__device__ float g_QKVS[(size_t)ROWS * NQ];       // [row][ q(180) k(180) v(180) pad ]
__device__ __nv_bfloat16 g_WQHI[NQ * 192];        // QKV^T [n][k]
__device__ __nv_bfloat16 g_WQLO[NQ * 192];
__device__ __nv_bfloat16 g_W1HI[768 * 192];
__device__ __nv_bfloat16 g_W1LO[768 * 192];
__device__ __nv_bfloat16 g_W2HI[192 * 768];
__device__ __nv_bfloat16 g_W2LO[192 * 768];

// ============================================================================
// helpers
// ============================================================================
__device__ __forceinline__ unsigned smem_u32(const void* p) {
    unsigned a;
    asm("{ .reg .u64 t; cvta.to.shared.u64 t, %1; cvt.u32.u64 %0, t; }" : "=r"(a) : "l"(p));
    return a;
}
__device__ __forceinline__ void ldsm_x4(unsigned* r, unsigned addr) {
    asm volatile("ldmatrix.sync.aligned.m8n8.x4.shared.b16 {%0,%1,%2,%3}, [%4];"
                 : "=r"(r[0]), "=r"(r[1]), "=r"(r[2]), "=r"(r[3]) : "r"(addr));
}
__device__ __forceinline__ void mma16816(float* c, const unsigned* a, const unsigned* b) {
    asm volatile(
        "mma.sync.aligned.m16n8k16.row.col.f32.bf16.bf16.f32 "
        "{%0,%1,%2,%3}, {%4,%5,%6,%7}, {%8,%9}, {%0,%1,%2,%3};"
        : "+f"(c[0]), "+f"(c[1]), "+f"(c[2]), "+f"(c[3])
        : "r"(a[0]), "r"(a[1]), "r"(a[2]), "r"(a[3]), "r"(b[0]), "r"(b[1]));
}
__device__ __forceinline__ void split2(float v0, float v1, unsigned& hp, unsigned& lp) {
    __nv_bfloat16 h0 = __float2bfloat16(v0);
    __nv_bfloat16 l0 = __float2bfloat16(v0 - __bfloat162float(h0));
    __nv_bfloat16 h1 = __float2bfloat16(v1);
    __nv_bfloat16 l1 = __float2bfloat16(v1 - __bfloat162float(h1));
    __nv_bfloat162 hh = __halves2bfloat162(h0, h1);
    __nv_bfloat162 ll = __halves2bfloat162(l0, l1);
    hp = *reinterpret_cast<unsigned*>(&hh);
    lp = *reinterpret_cast<unsigned*>(&ll);
}

// ============================================================================
// Prep kernels
// ============================================================================
__global__ void prep_wqkv(const float* __restrict__ wq, const float* __restrict__ wk,
                          const float* __restrict__ wv) {
    for (int i = blockIdx.x * blockDim.x + threadIdx.x; i < NQ * 192; i += gridDim.x * blockDim.x) {
        int n = i / 192, k = i % 192;
        float v = 0.f;
        if (n < 540 && k < Cc) {
            int mat = n / Cc, m = n % Cc;
            int hh = m / HDd, d = m % HDd;
            const float* W = (mat == 0 ? wq : (mat == 1 ? wk : wv));
            v = W[(size_t)hh * (Cc*HDd) + (size_t)k * HDd + d];
        }
        __nv_bfloat16 h = __float2bfloat16(v);
        g_WQHI[i] = h;
        g_WQLO[i] = __float2bfloat16(v - __bfloat162float(h));
    }
}
__global__ void prep_w1(const float* __restrict__ w1) {
    for (int i = blockIdx.x * blockDim.x + threadIdx.x; i < 768 * 192; i += gridDim.x * blockDim.x) {
        int n = i / 192, k = i % 192;
        float v = (n < Ff && k < Cc) ? w1[(size_t)k * Ff + n] : 0.f;
        __nv_bfloat16 h = __float2bfloat16(v);
        g_W1HI[i] = h;
        g_W1LO[i] = __float2bfloat16(v - __bfloat162float(h));
    }
}
__global__ void prep_w2(const float* __restrict__ w2) {
    for (int i = blockIdx.x * blockDim.x + threadIdx.x; i < 192 * 768; i += gridDim.x * blockDim.x) {
        int n = i / 768, k = i % 768;
        float v = (n < Cc && k < Ff) ? w2[(size_t)k * Cc + n] : 0.f;
        __nv_bfloat16 h = __float2bfloat16(v);
        g_W2HI[i] = h;
        g_W2LO[i] = __float2bfloat16(v - __bfloat162float(h));
    }
}

// ============================================================================
// Kernel 1: LN1 + QKV GEMM (HMMA split-3) -> g_QKVS
// ============================================================================
#define NT2 256
#define A1HI  0
#define A1LO  51200
#define B1HI  102400
#define B1LO  128000
#define SMQ_TOTAL 153600

__global__ void __launch_bounds__(NT2, 1) ln1qkv_kernel(
    const float* __restrict__ x,
    const float* __restrict__ g1, const float* __restrict__ be1)
{
    extern __shared__ char sm2[];
    const unsigned sb = smem_u32(sm2);
    const int tid = threadIdx.x;
    const int w   = tid >> 5;
    const int ln  = tid & 31;
    const int g   = ln >> 2;
    const int ti  = ln & 3;
    const size_t row0 = (size_t)blockIdx.x * 128;

    for (int r = w; r < 128; r += 8) {
        const float* xr = x + (row0 + r) * Cc;
        float s = 0.f, s2 = 0.f;
        for (int c = ln; c < Cc; c += 32) { float v = xr[c]; s += v; s2 += v*v; }
        #pragma unroll
        for (int o = 16; o; o >>= 1) {
            s  += __shfl_xor_sync(0xffffffffu, s,  o);
            s2 += __shfl_xor_sync(0xffffffffu, s2, o);
        }
        float mu = s * (1.f/Cc);
        float inv = rsqrtf(s2 * (1.f/Cc) - mu*mu + EPS);
        for (int cp = ln; cp < 96; cp += 32) {
            int c0 = cp * 2;
            float v0 = (c0   < Cc) ? (xr[c0]  -mu)*inv*g1[c0]   + be1[c0]   : 0.f;
            float v1 = (c0+1 < Cc) ? (xr[c0+1]-mu)*inv*g1[c0+1] + be1[c0+1] : 0.f;
            unsigned hp, lp;
            split2(v0, v1, hp, lp);
            unsigned off = (unsigned)(r*400 + c0*2);
            *(unsigned*)(sm2 + A1HI + off) = hp;
            *(unsigned*)(sm2 + A1LO + off) = lp;
        }
    }
    __syncthreads();

    const unsigned a1addr = sb + A1HI + (unsigned)((w*16 + (ln & 15))*400 + (ln >> 4)*16);
    const int brow = ln & 7;
    const int bk   = ((ln >> 3) & 1) * 16;
    const int bsel = (ln >> 4);

    for (int nt = 0; nt < 9; nt++) {
        for (int i = tid; i < 1536; i += NT2) {
            int nn = i / 24, k8 = i % 24;
            unsigned so = (unsigned)(nn*400 + k8*16);
            size_t go = (size_t)(nt*64 + nn)*192 + k8*8;
            *(uint4*)(sm2 + B1HI + so) = *(const uint4*)(g_WQHI + go);
            *(uint4*)(sm2 + B1LO + so) = *(const uint4*)(g_WQLO + go);
        }
        __syncthreads();

        float C1[32];
        #pragma unroll
        for (int i = 0; i < 32; i++) C1[i] = 0.f;
        for (int ka = 0; ka < 12; ka++) {
            unsigned ahi[4], alo[4];
            ldsm_x4(ahi, a1addr + ka*32);
            ldsm_x4(alo, a1addr + (A1LO - A1HI) + ka*32);
            #pragma unroll
            for (int na = 0; na < 8; na++) {
                unsigned bf[4];
                unsigned baddr = sb + B1HI + (unsigned)((na*8 + brow)*400 + ka*32 + bk)
                               + (unsigned)(bsel * (B1LO - B1HI));
                ldsm_x4(bf, baddr);
                mma16816(C1 + na*4, ahi, bf);
                mma16816(C1 + na*4, alo, bf);
                mma16816(C1 + na*4, ahi, bf + 2);
            }
        }

        {
            size_t rA = row0 + w*16 + g;
            size_t rB = rA + 8;
            #pragma unroll
            for (int na = 0; na < 8; na++) {
                int col = nt*64 + na*8 + 2*ti;
                *(float2*)(g_QKVS + rA*NQ + col) = make_float2(C1[na*4+0], C1[na*4+1]);
                *(float2*)(g_QKVS + rB*NQ + col) = make_float2(C1[na*4+2], C1[na*4+3]);
            }
        }
        __syncthreads();
    }
}

// ============================================================================
// Kernel 2: softmax + A@V + residual -> g_X2
// CTA = 64 threads = 2 warps; grid (Bb, 3); warp wi handles head 2*hp+wi.
// smem ~32KB -> ~7 CTAs/SM, latency hidden.
// ============================================================================
#define PD31 31
#define PT33 33
#define SMH_Q 0
#define SMH_K (2*Tt*PD31)                 // 1984
#define SMH_V (4*Tt*PD31)                 // 3968
#define SMH_S (6*Tt*PD31)                 // 5952
#define SMH_TOTAL (SMH_S + 2*Tt*PT33)     // 8064 floats = 32256 B

__global__ void __launch_bounds__(64, 7) attn2_kernel(const float* __restrict__ x)
{
    extern __shared__ float sm[];
    const int b   = blockIdx.x;
    const int hp  = blockIdx.y;           // head pair 0..2
    const int tid = threadIdx.x;
    const int wi  = tid >> 5;             // 0,1
    const int ln  = tid & 31;

    // ---- load q,k,v for heads 2hp, 2hp+1 (coalesced 120B segments) ----
    const float* base = g_QKVS + (size_t)b * (Tt*NQ);
    #pragma unroll
    for (int m = 0; m < 3; m++) {
        float* dst = sm + m * (2*Tt*PD31);
        for (int e = tid; e < 2*Tt*HDd; e += 64) {
            int hl = e / (Tt*HDd);
            int rem = e - hl*(Tt*HDd);
            int r = rem / HDd, d = rem - r*HDd;
            dst[hl*(Tt*PD31) + r*PD31 + d] = base[(size_t)r*NQ + m*Cc + (hp*2+hl)*HDd + d];
        }
    }
    __syncthreads();

    const float* qsw = sm + SMH_Q + wi*(Tt*PD31);
    const float* ksw = sm + SMH_K + wi*(Tt*PD31);
    const float* vsw = sm + SMH_V + wi*(Tt*PD31);
    float* ssw = sm + SMH_S + wi*(Tt*PT33);

    // ---- scores + causal softmax: lane = tj ----
    for (int ti = 0; ti < Tt; ti++) {
        const float* qp = qsw + ti*PD31;
        const float* kp = ksw + ln*PD31;
        float dot = 0.f;
        #pragma unroll
        for (int d = 0; d < HDd; d++) dot += qp[d] * kp[d];
        dot *= 0.18257418583505537f;
        float val = (ln <= ti) ? dot : -1e30f;
        float m = val;
        #pragma unroll
        for (int o = 16; o; o >>= 1) m = fmaxf(m, __shfl_xor_sync(0xffffffffu, m, o));
        float e = (ln <= ti) ? __expf(val - m) : 0.f;
        float sum = e;
        #pragma unroll
        for (int o = 16; o; o >>= 1) sum += __shfl_xor_sync(0xffffffffu, sum, o);
        ssw[ti*PT33 + ln] = e / sum;
    }
    __syncwarp();

    // ---- A@V: lane = ti, accumulate 30 dims in regs ----
    float acc[HDd];
    #pragma unroll
    for (int d = 0; d < HDd; d++) acc[d] = 0.f;
    const float* prow = ssw + ln*PT33;
    #pragma unroll 4
    for (int tj = 0; tj < Tt; tj++) {
        float p = prow[tj];
        const float* vr = vsw + tj*PD31;
        #pragma unroll
        for (int d = 0; d < HDd; d++) acc[d] += p * vr[d];
    }

    // ---- residual + store ----
    {
        size_t off = ((size_t)b*Tt + ln) * Cc + (hp*2 + wi)*HDd;
        const float* xr = x + off;
        float* og = g_X2 + off;
        #pragma unroll
        for (int d = 0; d < HDd; d++) og[d] = xr[d] + acc[d];
    }
}

// ============================================================================
// Kernel 3: LN2 + MLP (HMMA split-3) + residual -> out   (R4, proven)
// ============================================================================
#define B2HI  153600
#define B2LO  181248
#define SM2_TOTAL 208896

__global__ void __launch_bounds__(NT2, 1) mlp_kernel(
    const float* __restrict__ g2, const float* __restrict__ be2,
    const float* __restrict__ b1, const float* __restrict__ b2,
    float* __restrict__ out)
{
    extern __shared__ char sm2[];
    const unsigned sb = smem_u32(sm2);
    const int tid = threadIdx.x;
    const int w   = tid >> 5;
    const int ln  = tid & 31;
    const int g   = ln >> 2;
    const int ti  = ln & 3;
    const size_t row0 = (size_t)blockIdx.x * 128;

    for (int r = w; r < 128; r += 8) {
        const float* xr = g_X2 + (row0 + r) * Cc;
        float s = 0.f, s2 = 0.f;
        for (int c = ln; c < Cc; c += 32) { float v = xr[c]; s += v; s2 += v*v; }
        #pragma unroll
        for (int o = 16; o; o >>= 1) {
            s  += __shfl_xor_sync(0xffffffffu, s,  o);
            s2 += __shfl_xor_sync(0xffffffffu, s2, o);
        }
        float mu = s * (1.f/Cc);
        float inv = rsqrtf(s2 * (1.f/Cc) - mu*mu + EPS);
        for (int cp = ln; cp < 96; cp += 32) {
            int c0 = cp * 2;
            float v0 = (c0   < Cc) ? (xr[c0]  -mu)*inv*g2[c0]   + be2[c0]   : 0.f;
            float v1 = (c0+1 < Cc) ? (xr[c0+1]-mu)*inv*g2[c0+1] + be2[c0+1] : 0.f;
            unsigned hp, lp;
            split2(v0, v1, hp, lp);
            unsigned off = (unsigned)(r*400 + c0*2);
            *(unsigned*)(sm2 + A1HI + off) = hp;
            *(unsigned*)(sm2 + A1LO + off) = lp;
        }
    }
    __syncthreads();

    float C2[96];
    #pragma unroll
    for (int i = 0; i < 96; i++) C2[i] = 0.f;

    const unsigned a1addr = sb + A1HI + (unsigned)((w*16 + (ln & 15))*400 + (ln >> 4)*16);
    const int brow = ln & 7;
    const int bk   = ((ln >> 3) & 1) * 16;
    const int bsel = (ln >> 4);

    for (int nt = 0; nt < 12; nt++) {
        for (int i = tid; i < 1536; i += NT2) {
            int nn = i / 24, k8 = i % 24;
            unsigned so = (unsigned)(nn*400 + k8*16);
            size_t go = (size_t)(nt*64 + nn)*192 + k8*8;
            *(uint4*)(sm2 + B1HI + so) = *(const uint4*)(g_W1HI + go);
            *(uint4*)(sm2 + B1LO + so) = *(const uint4*)(g_W1LO + go);
        }
        for (int i = tid; i < 1536; i += NT2) {
            int nn = i / 8, k8 = i % 8;
            unsigned so = (unsigned)(nn*144 + k8*16);
            size_t go = (size_t)nn*768 + nt*64 + k8*8;
            *(uint4*)(sm2 + B2HI + so) = *(const uint4*)(g_W2HI + go);
            *(uint4*)(sm2 + B2LO + so) = *(const uint4*)(g_W2LO + go);
        }
        __syncthreads();

        float C1[32];
        #pragma unroll
        for (int i = 0; i < 32; i++) C1[i] = 0.f;
        for (int ka = 0; ka < 12; ka++) {
            unsigned ahi[4], alo[4];
            ldsm_x4(ahi, a1addr + ka*32);
            ldsm_x4(alo, a1addr + (A1LO - A1HI) + ka*32);
            #pragma unroll
            for (int na = 0; na < 8; na++) {
                unsigned bf[4];
                unsigned baddr = sb + B1HI + (unsigned)((na*8 + brow)*400 + ka*32 + bk)
                               + (unsigned)(bsel * (B1LO - B1HI));
                ldsm_x4(bf, baddr);
                mma16816(C1 + na*4, ahi, bf);
                mma16816(C1 + na*4, alo, bf);
                mma16816(C1 + na*4, ahi, bf + 2);
            }
        }

        unsigned a2hi[16], a2lo[16];
        #pragma unroll
        for (int j = 0; j < 4; j++) {
            const float* cA = C1 + (2*j)*4;
            const float* cB = C1 + (2*j+1)*4;
            int colA = nt*64 + 16*j + 2*ti;
            int colB = colA + 8;
            float bA0 = (colA   < Ff) ? __ldg(b1 + colA)     : 0.f;
            float bA1 = (colA+1 < Ff) ? __ldg(b1 + colA + 1) : 0.f;
            float bB0 = (colB   < Ff) ? __ldg(b1 + colB)     : 0.f;
            float bB1 = (colB+1 < Ff) ? __ldg(b1 + colB + 1) : 0.f;
            split2(fmaxf(cA[0]+bA0, 0.f), fmaxf(cA[1]+bA1, 0.f), a2hi[j*4+0], a2lo[j*4+0]);
            split2(fmaxf(cA[2]+bA0, 0.f), fmaxf(cA[3]+bA1, 0.f), a2hi[j*4+1], a2lo[j*4+1]);
            split2(fmaxf(cB[0]+bB0, 0.f), fmaxf(cB[1]+bB1, 0.f), a2hi[j*4+2], a2lo[j*4+2]);
            split2(fmaxf(cB[2]+bB0, 0.f), fmaxf(cB[3]+bB1, 0.f), a2hi[j*4+3], a2lo[j*4+3]);
        }

        #pragma unroll
        for (int ka = 0; ka < 4; ka++) {
            #pragma unroll
            for (int na = 0; na < 24; na++) {
                unsigned bf[4];
                unsigned baddr = sb + B2HI + (unsigned)((na*8 + brow)*144 + ka*32 + bk)
                               + (unsigned)(bsel * (B2LO - B2HI));
                ldsm_x4(bf, baddr);
                mma16816(C2 + na*4, a2hi + ka*4, bf);
                mma16816(C2 + na*4, a2lo + ka*4, bf);
                mma16816(C2 + na*4, a2hi + ka*4, bf + 2);
            }
        }
        __syncthreads();
    }

    {
        size_t rA = row0 + w*16 + g;
        size_t rB = rA + 8;
        #pragma unroll
        for (int na = 0; na < 24; na++) {
            int col = na*8 + 2*ti;
            if (col < Cc) {
                float b20 = __ldg(b2 + col), b21 = __ldg(b2 + col + 1);
                out[rA*Cc + col]     = C2[na*4+0] + b20 + g_X2[rA*Cc + col];
                out[rA*Cc + col + 1] = C2[na*4+1] + b21 + g_X2[rA*Cc + col + 1];
                out[rB*Cc + col]     = C2[na*4+2] + b20 + g_X2[rB*Cc + col];
                out[rB*Cc + col + 1] = C2[na*4+3] + b21 + g_X2[rB*Cc + col + 1];
            }
        }
    }
}

// ============================================================================
// Launch
// ============================================================================
extern "C" void kernel_launch(void* const* d_in, const int* in_sizes, int n_in,
                              void* d_out, int out_size) {
    const float* x   = (const float*)d_in[0];
    const float* wq  = (const float*)d_in[1];
    const float* wk  = (const float*)d_in[2];
    const float* wv  = (const float*)d_in[3];
    const float* g1  = (const float*)d_in[4];
    const float* be1 = (const float*)d_in[5];
    const float* g2  = (const float*)d_in[6];
    const float* be2 = (const float*)d_in[7];
    const float* w1  = (const float*)d_in[8];
    const float* b1  = (const float*)d_in[9];
    const float* w2  = (const float*)d_in[10];
    const float* b2  = (const float*)d_in[11];
    float* out = (float*)d_out;

    cudaFuncSetAttribute(ln1qkv_kernel, cudaFuncAttributeMaxDynamicSharedMemorySize, SMQ_TOTAL);
    cudaFuncSetAttribute(attn2_kernel, cudaFuncAttributeMaxDynamicSharedMemorySize,
                         SMH_TOTAL * (int)sizeof(float));
    cudaFuncSetAttribute(mlp_kernel, cudaFuncAttributeMaxDynamicSharedMemorySize, SM2_TOTAL);

    prep_wqkv<<<148, 256>>>(wq, wk, wv);
    prep_w1<<<148, 256>>>(w1);
    prep_w2<<<148, 256>>>(w2);
    ln1qkv_kernel<<<ROWS / 128, NT2, SMQ_TOTAL>>>(x, g1, be1);
    dim3 agrid(Bb, 3);
    attn2_kernel<<<agrid, 64, SMH_TOTAL * sizeof(float)>>>(x);
    mlp_kernel<<<ROWS / 128, NT2, SM2_TOTAL>>>(g2, be2, b1, b2, out);
}

// round 7
// speedup vs baseline: 1.7351x; 1.0781x over previous
#include <cuda_runtime.h>
#include <cuda_bf16.h>
#include <math.h>
#include <stdint.h>

#define Bb 4096
#define Tt 32
#define Cc 180
#define Hh 6
#define HDd 30
#define Ff 720
#define EPS 1e-5f
#define ROWS (Bb*Tt)
#define NQ 576

// ============================================================================
// Device scratch
// ============================================================================
__device__ float g_X2[(size_t)ROWS * Cc];
__device__ float g_QKVS[(size_t)ROWS * NQ];
__device__ __nv_bfloat16 g_WQHI[NQ * 192];
__device__ __nv_bfloat16 g_WQLO[NQ * 192];
__device__ __nv_bfloat16 g_W1HI[768 * 192];
__device__ __nv_bfloat16 g_W1LO[768 * 192];
__device__ __nv_bfloat16 g_W2HI[192 * 768];
__device__ __nv_bfloat16 g_W2LO[192 * 768];

// ============================================================================
// helpers
// ============================================================================
__device__ __forceinline__ unsigned smem_u32(const void* p) {
    unsigned a;
    asm("{ .reg .u64 t; cvta.to.shared.u64 t, %1; cvt.u32.u64 %0, t; }" : "=r"(a) : "l"(p));
    return a;
}
__device__ __forceinline__ void ldsm_x4(unsigned* r, unsigned addr) {
    asm volatile("ldmatrix.sync.aligned.m8n8.x4.shared.b16 {%0,%1,%2,%3}, [%4];"
                 : "=r"(r[0]), "=r"(r[1]), "=r"(r[2]), "=r"(r[3]) : "r"(addr));
}
__device__ __forceinline__ void mma16816(float* c, const unsigned* a, const unsigned* b) {
    asm volatile(
        "mma.sync.aligned.m16n8k16.row.col.f32.bf16.bf16.f32 "
        "{%0,%1,%2,%3}, {%4,%5,%6,%7}, {%8,%9}, {%0,%1,%2,%3};"
        : "+f"(c[0]), "+f"(c[1]), "+f"(c[2]), "+f"(c[3])
        : "r"(a[0]), "r"(a[1]), "r"(a[2]), "r"(a[3]), "r"(b[0]), "r"(b[1]));
}
__device__ __forceinline__ void split2(float v0, float v1, unsigned& hp, unsigned& lp) {
    __nv_bfloat16 h0 = __float2bfloat16(v0);
    __nv_bfloat16 l0 = __float2bfloat16(v0 - __bfloat162float(h0));
    __nv_bfloat16 h1 = __float2bfloat16(v1);
    __nv_bfloat16 l1 = __float2bfloat16(v1 - __bfloat162float(h1));
    __nv_bfloat162 hh = __halves2bfloat162(h0, h1);
    __nv_bfloat162 ll = __halves2bfloat162(l0, l1);
    hp = *reinterpret_cast<unsigned*>(&hh);
    lp = *reinterpret_cast<unsigned*>(&ll);
}
#define CP_ASYNC16(dst, src) \
    asm volatile("cp.async.cg.shared.global [%0], [%1], 16;" :: "r"(dst), "l"(src))
#define CP_COMMIT() asm volatile("cp.async.commit_group;" ::: "memory")
#define CP_WAIT1()  asm volatile("cp.async.wait_group 1;" ::: "memory")
#define CP_WAIT0()  asm volatile("cp.async.wait_group 0;" ::: "memory")

// ============================================================================
// Prep (single kernel)
// ============================================================================
__global__ void prep_all(const float* __restrict__ wq, const float* __restrict__ wk,
                         const float* __restrict__ wv, const float* __restrict__ w1,
                         const float* __restrict__ w2) {
    const int NWQ = NQ * 192, NW1 = 768 * 192, NW2 = 192 * 768;
    for (int i = blockIdx.x * blockDim.x + threadIdx.x; i < NWQ + NW1 + NW2;
         i += gridDim.x * blockDim.x) {
        float v = 0.f;
        __nv_bfloat16 *hi, *lo;
        int j;
        if (i < NWQ) {
            j = i;
            int n = j / 192, k = j % 192;
            if (n < 540 && k < Cc) {
                int mat = n / Cc, m = n % Cc;
                int hh = m / HDd, d = m % HDd;
                const float* W = (mat == 0 ? wq : (mat == 1 ? wk : wv));
                v = W[(size_t)hh * (Cc*HDd) + (size_t)k * HDd + d];
            }
            hi = g_WQHI; lo = g_WQLO;
        } else if (i < NWQ + NW1) {
            j = i - NWQ;
            int n = j / 192, k = j % 192;
            if (n < Ff && k < Cc) v = w1[(size_t)k * Ff + n];
            hi = g_W1HI; lo = g_W1LO;
        } else {
            j = i - NWQ - NW1;
            int n = j / 768, k = j % 768;
            if (n < Cc && k < Ff) v = w2[(size_t)k * Cc + n];
            hi = g_W2HI; lo = g_W2LO;
        }
        __nv_bfloat16 h = __float2bfloat16(v);
        hi[j] = h;
        lo[j] = __float2bfloat16(v - __bfloat162float(h));
    }
}

// ============================================================================
// Kernel 1: LN1 + QKV GEMM (HMMA split-3, cp.async double-buffered B)
// ============================================================================
#define NT2 256
#define QA1HI 0
#define QA1LO 51200
#define QB0   102400
#define QB1   153600
#define QBSZ  25600          // 64 rows * 400B (HI); LO at +25600
#define SMQ_TOTAL 204800

__global__ void __launch_bounds__(NT2, 1) ln1qkv_kernel(
    const float* __restrict__ x,
    const float* __restrict__ g1, const float* __restrict__ be1)
{
    extern __shared__ char sm2[];
    const unsigned sb = smem_u32(sm2);
    const int tid = threadIdx.x;
    const int w   = tid >> 5;
    const int ln  = tid & 31;
    const int g   = ln >> 2;
    const int ti  = ln & 3;
    const size_t row0 = (size_t)blockIdx.x * 128;

    // prefetch B[0] into buf0
    {
        const unsigned dst = sb + QB0;
        for (int i = tid; i < 1536; i += NT2) {
            int nn = i / 24, k8 = i % 24;
            unsigned so = (unsigned)(nn*400 + k8*16);
            size_t go = (size_t)nn*192 + k8*8;
            CP_ASYNC16(dst + so, (const char*)(g_WQHI + go));
            CP_ASYNC16(dst + QBSZ + so, (const char*)(g_WQLO + go));
        }
        CP_COMMIT();
    }

    // ---- LN1 + hi/lo split -> A ----
    for (int r = w; r < 128; r += 8) {
        const float* xr = x + (row0 + r) * Cc;
        float s = 0.f, s2 = 0.f;
        for (int c = ln; c < Cc; c += 32) { float v = xr[c]; s += v; s2 += v*v; }
        #pragma unroll
        for (int o = 16; o; o >>= 1) {
            s  += __shfl_xor_sync(0xffffffffu, s,  o);
            s2 += __shfl_xor_sync(0xffffffffu, s2, o);
        }
        float mu = s * (1.f/Cc);
        float inv = rsqrtf(s2 * (1.f/Cc) - mu*mu + EPS);
        for (int cp = ln; cp < 96; cp += 32) {
            int c0 = cp * 2;
            float v0 = (c0   < Cc) ? (xr[c0]  -mu)*inv*g1[c0]   + be1[c0]   : 0.f;
            float v1 = (c0+1 < Cc) ? (xr[c0+1]-mu)*inv*g1[c0+1] + be1[c0+1] : 0.f;
            unsigned hp, lp;
            split2(v0, v1, hp, lp);
            unsigned off = (unsigned)(r*400 + c0*2);
            *(unsigned*)(sm2 + QA1HI + off) = hp;
            *(unsigned*)(sm2 + QA1LO + off) = lp;
        }
    }
    __syncthreads();

    const unsigned a1addr = sb + QA1HI + (unsigned)((w*16 + (ln & 15))*400 + (ln >> 4)*16);
    const int brow = ln & 7;
    const int bk   = ((ln >> 3) & 1) * 16;
    const int bsel = (ln >> 4);

    for (int nt = 0; nt < 9; nt++) {
        // prefetch next tile into alternate buffer
        if (nt < 8) {
            const unsigned dst = sb + ((nt+1) & 1 ? QB1 : QB0);
            for (int i = tid; i < 1536; i += NT2) {
                int nn = i / 24, k8 = i % 24;
                unsigned so = (unsigned)(nn*400 + k8*16);
                size_t go = (size_t)((nt+1)*64 + nn)*192 + k8*8;
                CP_ASYNC16(dst + so, (const char*)(g_WQHI + go));
                CP_ASYNC16(dst + QBSZ + so, (const char*)(g_WQLO + go));
            }
            CP_COMMIT();
            CP_WAIT1();
        } else {
            CP_WAIT0();
        }
        __syncthreads();

        const unsigned bbase = sb + (nt & 1 ? QB1 : QB0);
        float C1[32];
        #pragma unroll
        for (int i = 0; i < 32; i++) C1[i] = 0.f;
        for (int ka = 0; ka < 12; ka++) {
            unsigned ahi[4], alo[4];
            ldsm_x4(ahi, a1addr + ka*32);
            ldsm_x4(alo, a1addr + (QA1LO - QA1HI) + ka*32);
            #pragma unroll
            for (int na = 0; na < 8; na++) {
                unsigned bf[4];
                unsigned baddr = bbase + (unsigned)((na*8 + brow)*400 + ka*32 + bk)
                               + (unsigned)(bsel * QBSZ);
                ldsm_x4(bf, baddr);
                mma16816(C1 + na*4, ahi, bf);
                mma16816(C1 + na*4, alo, bf);
                mma16816(C1 + na*4, ahi, bf + 2);
            }
        }

        {
            size_t rA = row0 + w*16 + g;
            size_t rB = rA + 8;
            #pragma unroll
            for (int na = 0; na < 8; na++) {
                int col = nt*64 + na*8 + 2*ti;
                *(float2*)(g_QKVS + rA*NQ + col) = make_float2(C1[na*4+0], C1[na*4+1]);
                *(float2*)(g_QKVS + rB*NQ + col) = make_float2(C1[na*4+2], C1[na*4+3]);
            }
        }
        __syncthreads();
    }
}

// ============================================================================
// Kernel 2: softmax + A@V + residual -> g_X2  (R6, proven)
// ============================================================================
#define PD31 31
#define PT33 33
#define SMH_Q 0
#define SMH_K (2*Tt*PD31)
#define SMH_V (4*Tt*PD31)
#define SMH_S (6*Tt*PD31)
#define SMH_TOTAL (SMH_S + 2*Tt*PT33)

__global__ void __launch_bounds__(64, 7) attn2_kernel(const float* __restrict__ x)
{
    extern __shared__ float sm[];
    const int b   = blockIdx.x;
    const int hp  = blockIdx.y;
    const int tid = threadIdx.x;
    const int wi  = tid >> 5;
    const int ln  = tid & 31;

    const float* base = g_QKVS + (size_t)b * (Tt*NQ);
    #pragma unroll
    for (int m = 0; m < 3; m++) {
        float* dst = sm + m * (2*Tt*PD31);
        for (int e = tid; e < 2*Tt*HDd; e += 64) {
            int hl = e / (Tt*HDd);
            int rem = e - hl*(Tt*HDd);
            int r = rem / HDd, d = rem - r*HDd;
            dst[hl*(Tt*PD31) + r*PD31 + d] = base[(size_t)r*NQ + m*Cc + (hp*2+hl)*HDd + d];
        }
    }
    __syncthreads();

    const float* qsw = sm + SMH_Q + wi*(Tt*PD31);
    const float* ksw = sm + SMH_K + wi*(Tt*PD31);
    const float* vsw = sm + SMH_V + wi*(Tt*PD31);
    float* ssw = sm + SMH_S + wi*(Tt*PT33);

    for (int ti = 0; ti < Tt; ti++) {
        const float* qp = qsw + ti*PD31;
        const float* kp = ksw + ln*PD31;
        float dot = 0.f;
        #pragma unroll
        for (int d = 0; d < HDd; d++) dot += qp[d] * kp[d];
        dot *= 0.18257418583505537f;
        float val = (ln <= ti) ? dot : -1e30f;
        float m = val;
        #pragma unroll
        for (int o = 16; o; o >>= 1) m = fmaxf(m, __shfl_xor_sync(0xffffffffu, m, o));
        float e = (ln <= ti) ? __expf(val - m) : 0.f;
        float sum = e;
        #pragma unroll
        for (int o = 16; o; o >>= 1) sum += __shfl_xor_sync(0xffffffffu, sum, o);
        ssw[ti*PT33 + ln] = e / sum;
    }
    __syncwarp();

    float acc[HDd];
    #pragma unroll
    for (int d = 0; d < HDd; d++) acc[d] = 0.f;
    const float* prow = ssw + ln*PT33;
    #pragma unroll 4
    for (int tj = 0; tj < Tt; tj++) {
        float p = prow[tj];
        const float* vr = vsw + tj*PD31;
        #pragma unroll
        for (int d = 0; d < HDd; d++) acc[d] += p * vr[d];
    }

    {
        size_t off = ((size_t)b*Tt + ln) * Cc + (hp*2 + wi)*HDd;
        const float* xr = x + off;
        float* og = g_X2 + off;
        #pragma unroll
        for (int d = 0; d < HDd; d++) og[d] = xr[d] + acc[d];
    }
}

// ============================================================================
// Kernel 3: LN2 + MLP (HMMA split-3, cp.async pipelined) + residual -> out
// ============================================================================
#define A1HI  0
#define A1LO  51200
#define B1HI  102400
#define B1LO  128000
#define B2HI  153600
#define B2LO  181248
#define SM2_TOTAL 208896

__global__ void __launch_bounds__(NT2, 1) mlp_kernel(
    const float* __restrict__ g2, const float* __restrict__ be2,
    const float* __restrict__ b1, const float* __restrict__ b2,
    float* __restrict__ out)
{
    extern __shared__ char sm2[];
    const unsigned sb = smem_u32(sm2);
    const int tid = threadIdx.x;
    const int w   = tid >> 5;
    const int ln  = tid & 31;
    const int g   = ln >> 2;
    const int ti  = ln & 3;
    const size_t row0 = (size_t)blockIdx.x * 128;

    // prefetch B1[0], B2[0]
    for (int i = tid; i < 1536; i += NT2) {
        int nn = i / 24, k8 = i % 24;
        unsigned so = (unsigned)(nn*400 + k8*16);
        size_t go = (size_t)nn*192 + k8*8;
        CP_ASYNC16(sb + B1HI + so, (const char*)(g_W1HI + go));
        CP_ASYNC16(sb + B1LO + so, (const char*)(g_W1LO + go));
    }
    CP_COMMIT();
    for (int i = tid; i < 1536; i += NT2) {
        int nn = i / 8, k8 = i % 8;
        unsigned so = (unsigned)(nn*144 + k8*16);
        size_t go = (size_t)nn*768 + k8*8;
        CP_ASYNC16(sb + B2HI + so, (const char*)(g_W2HI + go));
        CP_ASYNC16(sb + B2LO + so, (const char*)(g_W2LO + go));
    }
    CP_COMMIT();

    // ---- LN2 + split -> A1 ----
    for (int r = w; r < 128; r += 8) {
        const float* xr = g_X2 + (row0 + r) * Cc;
        float s = 0.f, s2 = 0.f;
        for (int c = ln; c < Cc; c += 32) { float v = xr[c]; s += v; s2 += v*v; }
        #pragma unroll
        for (int o = 16; o; o >>= 1) {
            s  += __shfl_xor_sync(0xffffffffu, s,  o);
            s2 += __shfl_xor_sync(0xffffffffu, s2, o);
        }
        float mu = s * (1.f/Cc);
        float inv = rsqrtf(s2 * (1.f/Cc) - mu*mu + EPS);
        for (int cp = ln; cp < 96; cp += 32) {
            int c0 = cp * 2;
            float v0 = (c0   < Cc) ? (xr[c0]  -mu)*inv*g2[c0]   + be2[c0]   : 0.f;
            float v1 = (c0+1 < Cc) ? (xr[c0+1]-mu)*inv*g2[c0+1] + be2[c0+1] : 0.f;
            unsigned hp, lp;
            split2(v0, v1, hp, lp);
            unsigned off = (unsigned)(r*400 + c0*2);
            *(unsigned*)(sm2 + A1HI + off) = hp;
            *(unsigned*)(sm2 + A1LO + off) = lp;
        }
    }
    __syncthreads();

    float C2[96];
    #pragma unroll
    for (int i = 0; i < 96; i++) C2[i] = 0.f;

    const unsigned a1addr = sb + A1HI + (unsigned)((w*16 + (ln & 15))*400 + (ln >> 4)*16);
    const int brow = ln & 7;
    const int bk   = ((ln >> 3) & 1) * 16;
    const int bsel = (ln >> 4);

    for (int nt = 0; nt < 12; nt++) {
        // B1[nt] ready? (pending: {B1[nt], B2[nt]} -> complete B1[nt])
        CP_WAIT1();
        __syncthreads();

        float C1[32];
        #pragma unroll
        for (int i = 0; i < 32; i++) C1[i] = 0.f;
        for (int ka = 0; ka < 12; ka++) {
            unsigned ahi[4], alo[4];
            ldsm_x4(ahi, a1addr + ka*32);
            ldsm_x4(alo, a1addr + (A1LO - A1HI) + ka*32);
            #pragma unroll
            for (int na = 0; na < 8; na++) {
                unsigned bf[4];
                unsigned baddr = sb + B1HI + (unsigned)((na*8 + brow)*400 + ka*32 + bk)
                               + (unsigned)(bsel * (B1LO - B1HI));
                ldsm_x4(bf, baddr);
                mma16816(C1 + na*4, ahi, bf);
                mma16816(C1 + na*4, alo, bf);
                mma16816(C1 + na*4, ahi, bf + 2);
            }
        }
        __syncthreads();   // all warps done reading B1 buffer

        // prefetch B1[nt+1] during epilogue + GEMM2
        if (nt < 11) {
            for (int i = tid; i < 1536; i += NT2) {
                int nn = i / 24, k8 = i % 24;
                unsigned so = (unsigned)(nn*400 + k8*16);
                size_t go = (size_t)((nt+1)*64 + nn)*192 + k8*8;
                CP_ASYNC16(sb + B1HI + so, (const char*)(g_W1HI + go));
                CP_ASYNC16(sb + B1LO + so, (const char*)(g_W1LO + go));
            }
            CP_COMMIT();
        }

        // epilogue1: bias + relu + split -> A2 fragments (registers only)
        unsigned a2hi[16], a2lo[16];
        #pragma unroll
        for (int j = 0; j < 4; j++) {
            const float* cA = C1 + (2*j)*4;
            const float* cB = C1 + (2*j+1)*4;
            int colA = nt*64 + 16*j + 2*ti;
            int colB = colA + 8;
            float bA0 = (colA   < Ff) ? __ldg(b1 + colA)     : 0.f;
            float bA1 = (colA+1 < Ff) ? __ldg(b1 + colA + 1) : 0.f;
            float bB0 = (colB   < Ff) ? __ldg(b1 + colB)     : 0.f;
            float bB1 = (colB+1 < Ff) ? __ldg(b1 + colB + 1) : 0.f;
            split2(fmaxf(cA[0]+bA0, 0.f), fmaxf(cA[1]+bA1, 0.f), a2hi[j*4+0], a2lo[j*4+0]);
            split2(fmaxf(cA[2]+bA0, 0.f), fmaxf(cA[3]+bA1, 0.f), a2hi[j*4+1], a2lo[j*4+1]);
            split2(fmaxf(cB[0]+bB0, 0.f), fmaxf(cB[1]+bB1, 0.f), a2hi[j*4+2], a2lo[j*4+2]);
            split2(fmaxf(cB[2]+bB0, 0.f), fmaxf(cB[3]+bB1, 0.f), a2hi[j*4+3], a2lo[j*4+3]);
        }

        // B2[nt] ready? pending: {B2[nt], B1[nt+1]} -> wait1; last iter: wait0
        if (nt < 11) CP_WAIT1(); else CP_WAIT0();
        __syncthreads();

        #pragma unroll
        for (int ka = 0; ka < 4; ka++) {
            #pragma unroll
            for (int na = 0; na < 24; na++) {
                unsigned bf[4];
                unsigned baddr = sb + B2HI + (unsigned)((na*8 + brow)*144 + ka*32 + bk)
                               + (unsigned)(bsel * (B2LO - B2HI));
                ldsm_x4(bf, baddr);
                mma16816(C2 + na*4, a2hi + ka*4, bf);
                mma16816(C2 + na*4, a2lo + ka*4, bf);
                mma16816(C2 + na*4, a2hi + ka*4, bf + 2);
            }
        }
        __syncthreads();   // all warps done reading B2 buffer

        // prefetch B2[nt+1] during next GEMM1
        if (nt < 11) {
            for (int i = tid; i < 1536; i += NT2) {
                int nn = i / 8, k8 = i % 8;
                unsigned so = (unsigned)(nn*144 + k8*16);
                size_t go = (size_t)nn*768 + (nt+1)*64 + k8*8;
                CP_ASYNC16(sb + B2HI + so, (const char*)(g_W2HI + go));
                CP_ASYNC16(sb + B2LO + so, (const char*)(g_W2LO + go));
            }
            CP_COMMIT();
        }
    }

    {
        size_t rA = row0 + w*16 + g;
        size_t rB = rA + 8;
        #pragma unroll
        for (int na = 0; na < 24; na++) {
            int col = na*8 + 2*ti;
            if (col < Cc) {
                float b20 = __ldg(b2 + col), b21 = __ldg(b2 + col + 1);
                out[rA*Cc + col]     = C2[na*4+0] + b20 + g_X2[rA*Cc + col];
                out[rA*Cc + col + 1] = C2[na*4+1] + b21 + g_X2[rA*Cc + col + 1];
                out[rB*Cc + col]     = C2[na*4+2] + b20 + g_X2[rB*Cc + col];
                out[rB*Cc + col + 1] = C2[na*4+3] + b21 + g_X2[rB*Cc + col + 1];
            }
        }
    }
}

// ============================================================================
// Launch
// ============================================================================
extern "C" void kernel_launch(void* const* d_in, const int* in_sizes, int n_in,
                              void* d_out, int out_size) {
    const float* x   = (const float*)d_in[0];
    const float* wq  = (const float*)d_in[1];
    const float* wk  = (const float*)d_in[2];
    const float* wv  = (const float*)d_in[3];
    const float* g1  = (const float*)d_in[4];
    const float* be1 = (const float*)d_in[5];
    const float* g2  = (const float*)d_in[6];
    const float* be2 = (const float*)d_in[7];
    const float* w1  = (const float*)d_in[8];
    const float* b1  = (const float*)d_in[9];
    const float* w2  = (const float*)d_in[10];
    const float* b2  = (const float*)d_in[11];
    float* out = (float*)d_out;

    cudaFuncSetAttribute(ln1qkv_kernel, cudaFuncAttributeMaxDynamicSharedMemorySize, SMQ_TOTAL);
    cudaFuncSetAttribute(attn2_kernel, cudaFuncAttributeMaxDynamicSharedMemorySize,
                         SMH_TOTAL * (int)sizeof(float));
    cudaFuncSetAttribute(mlp_kernel, cudaFuncAttributeMaxDynamicSharedMemorySize, SM2_TOTAL);

    prep_all<<<148, 256>>>(wq, wk, wv, w1, w2);
    ln1qkv_kernel<<<ROWS / 128, NT2, SMQ_TOTAL>>>(x, g1, be1);
    dim3 agrid(Bb, 3);
    attn2_kernel<<<agrid, 64, SMH_TOTAL * sizeof(float)>>>(x);
    mlp_kernel<<<ROWS / 128, NT2, SM2_TOTAL>>>(g2, be2, b1, b2, out);
}

// round 8
// speedup vs baseline: 1.8830x; 1.0852x over previous
#include <cuda_runtime.h>
#include <cuda_bf16.h>
#include <math.h>
#include <stdint.h>

#define Bb 4096
#define Tt 32
#define Cc 180
#define Hh 6
#define HDd 30
#define Ff 720
#define EPS 1e-5f
#define ROWS (Bb*Tt)
#define NQ 576

// tile-block sizes (bytes)
#define QBLK 51200     // 64n x 400B (hi) + 64n x 400B (lo)
#define W1BLK 51200
#define W2BLK 55296    // 192n x 144B (hi) + 192n x 144B (lo)

// ============================================================================
// Device scratch (tile-blocked, smem-layout-identical weights)
// ============================================================================
__device__ float g_X2[(size_t)ROWS * Cc];
__device__ float g_QKVS[(size_t)ROWS * NQ];
__device__ __align__(16) char g_WQB[9  * QBLK];
__device__ __align__(16) char g_W1B[12 * W1BLK];
__device__ __align__(16) char g_W2B[12 * W2BLK];

// ============================================================================
// helpers
// ============================================================================
__device__ __forceinline__ unsigned smem_u32(const void* p) {
    unsigned a;
    asm("{ .reg .u64 t; cvta.to.shared.u64 t, %1; cvt.u32.u64 %0, t; }" : "=r"(a) : "l"(p));
    return a;
}
__device__ __forceinline__ void ldsm_x4(unsigned* r, unsigned addr) {
    asm volatile("ldmatrix.sync.aligned.m8n8.x4.shared.b16 {%0,%1,%2,%3}, [%4];"
                 : "=r"(r[0]), "=r"(r[1]), "=r"(r[2]), "=r"(r[3]) : "r"(addr));
}
__device__ __forceinline__ void mma16816(float* c, const unsigned* a, const unsigned* b) {
    asm volatile(
        "mma.sync.aligned.m16n8k16.row.col.f32.bf16.bf16.f32 "
        "{%0,%1,%2,%3}, {%4,%5,%6,%7}, {%8,%9}, {%0,%1,%2,%3};"
        : "+f"(c[0]), "+f"(c[1]), "+f"(c[2]), "+f"(c[3])
        : "r"(a[0]), "r"(a[1]), "r"(a[2]), "r"(a[3]), "r"(b[0]), "r"(b[1]));
}
__device__ __forceinline__ void split2(float v0, float v1, unsigned& hp, unsigned& lp) {
    __nv_bfloat16 h0 = __float2bfloat16(v0);
    __nv_bfloat16 l0 = __float2bfloat16(v0 - __bfloat162float(h0));
    __nv_bfloat16 h1 = __float2bfloat16(v1);
    __nv_bfloat16 l1 = __float2bfloat16(v1 - __bfloat162float(h1));
    __nv_bfloat162 hh = __halves2bfloat162(h0, h1);
    __nv_bfloat162 ll = __halves2bfloat162(l0, l1);
    hp = *reinterpret_cast<unsigned*>(&hh);
    lp = *reinterpret_cast<unsigned*>(&ll);
}
#define MBAR_INIT(mb, c) \
    asm volatile("mbarrier.init.shared.b64 [%0], %1;" :: "r"((unsigned)(mb)), "r"((unsigned)(c)) : "memory")
#define MBAR_EXPECT_TX(mb, tx) \
    asm volatile("mbarrier.arrive.expect_tx.shared.b64 _, [%0], %1;" :: "r"((unsigned)(mb)), "r"((unsigned)(tx)) : "memory")
#define MBAR_WAIT(mb, par) do { \
    unsigned _m = (unsigned)(mb); unsigned _p = (unsigned)(par); unsigned _d; \
    asm volatile("{\n\t.reg .pred p;\n\t" \
        "mbarrier.try_wait.parity.acquire.cta.shared::cta.b64 p, [%1], %2;\n\t" \
        "selp.b32 %0, 1, 0, p;\n\t}" : "=r"(_d) : "r"(_m), "r"(_p) : "memory"); \
    if (!_d) { \
        asm volatile("{\n\t.reg .pred P1;\n\t" \
            "WL_%=:\n\t" \
            "mbarrier.try_wait.parity.acquire.cta.shared::cta.b64 P1, [%0], %1, 0x989680;\n\t" \
            "@P1 bra.uni WD_%=;\n\t" \
            "bra.uni WL_%=;\n\t" \
            "WD_%=:\n\t}" :: "r"(_m), "r"(_p) : "memory"); \
    } } while (0)
#define BULK_LD(dst, src, sz, mb) \
    asm volatile("cp.async.bulk.shared::cluster.global.mbarrier::complete_tx::bytes [%0], [%1], %2, [%3];" \
                 :: "r"((unsigned)(dst)), "l"(src), "r"((unsigned)(sz)), "r"((unsigned)(mb)) : "memory")

// ============================================================================
// Prep: weights -> tile-blocked padded bf16 hi/lo
// ============================================================================
__global__ void prep_all(const float* __restrict__ wq, const float* __restrict__ wk,
                         const float* __restrict__ wv, const float* __restrict__ w1,
                         const float* __restrict__ w2) {
    const int NWQ = NQ * 192, NW1 = 768 * 192, NW2 = 192 * 768;
    for (int i = blockIdx.x * blockDim.x + threadIdx.x; i < NWQ + NW1 + NW2;
         i += gridDim.x * blockDim.x) {
        float v = 0.f;
        char* hi;
        char* lo;
        if (i < NWQ) {
            int n = i / 192, k = i % 192;
            if (n < 540 && k < Cc) {
                int mat = n / Cc, m = n % Cc;
                int hh = m / HDd, d = m % HDd;
                const float* W = (mat == 0 ? wq : (mat == 1 ? wk : wv));
                v = W[(size_t)hh * (Cc*HDd) + (size_t)k * HDd + d];
            }
            char* base = g_WQB + (n >> 6) * QBLK;
            hi = base + (n & 63) * 400 + k * 2;
            lo = hi + 25600;
        } else if (i < NWQ + NW1) {
            int j = i - NWQ;
            int n = j / 192, k = j % 192;
            if (n < Ff && k < Cc) v = w1[(size_t)k * Ff + n];
            char* base = g_W1B + (n >> 6) * W1BLK;
            hi = base + (n & 63) * 400 + k * 2;
            lo = hi + 25600;
        } else {
            int j = i - NWQ - NW1;
            int n = j / 768, k = j % 768;
            if (n < Cc && k < Ff) v = w2[(size_t)k * Cc + n];
            char* base = g_W2B + (k >> 6) * W2BLK;
            hi = base + n * 144 + (k & 63) * 2;
            lo = hi + 27648;
        }
        __nv_bfloat16 h = __float2bfloat16(v);
        *(__nv_bfloat16*)hi = h;
        *(__nv_bfloat16*)lo = __float2bfloat16(v - __bfloat162float(h));
    }
}

// ============================================================================
// Kernel 1: LN1 + QKV GEMM (HMMA split-3, bulk double-buffered B)
// ============================================================================
#define NT2 256
#define QA1HI 0
#define QA1LO 51200
#define QB0   102400
#define QB1   153600
#define QBSZ  25600
#define QBAR  204800
#define SMQ_TOTAL 204928

__global__ void __launch_bounds__(NT2, 1) ln1qkv_kernel(
    const float* __restrict__ x,
    const float* __restrict__ g1, const float* __restrict__ be1)
{
    extern __shared__ char sm2[];
    const unsigned sb = smem_u32(sm2);
    const int tid = threadIdx.x;
    const int w   = tid >> 5;
    const int ln  = tid & 31;
    const int g   = ln >> 2;
    const int ti  = ln & 3;
    const size_t row0 = (size_t)blockIdx.x * 128;

    if (tid == 0) { MBAR_INIT(sb + QBAR, 1); MBAR_INIT(sb + QBAR + 8, 1); }
    __syncthreads();
    if (tid == 0) {
        MBAR_EXPECT_TX(sb + QBAR, QBLK);
        BULK_LD(sb + QB0, g_WQB, QBLK, sb + QBAR);
    }

    // ---- LN1 + hi/lo split -> A (overlaps first bulk) ----
    for (int r = w; r < 128; r += 8) {
        const float* xr = x + (row0 + r) * Cc;
        float s = 0.f, s2 = 0.f;
        for (int c = ln; c < Cc; c += 32) { float v = xr[c]; s += v; s2 += v*v; }
        #pragma unroll
        for (int o = 16; o; o >>= 1) {
            s  += __shfl_xor_sync(0xffffffffu, s,  o);
            s2 += __shfl_xor_sync(0xffffffffu, s2, o);
        }
        float mu = s * (1.f/Cc);
        float inv = rsqrtf(s2 * (1.f/Cc) - mu*mu + EPS);
        for (int cp = ln; cp < 96; cp += 32) {
            int c0 = cp * 2;
            float v0 = (c0   < Cc) ? (xr[c0]  -mu)*inv*g1[c0]   + be1[c0]   : 0.f;
            float v1 = (c0+1 < Cc) ? (xr[c0+1]-mu)*inv*g1[c0+1] + be1[c0+1] : 0.f;
            unsigned hp, lp;
            split2(v0, v1, hp, lp);
            unsigned off = (unsigned)(r*400 + c0*2);
            *(unsigned*)(sm2 + QA1HI + off) = hp;
            *(unsigned*)(sm2 + QA1LO + off) = lp;
        }
    }
    __syncthreads();

    const unsigned a1addr = sb + QA1HI + (unsigned)((w*16 + (ln & 15))*400 + (ln >> 4)*16);
    const int brow = ln & 7;
    const int bk   = ((ln >> 3) & 1) * 16;
    const int bsel = (ln >> 4);

    int ph0 = 0, ph1 = 0;
    for (int nt = 0; nt < 9; nt++) {
        const int c = nt & 1;
        MBAR_WAIT(sb + QBAR + 8*c, (c ? ph1 : ph0));
        if (c) ph1 ^= 1; else ph0 ^= 1;
        __syncthreads();                       // all threads past previous tile
        if (nt < 8 && tid == 0) {
            MBAR_EXPECT_TX(sb + QBAR + 8*(c^1), QBLK);
            BULK_LD(sb + (c ? QB0 : QB1), g_WQB + (size_t)(nt+1)*QBLK, QBLK, sb + QBAR + 8*(c^1));
        }

        const unsigned bbase = sb + (c ? QB1 : QB0);
        float C1[32];
        #pragma unroll
        for (int i = 0; i < 32; i++) C1[i] = 0.f;
        for (int ka = 0; ka < 12; ka++) {
            unsigned ahi[4], alo[4];
            ldsm_x4(ahi, a1addr + ka*32);
            ldsm_x4(alo, a1addr + (QA1LO - QA1HI) + ka*32);
            #pragma unroll
            for (int na = 0; na < 8; na++) {
                unsigned bf[4];
                unsigned baddr = bbase + (unsigned)((na*8 + brow)*400 + ka*32 + bk)
                               + (unsigned)(bsel * QBSZ);
                ldsm_x4(bf, baddr);
                mma16816(C1 + na*4, ahi, bf);
                mma16816(C1 + na*4, alo, bf);
                mma16816(C1 + na*4, ahi, bf + 2);
            }
        }

        {
            size_t rA = row0 + w*16 + g;
            size_t rB = rA + 8;
            #pragma unroll
            for (int na = 0; na < 8; na++) {
                int col = nt*64 + na*8 + 2*ti;
                *(float2*)(g_QKVS + rA*NQ + col) = make_float2(C1[na*4+0], C1[na*4+1]);
                *(float2*)(g_QKVS + rB*NQ + col) = make_float2(C1[na*4+2], C1[na*4+3]);
            }
        }
    }
}

// ============================================================================
// Kernel 2: softmax + A@V + residual -> g_X2  (R6, proven)
// ============================================================================
#define PD31 31
#define PT33 33
#define SMH_Q 0
#define SMH_K (2*Tt*PD31)
#define SMH_V (4*Tt*PD31)
#define SMH_S (6*Tt*PD31)
#define SMH_TOTAL (SMH_S + 2*Tt*PT33)

__global__ void __launch_bounds__(64, 7) attn2_kernel(const float* __restrict__ x)
{
    extern __shared__ float sm[];
    const int b   = blockIdx.x;
    const int hp  = blockIdx.y;
    const int tid = threadIdx.x;
    const int wi  = tid >> 5;
    const int ln  = tid & 31;

    const float* base = g_QKVS + (size_t)b * (Tt*NQ);
    #pragma unroll
    for (int m = 0; m < 3; m++) {
        float* dst = sm + m * (2*Tt*PD31);
        for (int e = tid; e < 2*Tt*HDd; e += 64) {
            int hl = e / (Tt*HDd);
            int rem = e - hl*(Tt*HDd);
            int r = rem / HDd, d = rem - r*HDd;
            dst[hl*(Tt*PD31) + r*PD31 + d] = base[(size_t)r*NQ + m*Cc + (hp*2+hl)*HDd + d];
        }
    }
    __syncthreads();

    const float* qsw = sm + SMH_Q + wi*(Tt*PD31);
    const float* ksw = sm + SMH_K + wi*(Tt*PD31);
    const float* vsw = sm + SMH_V + wi*(Tt*PD31);
    float* ssw = sm + SMH_S + wi*(Tt*PT33);

    for (int ti = 0; ti < Tt; ti++) {
        const float* qp = qsw + ti*PD31;
        const float* kp = ksw + ln*PD31;
        float dot = 0.f;
        #pragma unroll
        for (int d = 0; d < HDd; d++) dot += qp[d] * kp[d];
        dot *= 0.18257418583505537f;
        float val = (ln <= ti) ? dot : -1e30f;
        float m = val;
        #pragma unroll
        for (int o = 16; o; o >>= 1) m = fmaxf(m, __shfl_xor_sync(0xffffffffu, m, o));
        float e = (ln <= ti) ? __expf(val - m) : 0.f;
        float sum = e;
        #pragma unroll
        for (int o = 16; o; o >>= 1) sum += __shfl_xor_sync(0xffffffffu, sum, o);
        ssw[ti*PT33 + ln] = e / sum;
    }
    __syncwarp();

    float acc[HDd];
    #pragma unroll
    for (int d = 0; d < HDd; d++) acc[d] = 0.f;
    const float* prow = ssw + ln*PT33;
    #pragma unroll 4
    for (int tj = 0; tj < Tt; tj++) {
        float p = prow[tj];
        const float* vr = vsw + tj*PD31;
        #pragma unroll
        for (int d = 0; d < HDd; d++) acc[d] += p * vr[d];
    }

    {
        size_t off = ((size_t)b*Tt + ln) * Cc + (hp*2 + wi)*HDd;
        const float* xr = x + off;
        float* og = g_X2 + off;
        #pragma unroll
        for (int d = 0; d < HDd; d++) og[d] = xr[d] + acc[d];
    }
}

// ============================================================================
// Kernel 3: LN2 + MLP (HMMA split-3, bulk-staged B) + residual -> out
// ============================================================================
#define A1HI  0
#define A1LO  51200
#define B1HI  102400
#define B1LO  128000
#define B2HI  153600
#define B2LO  181248
#define MBARS 208896      // b1bar @ +0, b2bar @ +8
#define B1S   208928      // float[768] bias cache
#define SM2_TOTAL 212096

__global__ void __launch_bounds__(NT2, 1) mlp_kernel(
    const float* __restrict__ g2, const float* __restrict__ be2,
    const float* __restrict__ b1, const float* __restrict__ b2,
    float* __restrict__ out)
{
    extern __shared__ char sm2[];
    const unsigned sb = smem_u32(sm2);
    const int tid = threadIdx.x;
    const int w   = tid >> 5;
    const int ln  = tid & 31;
    const int g   = ln >> 2;
    const int ti  = ln & 3;
    const size_t row0 = (size_t)blockIdx.x * 128;
    float* b1s = (float*)(sm2 + B1S);

    if (tid == 0) { MBAR_INIT(sb + MBARS, 1); MBAR_INIT(sb + MBARS + 8, 1); }
    __syncthreads();
    if (tid == 0) {
        MBAR_EXPECT_TX(sb + MBARS, W1BLK);
        BULK_LD(sb + B1HI, g_W1B, W1BLK, sb + MBARS);
        MBAR_EXPECT_TX(sb + MBARS + 8, W2BLK);
        BULK_LD(sb + B2HI, g_W2B, W2BLK, sb + MBARS + 8);
    }

    // bias cache
    for (int i = tid; i < 768; i += NT2) b1s[i] = (i < Ff) ? b1[i] : 0.f;

    // ---- LN2 + split -> A1 (overlaps first bulks) ----
    for (int r = w; r < 128; r += 8) {
        const float* xr = g_X2 + (row0 + r) * Cc;
        float s = 0.f, s2 = 0.f;
        for (int c = ln; c < Cc; c += 32) { float v = xr[c]; s += v; s2 += v*v; }
        #pragma unroll
        for (int o = 16; o; o >>= 1) {
            s  += __shfl_xor_sync(0xffffffffu, s,  o);
            s2 += __shfl_xor_sync(0xffffffffu, s2, o);
        }
        float mu = s * (1.f/Cc);
        float inv = rsqrtf(s2 * (1.f/Cc) - mu*mu + EPS);
        for (int cp = ln; cp < 96; cp += 32) {
            int c0 = cp * 2;
            float v0 = (c0   < Cc) ? (xr[c0]  -mu)*inv*g2[c0]   + be2[c0]   : 0.f;
            float v1 = (c0+1 < Cc) ? (xr[c0+1]-mu)*inv*g2[c0+1] + be2[c0+1] : 0.f;
            unsigned hp, lp;
            split2(v0, v1, hp, lp);
            unsigned off = (unsigned)(r*400 + c0*2);
            *(unsigned*)(sm2 + A1HI + off) = hp;
            *(unsigned*)(sm2 + A1LO + off) = lp;
        }
    }
    __syncthreads();

    float C2[96];
    #pragma unroll
    for (int i = 0; i < 96; i++) C2[i] = 0.f;

    const unsigned a1addr = sb + A1HI + (unsigned)((w*16 + (ln & 15))*400 + (ln >> 4)*16);
    const int brow = ln & 7;
    const int bk   = ((ln >> 3) & 1) * 16;
    const int bsel = (ln >> 4);

    int p1 = 0, p2 = 0;
    for (int nt = 0; nt < 12; nt++) {
        // B1[nt] ready
        MBAR_WAIT(sb + MBARS, p1); p1 ^= 1;

        float C1[32];
        #pragma unroll
        for (int i = 0; i < 32; i++) C1[i] = 0.f;
        for (int ka = 0; ka < 12; ka++) {
            unsigned ahi[4], alo[4];
            ldsm_x4(ahi, a1addr + ka*32);
            ldsm_x4(alo, a1addr + (A1LO - A1HI) + ka*32);
            #pragma unroll
            for (int na = 0; na < 8; na++) {
                unsigned bf[4];
                unsigned baddr = sb + B1HI + (unsigned)((na*8 + brow)*400 + ka*32 + bk)
                               + (unsigned)(bsel * (B1LO - B1HI));
                ldsm_x4(bf, baddr);
                mma16816(C1 + na*4, ahi, bf);
                mma16816(C1 + na*4, alo, bf);
                mma16816(C1 + na*4, ahi, bf + 2);
            }
        }

        // epilogue1: bias + relu + split -> A2 fragments (registers only)
        unsigned a2hi[16], a2lo[16];
        #pragma unroll
        for (int j = 0; j < 4; j++) {
            const float* cA = C1 + (2*j)*4;
            const float* cB = C1 + (2*j+1)*4;
            int colA = nt*64 + 16*j + 2*ti;
            int colB = colA + 8;
            float bA0 = b1s[colA], bA1 = b1s[colA+1];
            float bB0 = b1s[colB], bB1 = b1s[colB+1];
            split2(fmaxf(cA[0]+bA0, 0.f), fmaxf(cA[1]+bA1, 0.f), a2hi[j*4+0], a2lo[j*4+0]);
            split2(fmaxf(cA[2]+bA0, 0.f), fmaxf(cA[3]+bA1, 0.f), a2hi[j*4+1], a2lo[j*4+1]);
            split2(fmaxf(cB[0]+bB0, 0.f), fmaxf(cB[1]+bB1, 0.f), a2hi[j*4+2], a2lo[j*4+2]);
            split2(fmaxf(cB[2]+bB0, 0.f), fmaxf(cB[3]+bB1, 0.f), a2hi[j*4+3], a2lo[j*4+3]);
        }

        __syncthreads();   // all warps done reading B1[nt]
        if (nt < 11 && tid == 0) {
            MBAR_EXPECT_TX(sb + MBARS, W1BLK);
            BULK_LD(sb + B1HI, g_W1B + (size_t)(nt+1)*W1BLK, W1BLK, sb + MBARS);
        }

        // B2[nt] ready
        MBAR_WAIT(sb + MBARS + 8, p2); p2 ^= 1;

        #pragma unroll
        for (int ka = 0; ka < 4; ka++) {
            #pragma unroll
            for (int na = 0; na < 24; na++) {
                unsigned bf[4];
                unsigned baddr = sb + B2HI + (unsigned)((na*8 + brow)*144 + ka*32 + bk)
                               + (unsigned)(bsel * (B2LO - B2HI));
                ldsm_x4(bf, baddr);
                mma16816(C2 + na*4, a2hi + ka*4, bf);
                mma16816(C2 + na*4, a2lo + ka*4, bf);
                mma16816(C2 + na*4, a2hi + ka*4, bf + 2);
            }
        }
        __syncthreads();   // all warps done reading B2[nt]
        if (nt < 11 && tid == 0) {
            MBAR_EXPECT_TX(sb + MBARS + 8, W2BLK);
            BULK_LD(sb + B2HI, g_W2B + (size_t)(nt+1)*W2BLK, W2BLK, sb + MBARS + 8);
        }
    }

    {
        size_t rA = row0 + w*16 + g;
        size_t rB = rA + 8;
        #pragma unroll
        for (int na = 0; na < 24; na++) {
            int col = na*8 + 2*ti;
            if (col < Cc) {
                float b20 = __ldg(b2 + col), b21 = __ldg(b2 + col + 1);
                out[rA*Cc + col]     = C2[na*4+0] + b20 + g_X2[rA*Cc + col];
                out[rA*Cc + col + 1] = C2[na*4+1] + b21 + g_X2[rA*Cc + col + 1];
                out[rB*Cc + col]     = C2[na*4+2] + b20 + g_X2[rB*Cc + col];
                out[rB*Cc + col + 1] = C2[na*4+3] + b21 + g_X2[rB*Cc + col + 1];
            }
        }
    }
}

// ============================================================================
// Launch
// ============================================================================
extern "C" void kernel_launch(void* const* d_in, const int* in_sizes, int n_in,
                              void* d_out, int out_size) {
    const float* x   = (const float*)d_in[0];
    const float* wq  = (const float*)d_in[1];
    const float* wk  = (const float*)d_in[2];
    const float* wv  = (const float*)d_in[3];
    const float* g1  = (const float*)d_in[4];
    const float* be1 = (const float*)d_in[5];
    const float* g2  = (const float*)d_in[6];
    const float* be2 = (const float*)d_in[7];
    const float* w1  = (const float*)d_in[8];
    const float* b1  = (const float*)d_in[9];
    const float* w2  = (const float*)d_in[10];
    const float* b2  = (const float*)d_in[11];
    float* out = (float*)d_out;

    cudaFuncSetAttribute(ln1qkv_kernel, cudaFuncAttributeMaxDynamicSharedMemorySize, SMQ_TOTAL);
    cudaFuncSetAttribute(attn2_kernel, cudaFuncAttributeMaxDynamicSharedMemorySize,
                         SMH_TOTAL * (int)sizeof(float));
    cudaFuncSetAttribute(mlp_kernel, cudaFuncAttributeMaxDynamicSharedMemorySize, SM2_TOTAL);

    prep_all<<<148, 256>>>(wq, wk, wv, w1, w2);
    ln1qkv_kernel<<<ROWS / 128, NT2, SMQ_TOTAL>>>(x, g1, be1);
    dim3 agrid(Bb, 3);
    attn2_kernel<<<agrid, 64, SMH_TOTAL * sizeof(float)>>>(x);
    mlp_kernel<<<ROWS / 128, NT2, SM2_TOTAL>>>(g2, be2, b1, b2, out);
}

// round 9
// speedup vs baseline: 2.1711x; 1.1530x over previous
#include <cuda_runtime.h>
#include <cuda_fp16.h>
#include <math.h>
#include <stdint.h>

#define Bb 4096
#define Tt 32
#define Cc 180
#define Hh 6
#define HDd 30
#define Ff 720
#define EPS 1e-5f
#define ROWS (Bb*Tt)
#define NQ 576

// tile-block sizes (bytes) — single fp16 weights
#define QBLK  25600    // 64n x 400B
#define W1BLK 25600
#define W2BLK 27648    // 192n x 144B

// ============================================================================
// Device scratch
// ============================================================================
__device__ float g_X2[(size_t)ROWS * Cc];
__device__ float g_QKVS[(size_t)ROWS * NQ];
__device__ __align__(16) char g_WQB[9  * QBLK];
__device__ __align__(16) char g_W1B[12 * W1BLK];
__device__ __align__(16) char g_W2B[12 * W2BLK];

// ============================================================================
// helpers
// ============================================================================
__device__ __forceinline__ unsigned smem_u32(const void* p) {
    unsigned a;
    asm("{ .reg .u64 t; cvta.to.shared.u64 t, %1; cvt.u32.u64 %0, t; }" : "=r"(a) : "l"(p));
    return a;
}
__device__ __forceinline__ void ldsm_x4(unsigned* r, unsigned addr) {
    asm volatile("ldmatrix.sync.aligned.m8n8.x4.shared.b16 {%0,%1,%2,%3}, [%4];"
                 : "=r"(r[0]), "=r"(r[1]), "=r"(r[2]), "=r"(r[3]) : "r"(addr));
}
__device__ __forceinline__ void mma16816(float* c, const unsigned* a, const unsigned* b) {
    asm volatile(
        "mma.sync.aligned.m16n8k16.row.col.f32.f16.f16.f32 "
        "{%0,%1,%2,%3}, {%4,%5,%6,%7}, {%8,%9}, {%0,%1,%2,%3};"
        : "+f"(c[0]), "+f"(c[1]), "+f"(c[2]), "+f"(c[3])
        : "r"(a[0]), "r"(a[1]), "r"(a[2]), "r"(a[3]), "r"(b[0]), "r"(b[1]));
}
__device__ __forceinline__ void split2h(float v0, float v1, unsigned& hp, unsigned& lp) {
    __half h0 = __float2half_rn(v0);
    __half l0 = __float2half_rn(v0 - __half2float(h0));
    __half h1 = __float2half_rn(v1);
    __half l1 = __float2half_rn(v1 - __half2float(h1));
    __half2 hh = __halves2half2(h0, h1);
    __half2 ll = __halves2half2(l0, l1);
    hp = *reinterpret_cast<unsigned*>(&hh);
    lp = *reinterpret_cast<unsigned*>(&ll);
}
#define MBAR_INIT(mb, c) \
    asm volatile("mbarrier.init.shared.b64 [%0], %1;" :: "r"((unsigned)(mb)), "r"((unsigned)(c)) : "memory")
#define MBAR_EXPECT_TX(mb, tx) \
    asm volatile("mbarrier.arrive.expect_tx.shared.b64 _, [%0], %1;" :: "r"((unsigned)(mb)), "r"((unsigned)(tx)) : "memory")
#define MBAR_WAIT(mb, par) do { \
    unsigned _m = (unsigned)(mb); unsigned _p = (unsigned)(par); unsigned _d; \
    asm volatile("{\n\t.reg .pred p;\n\t" \
        "mbarrier.try_wait.parity.acquire.cta.shared::cta.b64 p, [%1], %2;\n\t" \
        "selp.b32 %0, 1, 0, p;\n\t}" : "=r"(_d) : "r"(_m), "r"(_p) : "memory"); \
    if (!_d) { \
        asm volatile("{\n\t.reg .pred P1;\n\t" \
            "WL_%=:\n\t" \
            "mbarrier.try_wait.parity.acquire.cta.shared::cta.b64 P1, [%0], %1, 0x989680;\n\t" \
            "@P1 bra.uni WD_%=;\n\t" \
            "bra.uni WL_%=;\n\t" \
            "WD_%=:\n\t}" :: "r"(_m), "r"(_p) : "memory"); \
    } } while (0)
#define BULK_LD(dst, src, sz, mb) \
    asm volatile("cp.async.bulk.shared::cluster.global.mbarrier::complete_tx::bytes [%0], [%1], %2, [%3];" \
                 :: "r"((unsigned)(dst)), "l"(src), "r"((unsigned)(sz)), "r"((unsigned)(mb)) : "memory")

// ============================================================================
// Prep: weights -> tile-blocked padded fp16 (single precision copy)
// ============================================================================
__global__ void prep_all(const float* __restrict__ wq, const float* __restrict__ wk,
                         const float* __restrict__ wv, const float* __restrict__ w1,
                         const float* __restrict__ w2) {
    const int NWQ = NQ * 192, NW1 = 768 * 192, NW2 = 192 * 768;
    for (int i = blockIdx.x * blockDim.x + threadIdx.x; i < NWQ + NW1 + NW2;
         i += gridDim.x * blockDim.x) {
        float v = 0.f;
        char* p;
        if (i < NWQ) {
            int n = i / 192, k = i % 192;
            if (n < 540 && k < Cc) {
                int mat = n / Cc, m = n % Cc;
                int hh = m / HDd, d = m % HDd;
                const float* W = (mat == 0 ? wq : (mat == 1 ? wk : wv));
                v = W[(size_t)hh * (Cc*HDd) + (size_t)k * HDd + d];
            }
            p = g_WQB + (n >> 6) * QBLK + (n & 63) * 400 + k * 2;
        } else if (i < NWQ + NW1) {
            int j = i - NWQ;
            int n = j / 192, k = j % 192;
            if (n < Ff && k < Cc) v = w1[(size_t)k * Ff + n];
            p = g_W1B + (n >> 6) * W1BLK + (n & 63) * 400 + k * 2;
        } else {
            int j = i - NWQ - NW1;
            int n = j / 768, k = j % 768;
            if (n < Cc && k < Ff) v = w2[(size_t)k * Cc + n];
            p = g_W2B + (k >> 6) * W2BLK + n * 144 + (k & 63) * 2;
        }
        *(__half*)p = __float2half_rn(v);
    }
}

// ============================================================================
// Kernel 1: LN1 + QKV GEMM (fp16 A-split-2, bulk double-buffered B)
// ============================================================================
#define NT2 256
#define QA1HI 0
#define QA1LO 51200
#define QB0   102400
#define QB1   128000
#define QBAR  153600
#define SMQ_TOTAL 153728

__global__ void __launch_bounds__(NT2, 1) ln1qkv_kernel(
    const float* __restrict__ x,
    const float* __restrict__ g1, const float* __restrict__ be1)
{
    extern __shared__ char sm2[];
    const unsigned sb = smem_u32(sm2);
    const int tid = threadIdx.x;
    const int w   = tid >> 5;
    const int ln  = tid & 31;
    const int g   = ln >> 2;
    const int ti  = ln & 3;
    const size_t row0 = (size_t)blockIdx.x * 128;

    if (tid == 0) { MBAR_INIT(sb + QBAR, 1); MBAR_INIT(sb + QBAR + 8, 1); }
    __syncthreads();
    if (tid == 0) {
        MBAR_EXPECT_TX(sb + QBAR, QBLK);
        BULK_LD(sb + QB0, g_WQB, QBLK, sb + QBAR);
    }

    // ---- LN1 + fp16 hi/lo split -> A ----
    for (int r = w; r < 128; r += 8) {
        const float* xr = x + (row0 + r) * Cc;
        float s = 0.f, s2 = 0.f;
        for (int c = ln; c < Cc; c += 32) { float v = xr[c]; s += v; s2 += v*v; }
        #pragma unroll
        for (int o = 16; o; o >>= 1) {
            s  += __shfl_xor_sync(0xffffffffu, s,  o);
            s2 += __shfl_xor_sync(0xffffffffu, s2, o);
        }
        float mu = s * (1.f/Cc);
        float inv = rsqrtf(s2 * (1.f/Cc) - mu*mu + EPS);
        for (int cp = ln; cp < 96; cp += 32) {
            int c0 = cp * 2;
            float v0 = (c0   < Cc) ? (xr[c0]  -mu)*inv*g1[c0]   + be1[c0]   : 0.f;
            float v1 = (c0+1 < Cc) ? (xr[c0+1]-mu)*inv*g1[c0+1] + be1[c0+1] : 0.f;
            unsigned hp, lp;
            split2h(v0, v1, hp, lp);
            unsigned off = (unsigned)(r*400 + c0*2);
            *(unsigned*)(sm2 + QA1HI + off) = hp;
            *(unsigned*)(sm2 + QA1LO + off) = lp;
        }
    }
    __syncthreads();

    const unsigned a1addr = sb + QA1HI + (unsigned)((w*16 + (ln & 15))*400 + (ln >> 4)*16);
    const int brow = ln & 7;
    const int boff = ((ln >> 3) & 3) * 16;   // x4 spans two k16 chunks

    int ph0 = 0, ph1 = 0;
    for (int nt = 0; nt < 9; nt++) {
        const int c = nt & 1;
        MBAR_WAIT(sb + QBAR + 8*c, (c ? ph1 : ph0));
        if (c) ph1 ^= 1; else ph0 ^= 1;
        __syncthreads();
        if (nt < 8 && tid == 0) {
            MBAR_EXPECT_TX(sb + QBAR + 8*(c^1), QBLK);
            BULK_LD(sb + (c ? QB0 : QB1), g_WQB + (size_t)(nt+1)*QBLK, QBLK, sb + QBAR + 8*(c^1));
        }

        const unsigned bbase = sb + (c ? QB1 : QB0);
        float C1[32];
        #pragma unroll
        for (int i = 0; i < 32; i++) C1[i] = 0.f;
        for (int p = 0; p < 6; p++) {           // k16 pairs
            unsigned ah0[4], al0[4], ah1[4], al1[4];
            ldsm_x4(ah0, a1addr + p*64);
            ldsm_x4(al0, a1addr + (QA1LO - QA1HI) + p*64);
            ldsm_x4(ah1, a1addr + p*64 + 32);
            ldsm_x4(al1, a1addr + (QA1LO - QA1HI) + p*64 + 32);
            #pragma unroll
            for (int na = 0; na < 8; na++) {
                unsigned bf[4];
                ldsm_x4(bf, bbase + (unsigned)((na*8 + brow)*400 + p*64 + boff));
                mma16816(C1 + na*4, ah0, bf);
                mma16816(C1 + na*4, al0, bf);
                mma16816(C1 + na*4, ah1, bf + 2);
                mma16816(C1 + na*4, al1, bf + 2);
            }
        }

        {
            size_t rA = row0 + w*16 + g;
            size_t rB = rA + 8;
            #pragma unroll
            for (int na = 0; na < 8; na++) {
                int col = nt*64 + na*8 + 2*ti;
                *(float2*)(g_QKVS + rA*NQ + col) = make_float2(C1[na*4+0], C1[na*4+1]);
                *(float2*)(g_QKVS + rB*NQ + col) = make_float2(C1[na*4+2], C1[na*4+3]);
            }
        }
    }
}

// ============================================================================
// Kernel 2: softmax + A@V + residual -> g_X2  (R6, proven)
// ============================================================================
#define PD31 31
#define PT33 33
#define SMH_Q 0
#define SMH_K (2*Tt*PD31)
#define SMH_V (4*Tt*PD31)
#define SMH_S (6*Tt*PD31)
#define SMH_TOTAL (SMH_S + 2*Tt*PT33)

__global__ void __launch_bounds__(64, 7) attn2_kernel(const float* __restrict__ x)
{
    extern __shared__ float sm[];
    const int b   = blockIdx.x;
    const int hp  = blockIdx.y;
    const int tid = threadIdx.x;
    const int wi  = tid >> 5;
    const int ln  = tid & 31;

    const float* base = g_QKVS + (size_t)b * (Tt*NQ);
    #pragma unroll
    for (int m = 0; m < 3; m++) {
        float* dst = sm + m * (2*Tt*PD31);
        for (int e = tid; e < 2*Tt*HDd; e += 64) {
            int hl = e / (Tt*HDd);
            int rem = e - hl*(Tt*HDd);
            int r = rem / HDd, d = rem - r*HDd;
            dst[hl*(Tt*PD31) + r*PD31 + d] = base[(size_t)r*NQ + m*Cc + (hp*2+hl)*HDd + d];
        }
    }
    __syncthreads();

    const float* qsw = sm + SMH_Q + wi*(Tt*PD31);
    const float* ksw = sm + SMH_K + wi*(Tt*PD31);
    const float* vsw = sm + SMH_V + wi*(Tt*PD31);
    float* ssw = sm + SMH_S + wi*(Tt*PT33);

    for (int ti = 0; ti < Tt; ti++) {
        const float* qp = qsw + ti*PD31;
        const float* kp = ksw + ln*PD31;
        float dot = 0.f;
        #pragma unroll
        for (int d = 0; d < HDd; d++) dot += qp[d] * kp[d];
        dot *= 0.18257418583505537f;
        float val = (ln <= ti) ? dot : -1e30f;
        float m = val;
        #pragma unroll
        for (int o = 16; o; o >>= 1) m = fmaxf(m, __shfl_xor_sync(0xffffffffu, m, o));
        float e = (ln <= ti) ? __expf(val - m) : 0.f;
        float sum = e;
        #pragma unroll
        for (int o = 16; o; o >>= 1) sum += __shfl_xor_sync(0xffffffffu, sum, o);
        ssw[ti*PT33 + ln] = e / sum;
    }
    __syncwarp();

    float acc[HDd];
    #pragma unroll
    for (int d = 0; d < HDd; d++) acc[d] = 0.f;
    const float* prow = ssw + ln*PT33;
    #pragma unroll 4
    for (int tj = 0; tj < Tt; tj++) {
        float p = prow[tj];
        const float* vr = vsw + tj*PD31;
        #pragma unroll
        for (int d = 0; d < HDd; d++) acc[d] += p * vr[d];
    }

    {
        size_t off = ((size_t)b*Tt + ln) * Cc + (hp*2 + wi)*HDd;
        const float* xr = x + off;
        float* og = g_X2 + off;
        #pragma unroll
        for (int d = 0; d < HDd; d++) og[d] = xr[d] + acc[d];
    }
}

// ============================================================================
// Kernel 3: LN2 + MLP (fp16 A-split-2, bulk-staged B) + residual -> out
// ============================================================================
#define A1HI  0
#define A1LO  51200
#define B1S_  102400   // B1 tile (25600)
#define B2S_  128000   // B2 tile (27648)
#define MBARS 155648   // two mbarriers
#define BIAS  155664   // float[768]
#define SM2_TOTAL 158784

__global__ void __launch_bounds__(NT2, 1) mlp_kernel(
    const float* __restrict__ g2, const float* __restrict__ be2,
    const float* __restrict__ b1, const float* __restrict__ b2,
    float* __restrict__ out)
{
    extern __shared__ char sm2[];
    const unsigned sb = smem_u32(sm2);
    const int tid = threadIdx.x;
    const int w   = tid >> 5;
    const int ln  = tid & 31;
    const int g   = ln >> 2;
    const int ti  = ln & 3;
    const size_t row0 = (size_t)blockIdx.x * 128;
    float* b1s = (float*)(sm2 + BIAS);

    if (tid == 0) { MBAR_INIT(sb + MBARS, 1); MBAR_INIT(sb + MBARS + 8, 1); }
    __syncthreads();
    if (tid == 0) {
        MBAR_EXPECT_TX(sb + MBARS, W1BLK);
        BULK_LD(sb + B1S_, g_W1B, W1BLK, sb + MBARS);
        MBAR_EXPECT_TX(sb + MBARS + 8, W2BLK);
        BULK_LD(sb + B2S_, g_W2B, W2BLK, sb + MBARS + 8);
    }

    for (int i = tid; i < 768; i += NT2) b1s[i] = (i < Ff) ? b1[i] : 0.f;

    // ---- LN2 + fp16 split -> A1 ----
    for (int r = w; r < 128; r += 8) {
        const float* xr = g_X2 + (row0 + r) * Cc;
        float s = 0.f, s2 = 0.f;
        for (int c = ln; c < Cc; c += 32) { float v = xr[c]; s += v; s2 += v*v; }
        #pragma unroll
        for (int o = 16; o; o >>= 1) {
            s  += __shfl_xor_sync(0xffffffffu, s,  o);
            s2 += __shfl_xor_sync(0xffffffffu, s2, o);
        }
        float mu = s * (1.f/Cc);
        float inv = rsqrtf(s2 * (1.f/Cc) - mu*mu + EPS);
        for (int cp = ln; cp < 96; cp += 32) {
            int c0 = cp * 2;
            float v0 = (c0   < Cc) ? (xr[c0]  -mu)*inv*g2[c0]   + be2[c0]   : 0.f;
            float v1 = (c0+1 < Cc) ? (xr[c0+1]-mu)*inv*g2[c0+1] + be2[c0+1] : 0.f;
            unsigned hp, lp;
            split2h(v0, v1, hp, lp);
            unsigned off = (unsigned)(r*400 + c0*2);
            *(unsigned*)(sm2 + A1HI + off) = hp;
            *(unsigned*)(sm2 + A1LO + off) = lp;
        }
    }
    __syncthreads();

    float C2[96];
    #pragma unroll
    for (int i = 0; i < 96; i++) C2[i] = 0.f;

    const unsigned a1addr = sb + A1HI + (unsigned)((w*16 + (ln & 15))*400 + (ln >> 4)*16);
    const int brow = ln & 7;
    const int boff = ((ln >> 3) & 3) * 16;

    int p1 = 0, p2 = 0;
    for (int nt = 0; nt < 12; nt++) {
        MBAR_WAIT(sb + MBARS, p1); p1 ^= 1;

        float C1[32];
        #pragma unroll
        for (int i = 0; i < 32; i++) C1[i] = 0.f;
        for (int p = 0; p < 6; p++) {
            unsigned ah0[4], al0[4], ah1[4], al1[4];
            ldsm_x4(ah0, a1addr + p*64);
            ldsm_x4(al0, a1addr + (A1LO - A1HI) + p*64);
            ldsm_x4(ah1, a1addr + p*64 + 32);
            ldsm_x4(al1, a1addr + (A1LO - A1HI) + p*64 + 32);
            #pragma unroll
            for (int na = 0; na < 8; na++) {
                unsigned bf[4];
                ldsm_x4(bf, sb + B1S_ + (unsigned)((na*8 + brow)*400 + p*64 + boff));
                mma16816(C1 + na*4, ah0, bf);
                mma16816(C1 + na*4, al0, bf);
                mma16816(C1 + na*4, ah1, bf + 2);
                mma16816(C1 + na*4, al1, bf + 2);
            }
        }

        // epilogue1: bias + relu + fp16 split -> A2 fragments (registers)
        unsigned a2hi[16], a2lo[16];
        #pragma unroll
        for (int j = 0; j < 4; j++) {
            const float* cA = C1 + (2*j)*4;
            const float* cB = C1 + (2*j+1)*4;
            int colA = nt*64 + 16*j + 2*ti;
            int colB = colA + 8;
            float bA0 = b1s[colA], bA1 = b1s[colA+1];
            float bB0 = b1s[colB], bB1 = b1s[colB+1];
            split2h(fmaxf(cA[0]+bA0, 0.f), fmaxf(cA[1]+bA1, 0.f), a2hi[j*4+0], a2lo[j*4+0]);
            split2h(fmaxf(cA[2]+bA0, 0.f), fmaxf(cA[3]+bA1, 0.f), a2hi[j*4+1], a2lo[j*4+1]);
            split2h(fmaxf(cB[0]+bB0, 0.f), fmaxf(cB[1]+bB1, 0.f), a2hi[j*4+2], a2lo[j*4+2]);
            split2h(fmaxf(cB[2]+bB0, 0.f), fmaxf(cB[3]+bB1, 0.f), a2hi[j*4+3], a2lo[j*4+3]);
        }

        __syncthreads();   // all warps done reading B1[nt]
        if (nt < 11 && tid == 0) {
            MBAR_EXPECT_TX(sb + MBARS, W1BLK);
            BULK_LD(sb + B1S_, g_W1B + (size_t)(nt+1)*W1BLK, W1BLK, sb + MBARS);
        }

        MBAR_WAIT(sb + MBARS + 8, p2); p2 ^= 1;

        #pragma unroll
        for (int p = 0; p < 2; p++) {
            #pragma unroll
            for (int na = 0; na < 24; na++) {
                unsigned bf[4];
                ldsm_x4(bf, sb + B2S_ + (unsigned)((na*8 + brow)*144 + p*64 + boff));
                mma16816(C2 + na*4, a2hi + (2*p)*4,   bf);
                mma16816(C2 + na*4, a2lo + (2*p)*4,   bf);
                mma16816(C2 + na*4, a2hi + (2*p+1)*4, bf + 2);
                mma16816(C2 + na*4, a2lo + (2*p+1)*4, bf + 2);
            }
        }
        __syncthreads();   // all warps done reading B2[nt]
        if (nt < 11 && tid == 0) {
            MBAR_EXPECT_TX(sb + MBARS + 8, W2BLK);
            BULK_LD(sb + B2S_, g_W2B + (size_t)(nt+1)*W2BLK, W2BLK, sb + MBARS + 8);
        }
    }

    {
        size_t rA = row0 + w*16 + g;
        size_t rB = rA + 8;
        #pragma unroll
        for (int na = 0; na < 24; na++) {
            int col = na*8 + 2*ti;
            if (col < Cc) {
                float b20 = __ldg(b2 + col), b21 = __ldg(b2 + col + 1);
                out[rA*Cc + col]     = C2[na*4+0] + b20 + g_X2[rA*Cc + col];
                out[rA*Cc + col + 1] = C2[na*4+1] + b21 + g_X2[rA*Cc + col + 1];
                out[rB*Cc + col]     = C2[na*4+2] + b20 + g_X2[rB*Cc + col];
                out[rB*Cc + col + 1] = C2[na*4+3] + b21 + g_X2[rB*Cc + col + 1];
            }
        }
    }
}

// ============================================================================
// Launch
// ============================================================================
extern "C" void kernel_launch(void* const* d_in, const int* in_sizes, int n_in,
                              void* d_out, int out_size) {
    const float* x   = (const float*)d_in[0];
    const float* wq  = (const float*)d_in[1];
    const float* wk  = (const float*)d_in[2];
    const float* wv  = (const float*)d_in[3];
    const float* g1  = (const float*)d_in[4];
    const float* be1 = (const float*)d_in[5];
    const float* g2  = (const float*)d_in[6];
    const float* be2 = (const float*)d_in[7];
    const float* w1  = (const float*)d_in[8];
    const float* b1  = (const float*)d_in[9];
    const float* w2  = (const float*)d_in[10];
    const float* b2  = (const float*)d_in[11];
    float* out = (float*)d_out;

    cudaFuncSetAttribute(ln1qkv_kernel, cudaFuncAttributeMaxDynamicSharedMemorySize, SMQ_TOTAL);
    cudaFuncSetAttribute(attn2_kernel, cudaFuncAttributeMaxDynamicSharedMemorySize,
                         SMH_TOTAL * (int)sizeof(float));
    cudaFuncSetAttribute(mlp_kernel, cudaFuncAttributeMaxDynamicSharedMemorySize, SM2_TOTAL);

    prep_all<<<148, 256>>>(wq, wk, wv, w1, w2);
    ln1qkv_kernel<<<ROWS / 128, NT2, SMQ_TOTAL>>>(x, g1, be1);
    dim3 agrid(Bb, 3);
    attn2_kernel<<<agrid, 64, SMH_TOTAL * sizeof(float)>>>(x);
    mlp_kernel<<<ROWS / 128, NT2, SM2_TOTAL>>>(g2, be2, b1, b2, out);
}

// round 10
// speedup vs baseline: 2.5867x; 1.1914x over previous
#include <cuda_runtime.h>
#include <cuda_fp16.h>
#include <math.h>
#include <stdint.h>

#define Bb 4096
#define Tt 32
#define Cc 180
#define Hh 6
#define HDd 30
#define Ff 720
#define EPS 1e-5f
#define ROWS (Bb*Tt)
#define NQ 576

#define QBLK  25600    // 64n x 400B fp16
#define W1BLK 25600
#define W2BLK 27648    // 192n x 144B fp16

// ============================================================================
// Device scratch
// ============================================================================
__device__ float g_X2[(size_t)ROWS * Cc];
__device__ float g_QKVS[(size_t)ROWS * NQ];
__device__ __align__(16) char g_WQB[9  * QBLK];
__device__ __align__(16) char g_W1B[12 * W1BLK];
__device__ __align__(16) char g_W2B[12 * W2BLK];

// ============================================================================
// helpers
// ============================================================================
__device__ __forceinline__ unsigned smem_u32(const void* p) {
    unsigned a;
    asm("{ .reg .u64 t; cvta.to.shared.u64 t, %1; cvt.u32.u64 %0, t; }" : "=r"(a) : "l"(p));
    return a;
}
__device__ __forceinline__ void ldsm_x4(unsigned* r, unsigned addr) {
    asm volatile("ldmatrix.sync.aligned.m8n8.x4.shared.b16 {%0,%1,%2,%3}, [%4];"
                 : "=r"(r[0]), "=r"(r[1]), "=r"(r[2]), "=r"(r[3]) : "r"(addr));
}
__device__ __forceinline__ void mma16816(float* c, const unsigned* a, const unsigned* b) {
    asm volatile(
        "mma.sync.aligned.m16n8k16.row.col.f32.f16.f16.f32 "
        "{%0,%1,%2,%3}, {%4,%5,%6,%7}, {%8,%9}, {%0,%1,%2,%3};"
        : "+f"(c[0]), "+f"(c[1]), "+f"(c[2]), "+f"(c[3])
        : "r"(a[0]), "r"(a[1]), "r"(a[2]), "r"(a[3]), "r"(b[0]), "r"(b[1]));
}
__device__ __forceinline__ void split2h(float v0, float v1, unsigned& hp, unsigned& lp) {
    __half h0 = __float2half_rn(v0);
    __half l0 = __float2half_rn(v0 - __half2float(h0));
    __half h1 = __float2half_rn(v1);
    __half l1 = __float2half_rn(v1 - __half2float(h1));
    __half2 hh = __halves2half2(h0, h1);
    __half2 ll = __halves2half2(l0, l1);
    hp = *reinterpret_cast<unsigned*>(&hh);
    lp = *reinterpret_cast<unsigned*>(&ll);
}
#define MBAR_INIT(mb, c) \
    asm volatile("mbarrier.init.shared.b64 [%0], %1;" :: "r"((unsigned)(mb)), "r"((unsigned)(c)) : "memory")
#define MBAR_EXPECT_TX(mb, tx) \
    asm volatile("mbarrier.arrive.expect_tx.shared.b64 _, [%0], %1;" :: "r"((unsigned)(mb)), "r"((unsigned)(tx)) : "memory")
#define MBAR_WAIT(mb, par) do { \
    unsigned _m = (unsigned)(mb); unsigned _p = (unsigned)(par); unsigned _d; \
    asm volatile("{\n\t.reg .pred p;\n\t" \
        "mbarrier.try_wait.parity.acquire.cta.shared::cta.b64 p, [%1], %2;\n\t" \
        "selp.b32 %0, 1, 0, p;\n\t}" : "=r"(_d) : "r"(_m), "r"(_p) : "memory"); \
    if (!_d) { \
        asm volatile("{\n\t.reg .pred P1;\n\t" \
            "WL_%=:\n\t" \
            "mbarrier.try_wait.parity.acquire.cta.shared::cta.b64 P1, [%0], %1, 0x989680;\n\t" \
            "@P1 bra.uni WD_%=;\n\t" \
            "bra.uni WL_%=;\n\t" \
            "WD_%=:\n\t}" :: "r"(_m), "r"(_p) : "memory"); \
    } } while (0)
#define BULK_LD(dst, src, sz, mb) \
    asm volatile("cp.async.bulk.shared::cluster.global.mbarrier::complete_tx::bytes [%0], [%1], %2, [%3];" \
                 :: "r"((unsigned)(dst)), "l"(src), "r"((unsigned)(sz)), "r"((unsigned)(mb)) : "memory")

// ============================================================================
// Prep
// ============================================================================
__global__ void prep_all(const float* __restrict__ wq, const float* __restrict__ wk,
                         const float* __restrict__ wv, const float* __restrict__ w1,
                         const float* __restrict__ w2) {
    const int NWQ = NQ * 192, NW1 = 768 * 192, NW2 = 192 * 768;
    for (int i = blockIdx.x * blockDim.x + threadIdx.x; i < NWQ + NW1 + NW2;
         i += gridDim.x * blockDim.x) {
        float v = 0.f;
        char* p;
        if (i < NWQ) {
            int n = i / 192, k = i % 192;
            if (n < 540 && k < Cc) {
                int mat = n / Cc, m = n % Cc;
                int hh = m / HDd, d = m % HDd;
                const float* W = (mat == 0 ? wq : (mat == 1 ? wk : wv));
                v = W[(size_t)hh * (Cc*HDd) + (size_t)k * HDd + d];
            }
            p = g_WQB + (n >> 6) * QBLK + (n & 63) * 400 + k * 2;
        } else if (i < NWQ + NW1) {
            int j = i - NWQ;
            int n = j / 192, k = j % 192;
            if (n < Ff && k < Cc) v = w1[(size_t)k * Ff + n];
            p = g_W1B + (n >> 6) * W1BLK + (n & 63) * 400 + k * 2;
        } else {
            int j = i - NWQ - NW1;
            int n = j / 768, k = j % 768;
            if (n < Cc && k < Ff) v = w2[(size_t)k * Cc + n];
            p = g_W2B + (k >> 6) * W2BLK + n * 144 + (k & 63) * 2;
        }
        *(__half*)p = __float2half_rn(v);
    }
}

// ============================================================================
// Kernel 1: LN1 + QKV GEMM — 512 threads, N-split warps
// ============================================================================
#define NTK 512
#define QA1HI 0
#define QA1LO 51200
#define QB0   102400
#define QB1   128000
#define QBAR  153600
#define SMQ_TOTAL 153728

__global__ void __launch_bounds__(NTK, 1) ln1qkv_kernel(
    const float* __restrict__ x,
    const float* __restrict__ g1, const float* __restrict__ be1)
{
    extern __shared__ char sm2[];
    const unsigned sb = smem_u32(sm2);
    const int tid = threadIdx.x;
    const int w   = tid >> 5;
    const int ln  = tid & 31;
    const int g   = ln >> 2;
    const int ti  = ln & 3;
    const int rg  = w & 7;         // row group (16 rows)
    const int nh  = w >> 3;        // N half
    const size_t row0 = (size_t)blockIdx.x * 128;

    if (tid == 0) { MBAR_INIT(sb + QBAR, 1); MBAR_INIT(sb + QBAR + 8, 1); }
    __syncthreads();
    if (tid == 0) {
        MBAR_EXPECT_TX(sb + QBAR, QBLK);
        BULK_LD(sb + QB0, g_WQB, QBLK, sb + QBAR);
    }

    // ---- LN1 + fp16 hi/lo split -> A ----
    for (int r = w; r < 128; r += 16) {
        const float* xr = x + (row0 + r) * Cc;
        float s = 0.f, s2 = 0.f;
        for (int c = ln; c < Cc; c += 32) { float v = xr[c]; s += v; s2 += v*v; }
        #pragma unroll
        for (int o = 16; o; o >>= 1) {
            s  += __shfl_xor_sync(0xffffffffu, s,  o);
            s2 += __shfl_xor_sync(0xffffffffu, s2, o);
        }
        float mu = s * (1.f/Cc);
        float inv = rsqrtf(s2 * (1.f/Cc) - mu*mu + EPS);
        for (int cp = ln; cp < 96; cp += 32) {
            int c0 = cp * 2;
            float v0 = (c0   < Cc) ? (xr[c0]  -mu)*inv*g1[c0]   + be1[c0]   : 0.f;
            float v1 = (c0+1 < Cc) ? (xr[c0+1]-mu)*inv*g1[c0+1] + be1[c0+1] : 0.f;
            unsigned hp, lp;
            split2h(v0, v1, hp, lp);
            unsigned off = (unsigned)(r*400 + c0*2);
            *(unsigned*)(sm2 + QA1HI + off) = hp;
            *(unsigned*)(sm2 + QA1LO + off) = lp;
        }
    }
    __syncthreads();

    const unsigned a1addr = sb + QA1HI + (unsigned)((rg*16 + (ln & 15))*400 + (ln >> 4)*16);
    const int brow = ln & 7;
    const int boff = ((ln >> 3) & 3) * 16;

    int ph0 = 0, ph1 = 0;
    for (int nt = 0; nt < 9; nt++) {
        const int c = nt & 1;
        MBAR_WAIT(sb + QBAR + 8*c, (c ? ph1 : ph0));
        if (c) ph1 ^= 1; else ph0 ^= 1;
        __syncthreads();
        if (nt < 8 && tid == 0) {
            MBAR_EXPECT_TX(sb + QBAR + 8*(c^1), QBLK);
            BULK_LD(sb + (c ? QB0 : QB1), g_WQB + (size_t)(nt+1)*QBLK, QBLK, sb + QBAR + 8*(c^1));
        }

        const unsigned bbase = sb + (c ? QB1 : QB0);
        float C1[16];
        #pragma unroll
        for (int i = 0; i < 16; i++) C1[i] = 0.f;
        for (int p = 0; p < 6; p++) {
            unsigned ah0[4], al0[4], ah1[4], al1[4];
            ldsm_x4(ah0, a1addr + p*64);
            ldsm_x4(al0, a1addr + (QA1LO - QA1HI) + p*64);
            ldsm_x4(ah1, a1addr + p*64 + 32);
            ldsm_x4(al1, a1addr + (QA1LO - QA1HI) + p*64 + 32);
            #pragma unroll
            for (int na = 0; na < 4; na++) {
                unsigned bf[4];
                ldsm_x4(bf, bbase + (unsigned)((nh*32 + na*8 + brow)*400 + p*64 + boff));
                mma16816(C1 + na*4, ah0, bf);
                mma16816(C1 + na*4, al0, bf);
                mma16816(C1 + na*4, ah1, bf + 2);
                mma16816(C1 + na*4, al1, bf + 2);
            }
        }

        {
            size_t rA = row0 + rg*16 + g;
            size_t rB = rA + 8;
            #pragma unroll
            for (int na = 0; na < 4; na++) {
                int col = nt*64 + nh*32 + na*8 + 2*ti;
                *(float2*)(g_QKVS + rA*NQ + col) = make_float2(C1[na*4+0], C1[na*4+1]);
                *(float2*)(g_QKVS + rB*NQ + col) = make_float2(C1[na*4+2], C1[na*4+3]);
            }
        }
    }
}

// ============================================================================
// Kernel 2: softmax + A@V + residual -> g_X2  (R6, proven)
// ============================================================================
#define PD31 31
#define PT33 33
#define SMH_Q 0
#define SMH_K (2*Tt*PD31)
#define SMH_V (4*Tt*PD31)
#define SMH_S (6*Tt*PD31)
#define SMH_TOTAL (SMH_S + 2*Tt*PT33)

__global__ void __launch_bounds__(64, 7) attn2_kernel(const float* __restrict__ x)
{
    extern __shared__ float sm[];
    const int b   = blockIdx.x;
    const int hp  = blockIdx.y;
    const int tid = threadIdx.x;
    const int wi  = tid >> 5;
    const int ln  = tid & 31;

    const float* base = g_QKVS + (size_t)b * (Tt*NQ);
    #pragma unroll
    for (int m = 0; m < 3; m++) {
        float* dst = sm + m * (2*Tt*PD31);
        for (int e = tid; e < 2*Tt*HDd; e += 64) {
            int hl = e / (Tt*HDd);
            int rem = e - hl*(Tt*HDd);
            int r = rem / HDd, d = rem - r*HDd;
            dst[hl*(Tt*PD31) + r*PD31 + d] = base[(size_t)r*NQ + m*Cc + (hp*2+hl)*HDd + d];
        }
    }
    __syncthreads();

    const float* qsw = sm + SMH_Q + wi*(Tt*PD31);
    const float* ksw = sm + SMH_K + wi*(Tt*PD31);
    const float* vsw = sm + SMH_V + wi*(Tt*PD31);
    float* ssw = sm + SMH_S + wi*(Tt*PT33);

    for (int ti = 0; ti < Tt; ti++) {
        const float* qp = qsw + ti*PD31;
        const float* kp = ksw + ln*PD31;
        float dot = 0.f;
        #pragma unroll
        for (int d = 0; d < HDd; d++) dot += qp[d] * kp[d];
        dot *= 0.18257418583505537f;
        float val = (ln <= ti) ? dot : -1e30f;
        float m = val;
        #pragma unroll
        for (int o = 16; o; o >>= 1) m = fmaxf(m, __shfl_xor_sync(0xffffffffu, m, o));
        float e = (ln <= ti) ? __expf(val - m) : 0.f;
        float sum = e;
        #pragma unroll
        for (int o = 16; o; o >>= 1) sum += __shfl_xor_sync(0xffffffffu, sum, o);
        ssw[ti*PT33 + ln] = e / sum;
    }
    __syncwarp();

    float acc[HDd];
    #pragma unroll
    for (int d = 0; d < HDd; d++) acc[d] = 0.f;
    const float* prow = ssw + ln*PT33;
    #pragma unroll 4
    for (int tj = 0; tj < Tt; tj++) {
        float p = prow[tj];
        const float* vr = vsw + tj*PD31;
        #pragma unroll
        for (int d = 0; d < HDd; d++) acc[d] += p * vr[d];
    }

    {
        size_t off = ((size_t)b*Tt + ln) * Cc + (hp*2 + wi)*HDd;
        const float* xr = x + off;
        float* og = g_X2 + off;
        #pragma unroll
        for (int d = 0; d < HDd; d++) og[d] = xr[d] + acc[d];
    }
}

// ============================================================================
// Kernel 3: LN2 + MLP — 512 threads, N-split warps, A2 via smem
// ============================================================================
#define A1HI  0
#define A1LO  51200
#define A2HI  102400    // 128 x 144B
#define A2LO  120832
#define B1S_  139264    // 25600
#define B2S_  164864    // 27648
#define MBARS 192512
#define BIAS  192528    // float[768]
#define SM2_TOTAL 195616

__global__ void __launch_bounds__(NTK, 1) mlp_kernel(
    const float* __restrict__ g2, const float* __restrict__ be2,
    const float* __restrict__ b1, const float* __restrict__ b2,
    float* __restrict__ out)
{
    extern __shared__ char sm2[];
    const unsigned sb = smem_u32(sm2);
    const int tid = threadIdx.x;
    const int w   = tid >> 5;
    const int ln  = tid & 31;
    const int g   = ln >> 2;
    const int ti  = ln & 3;
    const int rg  = w & 7;
    const int nh  = w >> 3;
    const size_t row0 = (size_t)blockIdx.x * 128;
    float* b1s = (float*)(sm2 + BIAS);

    if (tid == 0) { MBAR_INIT(sb + MBARS, 1); MBAR_INIT(sb + MBARS + 8, 1); }
    __syncthreads();
    if (tid == 0) {
        MBAR_EXPECT_TX(sb + MBARS, W1BLK);
        BULK_LD(sb + B1S_, g_W1B, W1BLK, sb + MBARS);
        MBAR_EXPECT_TX(sb + MBARS + 8, W2BLK);
        BULK_LD(sb + B2S_, g_W2B, W2BLK, sb + MBARS + 8);
    }

    for (int i = tid; i < 768; i += NTK) b1s[i] = (i < Ff) ? b1[i] : 0.f;

    // ---- LN2 + fp16 split -> A1 ----
    for (int r = w; r < 128; r += 16) {
        const float* xr = g_X2 + (row0 + r) * Cc;
        float s = 0.f, s2 = 0.f;
        for (int c = ln; c < Cc; c += 32) { float v = xr[c]; s += v; s2 += v*v; }
        #pragma unroll
        for (int o = 16; o; o >>= 1) {
            s  += __shfl_xor_sync(0xffffffffu, s,  o);
            s2 += __shfl_xor_sync(0xffffffffu, s2, o);
        }
        float mu = s * (1.f/Cc);
        float inv = rsqrtf(s2 * (1.f/Cc) - mu*mu + EPS);
        for (int cp = ln; cp < 96; cp += 32) {
            int c0 = cp * 2;
            float v0 = (c0   < Cc) ? (xr[c0]  -mu)*inv*g2[c0]   + be2[c0]   : 0.f;
            float v1 = (c0+1 < Cc) ? (xr[c0+1]-mu)*inv*g2[c0+1] + be2[c0+1] : 0.f;
            unsigned hp, lp;
            split2h(v0, v1, hp, lp);
            unsigned off = (unsigned)(r*400 + c0*2);
            *(unsigned*)(sm2 + A1HI + off) = hp;
            *(unsigned*)(sm2 + A1LO + off) = lp;
        }
    }
    __syncthreads();

    float C2[48];
    #pragma unroll
    for (int i = 0; i < 48; i++) C2[i] = 0.f;

    const unsigned a1addr = sb + A1HI + (unsigned)((rg*16 + (ln & 15))*400 + (ln >> 4)*16);
    const unsigned a2addr = sb + A2HI + (unsigned)((rg*16 + (ln & 15))*144 + (ln >> 4)*16);
    const int brow = ln & 7;
    const int boff = ((ln >> 3) & 3) * 16;

    int p1 = 0, p2 = 0;
    for (int nt = 0; nt < 12; nt++) {
        MBAR_WAIT(sb + MBARS, p1); p1 ^= 1;

        // ---- GEMM1: warp computes 16 rows x 32 cols (its N half) ----
        float C1[16];
        #pragma unroll
        for (int i = 0; i < 16; i++) C1[i] = 0.f;
        for (int p = 0; p < 6; p++) {
            unsigned ah0[4], al0[4], ah1[4], al1[4];
            ldsm_x4(ah0, a1addr + p*64);
            ldsm_x4(al0, a1addr + (A1LO - A1HI) + p*64);
            ldsm_x4(ah1, a1addr + p*64 + 32);
            ldsm_x4(al1, a1addr + (A1LO - A1HI) + p*64 + 32);
            #pragma unroll
            for (int na = 0; na < 4; na++) {
                unsigned bf[4];
                ldsm_x4(bf, sb + B1S_ + (unsigned)((nh*32 + na*8 + brow)*400 + p*64 + boff));
                mma16816(C1 + na*4, ah0, bf);
                mma16816(C1 + na*4, al0, bf);
                mma16816(C1 + na*4, ah1, bf + 2);
                mma16816(C1 + na*4, al1, bf + 2);
            }
        }

        // ---- epilogue1: bias + relu + split -> A2 smem ----
        {
            int rA = rg*16 + g;
            #pragma unroll
            for (int na = 0; na < 4; na++) {
                int kc = nh*32 + na*8 + 2*ti;       // col within tile
                int colT = nt*64 + kc;               // global hidden col
                float bb0 = b1s[colT], bb1 = b1s[colT+1];
                unsigned hp, lp;
                split2h(fmaxf(C1[na*4+0]+bb0, 0.f), fmaxf(C1[na*4+1]+bb1, 0.f), hp, lp);
                *(unsigned*)(sm2 + A2HI + rA*144 + kc*2) = hp;
                *(unsigned*)(sm2 + A2LO + rA*144 + kc*2) = lp;
                split2h(fmaxf(C1[na*4+2]+bb0, 0.f), fmaxf(C1[na*4+3]+bb1, 0.f), hp, lp);
                *(unsigned*)(sm2 + A2HI + (rA+8)*144 + kc*2) = hp;
                *(unsigned*)(sm2 + A2LO + (rA+8)*144 + kc*2) = lp;
            }
        }

        __syncthreads();   // A2 complete; B1[nt] consumed
        if (nt < 11 && tid == 0) {
            MBAR_EXPECT_TX(sb + MBARS, W1BLK);
            BULK_LD(sb + B1S_, g_W1B + (size_t)(nt+1)*W1BLK, W1BLK, sb + MBARS);
        }

        MBAR_WAIT(sb + MBARS + 8, p2); p2 ^= 1;

        // ---- GEMM2: warp accumulates 16 rows x 96 cols (its N half) ----
        for (int p = 0; p < 2; p++) {
            unsigned ah0[4], al0[4], ah1[4], al1[4];
            ldsm_x4(ah0, a2addr + p*64);
            ldsm_x4(al0, a2addr + (A2LO - A2HI) + p*64);
            ldsm_x4(ah1, a2addr + p*64 + 32);
            ldsm_x4(al1, a2addr + (A2LO - A2HI) + p*64 + 32);
            #pragma unroll
            for (int na = 0; na < 12; na++) {
                unsigned bf[4];
                ldsm_x4(bf, sb + B2S_ + (unsigned)((nh*96 + na*8 + brow)*144 + p*64 + boff));
                mma16816(C2 + na*4, ah0, bf);
                mma16816(C2 + na*4, al0, bf);
                mma16816(C2 + na*4, ah1, bf + 2);
                mma16816(C2 + na*4, al1, bf + 2);
            }
        }
        __syncthreads();   // A2 + B2[nt] consumed
        if (nt < 11 && tid == 0) {
            MBAR_EXPECT_TX(sb + MBARS + 8, W2BLK);
            BULK_LD(sb + B2S_, g_W2B + (size_t)(nt+1)*W2BLK, W2BLK, sb + MBARS + 8);
        }
    }

    // ---- final: C2 + b2 + residual -> out ----
    {
        size_t rA = row0 + rg*16 + g;
        size_t rB = rA + 8;
        #pragma unroll
        for (int na = 0; na < 12; na++) {
            int col = nh*96 + na*8 + 2*ti;
            if (col < Cc) {
                float b20 = __ldg(b2 + col), b21 = __ldg(b2 + col + 1);
                out[rA*Cc + col]     = C2[na*4+0] + b20 + g_X2[rA*Cc + col];
                out[rA*Cc + col + 1] = C2[na*4+1] + b21 + g_X2[rA*Cc + col + 1];
                out[rB*Cc + col]     = C2[na*4+2] + b20 + g_X2[rB*Cc + col];
                out[rB*Cc + col + 1] = C2[na*4+3] + b21 + g_X2[rB*Cc + col + 1];
            }
        }
    }
}

// ============================================================================
// Launch
// ============================================================================
extern "C" void kernel_launch(void* const* d_in, const int* in_sizes, int n_in,
                              void* d_out, int out_size) {
    const float* x   = (const float*)d_in[0];
    const float* wq  = (const float*)d_in[1];
    const float* wk  = (const float*)d_in[2];
    const float* wv  = (const float*)d_in[3];
    const float* g1  = (const float*)d_in[4];
    const float* be1 = (const float*)d_in[5];
    const float* g2  = (const float*)d_in[6];
    const float* be2 = (const float*)d_in[7];
    const float* w1  = (const float*)d_in[8];
    const float* b1  = (const float*)d_in[9];
    const float* w2  = (const float*)d_in[10];
    const float* b2  = (const float*)d_in[11];
    float* out = (float*)d_out;

    cudaFuncSetAttribute(ln1qkv_kernel, cudaFuncAttributeMaxDynamicSharedMemorySize, SMQ_TOTAL);
    cudaFuncSetAttribute(attn2_kernel, cudaFuncAttributeMaxDynamicSharedMemorySize,
                         SMH_TOTAL * (int)sizeof(float));
    cudaFuncSetAttribute(mlp_kernel, cudaFuncAttributeMaxDynamicSharedMemorySize, SM2_TOTAL);

    prep_all<<<148, 256>>>(wq, wk, wv, w1, w2);
    ln1qkv_kernel<<<ROWS / 128, NTK, SMQ_TOTAL>>>(x, g1, be1);
    dim3 agrid(Bb, 3);
    attn2_kernel<<<agrid, 64, SMH_TOTAL * sizeof(float)>>>(x);
    mlp_kernel<<<ROWS / 128, NTK, SM2_TOTAL>>>(g2, be2, b1, b2, out);
}

// round 11
// speedup vs baseline: 2.9075x; 1.1240x over previous
#include <cuda_runtime.h>
#include <cuda_fp16.h>
#include <math.h>
#include <stdint.h>

#define Bb 4096
#define Tt 32
#define Cc 180
#define Hh 6
#define HDd 30
#define Ff 720
#define EPS 1e-5f
#define ROWS (Bb*Tt)
#define NQ 576

#define QBLK  25600
#define W1BLK 25600
#define W2BLK 27648

// ============================================================================
// Device scratch
// ============================================================================
__device__ float g_X2[(size_t)ROWS * Cc];
__device__ float g_QKVS[(size_t)ROWS * NQ];
__device__ __align__(16) char g_WQB[9  * QBLK];
__device__ __align__(16) char g_W1B[12 * W1BLK];
__device__ __align__(16) char g_W2B[12 * W2BLK];

// ============================================================================
// helpers
// ============================================================================
__device__ __forceinline__ unsigned smem_u32(const void* p) {
    unsigned a;
    asm("{ .reg .u64 t; cvta.to.shared.u64 t, %1; cvt.u32.u64 %0, t; }" : "=r"(a) : "l"(p));
    return a;
}
__device__ __forceinline__ void ldsm_x4(unsigned* r, unsigned addr) {
    asm volatile("ldmatrix.sync.aligned.m8n8.x4.shared.b16 {%0,%1,%2,%3}, [%4];"
                 : "=r"(r[0]), "=r"(r[1]), "=r"(r[2]), "=r"(r[3]) : "r"(addr));
}
__device__ __forceinline__ void mma16816(float* c, const unsigned* a, const unsigned* b) {
    asm volatile(
        "mma.sync.aligned.m16n8k16.row.col.f32.f16.f16.f32 "
        "{%0,%1,%2,%3}, {%4,%5,%6,%7}, {%8,%9}, {%0,%1,%2,%3};"
        : "+f"(c[0]), "+f"(c[1]), "+f"(c[2]), "+f"(c[3])
        : "r"(a[0]), "r"(a[1]), "r"(a[2]), "r"(a[3]), "r"(b[0]), "r"(b[1]));
}
__device__ __forceinline__ void split2h(float v0, float v1, unsigned& hp, unsigned& lp) {
    __half h0 = __float2half_rn(v0);
    __half l0 = __float2half_rn(v0 - __half2float(h0));
    __half h1 = __float2half_rn(v1);
    __half l1 = __float2half_rn(v1 - __half2float(h1));
    __half2 hh = __halves2half2(h0, h1);
    __half2 ll = __halves2half2(l0, l1);
    hp = *reinterpret_cast<unsigned*>(&hh);
    lp = *reinterpret_cast<unsigned*>(&ll);
}
#define MBAR_INIT(mb, c) \
    asm volatile("mbarrier.init.shared.b64 [%0], %1;" :: "r"((unsigned)(mb)), "r"((unsigned)(c)) : "memory")
#define MBAR_EXPECT_TX(mb, tx) \
    asm volatile("mbarrier.arrive.expect_tx.shared.b64 _, [%0], %1;" :: "r"((unsigned)(mb)), "r"((unsigned)(tx)) : "memory")
#define MBAR_WAIT(mb, par) do { \
    unsigned _m = (unsigned)(mb); unsigned _p = (unsigned)(par); unsigned _d; \
    asm volatile("{\n\t.reg .pred p;\n\t" \
        "mbarrier.try_wait.parity.acquire.cta.shared::cta.b64 p, [%1], %2;\n\t" \
        "selp.b32 %0, 1, 0, p;\n\t}" : "=r"(_d) : "r"(_m), "r"(_p) : "memory"); \
    if (!_d) { \
        asm volatile("{\n\t.reg .pred P1;\n\t" \
            "WL_%=:\n\t" \
            "mbarrier.try_wait.parity.acquire.cta.shared::cta.b64 P1, [%0], %1, 0x989680;\n\t" \
            "@P1 bra.uni WD_%=;\n\t" \
            "bra.uni WL_%=;\n\t" \
            "WD_%=:\n\t}" :: "r"(_m), "r"(_p) : "memory"); \
    } } while (0)
#define BULK_LD(dst, src, sz, mb) \
    asm volatile("cp.async.bulk.shared::cluster.global.mbarrier::complete_tx::bytes [%0], [%1], %2, [%3];" \
                 :: "r"((unsigned)(dst)), "l"(src), "r"((unsigned)(sz)), "r"((unsigned)(mb)) : "memory")

// ============================================================================
// Prep
// ============================================================================
__global__ void prep_all(const float* __restrict__ wq, const float* __restrict__ wk,
                         const float* __restrict__ wv, const float* __restrict__ w1,
                         const float* __restrict__ w2) {
    const int NWQ = NQ * 192, NW1 = 768 * 192, NW2 = 192 * 768;
    for (int i = blockIdx.x * blockDim.x + threadIdx.x; i < NWQ + NW1 + NW2;
         i += gridDim.x * blockDim.x) {
        float v = 0.f;
        char* p;
        if (i < NWQ) {
            int n = i / 192, k = i % 192;
            if (n < 540 && k < Cc) {
                int mat = n / Cc, m = n % Cc;
                int hh = m / HDd, d = m % HDd;
                const float* W = (mat == 0 ? wq : (mat == 1 ? wk : wv));
                v = W[(size_t)hh * (Cc*HDd) + (size_t)k * HDd + d];
            }
            p = g_WQB + (n >> 6) * QBLK + (n & 63) * 400 + k * 2;
        } else if (i < NWQ + NW1) {
            int j = i - NWQ;
            int n = j / 192, k = j % 192;
            if (n < Ff && k < Cc) v = w1[(size_t)k * Ff + n];
            p = g_W1B + (n >> 6) * W1BLK + (n & 63) * 400 + k * 2;
        } else {
            int j = i - NWQ - NW1;
            int n = j / 768, k = j % 768;
            if (n < Cc && k < Ff) v = w2[(size_t)k * Cc + n];
            p = g_W2B + (k >> 6) * W2BLK + n * 144 + (k & 63) * 2;
        }
        *(__half*)p = __float2half_rn(v);
    }
}

// ============================================================================
// Kernel 1: LN1 + QKV GEMM — 512 threads, N-split, interleaved MMA
// ============================================================================
#define NTK 512
#define QA1HI 0
#define QA1LO 51200
#define QB0   102400
#define QB1   128000
#define QBAR  153600
#define SMQ_TOTAL 153728

__global__ void __launch_bounds__(NTK, 1) ln1qkv_kernel(
    const float* __restrict__ x,
    const float* __restrict__ g1, const float* __restrict__ be1)
{
    extern __shared__ char sm2[];
    const unsigned sb = smem_u32(sm2);
    const int tid = threadIdx.x;
    const int w   = tid >> 5;
    const int ln  = tid & 31;
    const int g   = ln >> 2;
    const int ti  = ln & 3;
    const int rg  = w & 7;
    const int nh  = w >> 3;
    const size_t row0 = (size_t)blockIdx.x * 128;

    if (tid == 0) { MBAR_INIT(sb + QBAR, 1); MBAR_INIT(sb + QBAR + 8, 1); }
    __syncthreads();
    if (tid == 0) {
        MBAR_EXPECT_TX(sb + QBAR, QBLK);
        BULK_LD(sb + QB0, g_WQB, QBLK, sb + QBAR);
    }

    for (int r = w; r < 128; r += 16) {
        const float* xr = x + (row0 + r) * Cc;
        float s = 0.f, s2 = 0.f;
        for (int c = ln; c < Cc; c += 32) { float v = xr[c]; s += v; s2 += v*v; }
        #pragma unroll
        for (int o = 16; o; o >>= 1) {
            s  += __shfl_xor_sync(0xffffffffu, s,  o);
            s2 += __shfl_xor_sync(0xffffffffu, s2, o);
        }
        float mu = s * (1.f/Cc);
        float inv = rsqrtf(s2 * (1.f/Cc) - mu*mu + EPS);
        for (int cp = ln; cp < 96; cp += 32) {
            int c0 = cp * 2;
            float v0 = (c0   < Cc) ? (xr[c0]  -mu)*inv*g1[c0]   + be1[c0]   : 0.f;
            float v1 = (c0+1 < Cc) ? (xr[c0+1]-mu)*inv*g1[c0+1] + be1[c0+1] : 0.f;
            unsigned hp, lp;
            split2h(v0, v1, hp, lp);
            unsigned off = (unsigned)(r*400 + c0*2);
            *(unsigned*)(sm2 + QA1HI + off) = hp;
            *(unsigned*)(sm2 + QA1LO + off) = lp;
        }
    }
    __syncthreads();

    const unsigned a1addr = sb + QA1HI + (unsigned)((rg*16 + (ln & 15))*400 + (ln >> 4)*16);
    const int brow = ln & 7;
    const int boff = ((ln >> 3) & 3) * 16;

    int ph0 = 0, ph1 = 0;
    for (int nt = 0; nt < 9; nt++) {
        const int c = nt & 1;
        MBAR_WAIT(sb + QBAR + 8*c, (c ? ph1 : ph0));
        if (c) ph1 ^= 1; else ph0 ^= 1;
        __syncthreads();
        if (nt < 8 && tid == 0) {
            MBAR_EXPECT_TX(sb + QBAR + 8*(c^1), QBLK);
            BULK_LD(sb + (c ? QB0 : QB1), g_WQB + (size_t)(nt+1)*QBLK, QBLK, sb + QBAR + 8*(c^1));
        }

        const unsigned bbase = sb + (c ? QB1 : QB0);
        float C1[16];
        #pragma unroll
        for (int i = 0; i < 16; i++) C1[i] = 0.f;
        for (int p = 0; p < 6; p++) {
            unsigned ah0[4], al0[4], ah1[4], al1[4];
            ldsm_x4(ah0, a1addr + p*64);
            ldsm_x4(al0, a1addr + (QA1LO - QA1HI) + p*64);
            ldsm_x4(ah1, a1addr + p*64 + 32);
            ldsm_x4(al1, a1addr + (QA1LO - QA1HI) + p*64 + 32);
            unsigned bf[4][4];
            #pragma unroll
            for (int na = 0; na < 4; na++)
                ldsm_x4(bf[na], bbase + (unsigned)((nh*32 + na*8 + brow)*400 + p*64 + boff));
            // term-major: 4 independent MMAs between dependent pairs
            #pragma unroll
            for (int na = 0; na < 4; na++) mma16816(C1 + na*4, ah0, bf[na]);
            #pragma unroll
            for (int na = 0; na < 4; na++) mma16816(C1 + na*4, al0, bf[na]);
            #pragma unroll
            for (int na = 0; na < 4; na++) mma16816(C1 + na*4, ah1, bf[na] + 2);
            #pragma unroll
            for (int na = 0; na < 4; na++) mma16816(C1 + na*4, al1, bf[na] + 2);
        }

        {
            size_t rA = row0 + rg*16 + g;
            size_t rB = rA + 8;
            #pragma unroll
            for (int na = 0; na < 4; na++) {
                int col = nt*64 + nh*32 + na*8 + 2*ti;
                *(float2*)(g_QKVS + rA*NQ + col) = make_float2(C1[na*4+0], C1[na*4+1]);
                *(float2*)(g_QKVS + rB*NQ + col) = make_float2(C1[na*4+2], C1[na*4+3]);
            }
        }
    }
}

// ============================================================================
// Kernel 2: softmax + A@V + residual — lane-per-row, no shuffles
// ============================================================================
#define PD32 32
#define SMH_TOTAL (6*Tt*PD32)    // 6144 floats = 24576 B

__global__ void __launch_bounds__(64, 8) attn2_kernel(const float* __restrict__ x)
{
    extern __shared__ float sm[];
    const int b   = blockIdx.x;
    const int hp  = blockIdx.y;
    const int tid = threadIdx.x;
    const int wi  = tid >> 5;
    const int ln  = tid & 31;

    const float* base = g_QKVS + (size_t)b * (Tt*NQ);
    #pragma unroll
    for (int m = 0; m < 3; m++) {
        float* dst = sm + m * (2*Tt*PD32);
        for (int e = tid; e < 2*Tt*HDd; e += 64) {
            int hl = e / (Tt*HDd);
            int rem = e - hl*(Tt*HDd);
            int r = rem / HDd, d = rem - r*HDd;
            dst[hl*(Tt*PD32) + r*PD32 + d] = base[(size_t)r*NQ + m*Cc + (hp*2+hl)*HDd + d];
        }
    }
    __syncthreads();

    const float* qsw = sm + 0*(2*Tt*PD32) + wi*(Tt*PD32);
    const float* ksw = sm + 1*(2*Tt*PD32) + wi*(Tt*PD32);
    const float* vsw = sm + 2*(2*Tt*PD32) + wi*(Tt*PD32);

    // lane = query row ti = ln
    float q[HDd];
    #pragma unroll
    for (int d = 0; d < HDd; d++) q[d] = qsw[ln*PD32 + d];

    float sc[Tt];
    #pragma unroll 4
    for (int tj = 0; tj < Tt; tj++) {
        const float4* kr = (const float4*)(ksw + tj*PD32);
        float dot = 0.f;
        #pragma unroll
        for (int i = 0; i < 7; i++) {
            float4 kv = kr[i];
            dot += q[4*i+0]*kv.x + q[4*i+1]*kv.y + q[4*i+2]*kv.z + q[4*i+3]*kv.w;
        }
        dot += q[28]*ksw[tj*PD32+28] + q[29]*ksw[tj*PD32+29];
        sc[tj] = dot * 0.18257418583505537f;
    }

    // causal softmax entirely in-lane
    float m = -1e30f;
    #pragma unroll
    for (int tj = 0; tj < Tt; tj++) if (tj <= ln) m = fmaxf(m, sc[tj]);
    float sum = 0.f;
    #pragma unroll
    for (int tj = 0; tj < Tt; tj++) {
        float e = (tj <= ln) ? __expf(sc[tj] - m) : 0.f;
        sc[tj] = e;
        sum += e;
    }
    float inv = 1.f / sum;

    float acc[HDd];
    #pragma unroll
    for (int d = 0; d < HDd; d++) acc[d] = 0.f;
    #pragma unroll 4
    for (int tj = 0; tj < Tt; tj++) {
        float p = sc[tj] * inv;
        const float4* vr = (const float4*)(vsw + tj*PD32);
        #pragma unroll
        for (int i = 0; i < 7; i++) {
            float4 vv = vr[i];
            acc[4*i+0] += p*vv.x; acc[4*i+1] += p*vv.y;
            acc[4*i+2] += p*vv.z; acc[4*i+3] += p*vv.w;
        }
        acc[28] += p*vsw[tj*PD32+28];
        acc[29] += p*vsw[tj*PD32+29];
    }

    {
        size_t off = ((size_t)b*Tt + ln) * Cc + (hp*2 + wi)*HDd;
        const float* xr = x + off;
        float* og = g_X2 + off;
        #pragma unroll
        for (int d = 0; d < HDd; d++) og[d] = xr[d] + acc[d];
    }
}

// ============================================================================
// Kernel 3: LN2 + MLP — 512 threads, N-split, interleaved MMA, A2 via smem
// ============================================================================
#define A1HI  0
#define A1LO  51200
#define A2HI  102400
#define A2LO  120832
#define B1S_  139264
#define B2S_  164864
#define MBARS 192512
#define BIAS  192528
#define SM2_TOTAL 195616

__global__ void __launch_bounds__(NTK, 1) mlp_kernel(
    const float* __restrict__ g2, const float* __restrict__ be2,
    const float* __restrict__ b1, const float* __restrict__ b2,
    float* __restrict__ out)
{
    extern __shared__ char sm2[];
    const unsigned sb = smem_u32(sm2);
    const int tid = threadIdx.x;
    const int w   = tid >> 5;
    const int ln  = tid & 31;
    const int g   = ln >> 2;
    const int ti  = ln & 3;
    const int rg  = w & 7;
    const int nh  = w >> 3;
    const size_t row0 = (size_t)blockIdx.x * 128;
    float* b1s = (float*)(sm2 + BIAS);

    if (tid == 0) { MBAR_INIT(sb + MBARS, 1); MBAR_INIT(sb + MBARS + 8, 1); }
    __syncthreads();
    if (tid == 0) {
        MBAR_EXPECT_TX(sb + MBARS, W1BLK);
        BULK_LD(sb + B1S_, g_W1B, W1BLK, sb + MBARS);
        MBAR_EXPECT_TX(sb + MBARS + 8, W2BLK);
        BULK_LD(sb + B2S_, g_W2B, W2BLK, sb + MBARS + 8);
    }

    for (int i = tid; i < 768; i += NTK) b1s[i] = (i < Ff) ? b1[i] : 0.f;

    for (int r = w; r < 128; r += 16) {
        const float* xr = g_X2 + (row0 + r) * Cc;
        float s = 0.f, s2 = 0.f;
        for (int c = ln; c < Cc; c += 32) { float v = xr[c]; s += v; s2 += v*v; }
        #pragma unroll
        for (int o = 16; o; o >>= 1) {
            s  += __shfl_xor_sync(0xffffffffu, s,  o);
            s2 += __shfl_xor_sync(0xffffffffu, s2, o);
        }
        float mu = s * (1.f/Cc);
        float inv = rsqrtf(s2 * (1.f/Cc) - mu*mu + EPS);
        for (int cp = ln; cp < 96; cp += 32) {
            int c0 = cp * 2;
            float v0 = (c0   < Cc) ? (xr[c0]  -mu)*inv*g2[c0]   + be2[c0]   : 0.f;
            float v1 = (c0+1 < Cc) ? (xr[c0+1]-mu)*inv*g2[c0+1] + be2[c0+1] : 0.f;
            unsigned hp, lp;
            split2h(v0, v1, hp, lp);
            unsigned off = (unsigned)(r*400 + c0*2);
            *(unsigned*)(sm2 + A1HI + off) = hp;
            *(unsigned*)(sm2 + A1LO + off) = lp;
        }
    }
    __syncthreads();

    float C2[48];
    #pragma unroll
    for (int i = 0; i < 48; i++) C2[i] = 0.f;

    const unsigned a1addr = sb + A1HI + (unsigned)((rg*16 + (ln & 15))*400 + (ln >> 4)*16);
    const unsigned a2addr = sb + A2HI + (unsigned)((rg*16 + (ln & 15))*144 + (ln >> 4)*16);
    const int brow = ln & 7;
    const int boff = ((ln >> 3) & 3) * 16;

    int p1 = 0, p2 = 0;
    for (int nt = 0; nt < 12; nt++) {
        MBAR_WAIT(sb + MBARS, p1); p1 ^= 1;

        float C1[16];
        #pragma unroll
        for (int i = 0; i < 16; i++) C1[i] = 0.f;
        for (int p = 0; p < 6; p++) {
            unsigned ah0[4], al0[4], ah1[4], al1[4];
            ldsm_x4(ah0, a1addr + p*64);
            ldsm_x4(al0, a1addr + (A1LO - A1HI) + p*64);
            ldsm_x4(ah1, a1addr + p*64 + 32);
            ldsm_x4(al1, a1addr + (A1LO - A1HI) + p*64 + 32);
            unsigned bf[4][4];
            #pragma unroll
            for (int na = 0; na < 4; na++)
                ldsm_x4(bf[na], sb + B1S_ + (unsigned)((nh*32 + na*8 + brow)*400 + p*64 + boff));
            #pragma unroll
            for (int na = 0; na < 4; na++) mma16816(C1 + na*4, ah0, bf[na]);
            #pragma unroll
            for (int na = 0; na < 4; na++) mma16816(C1 + na*4, al0, bf[na]);
            #pragma unroll
            for (int na = 0; na < 4; na++) mma16816(C1 + na*4, ah1, bf[na] + 2);
            #pragma unroll
            for (int na = 0; na < 4; na++) mma16816(C1 + na*4, al1, bf[na] + 2);
        }

        // epilogue1: bias + relu + split -> A2 smem
        {
            int rA = rg*16 + g;
            #pragma unroll
            for (int na = 0; na < 4; na++) {
                int kc = nh*32 + na*8 + 2*ti;
                int colT = nt*64 + kc;
                float bb0 = b1s[colT], bb1 = b1s[colT+1];
                unsigned hp, lp;
                split2h(fmaxf(C1[na*4+0]+bb0, 0.f), fmaxf(C1[na*4+1]+bb1, 0.f), hp, lp);
                *(unsigned*)(sm2 + A2HI + rA*144 + kc*2) = hp;
                *(unsigned*)(sm2 + A2LO + rA*144 + kc*2) = lp;
                split2h(fmaxf(C1[na*4+2]+bb0, 0.f), fmaxf(C1[na*4+3]+bb1, 0.f), hp, lp);
                *(unsigned*)(sm2 + A2HI + (rA+8)*144 + kc*2) = hp;
                *(unsigned*)(sm2 + A2LO + (rA+8)*144 + kc*2) = lp;
            }
        }

        __syncthreads();
        if (nt < 11 && tid == 0) {
            MBAR_EXPECT_TX(sb + MBARS, W1BLK);
            BULK_LD(sb + B1S_, g_W1B + (size_t)(nt+1)*W1BLK, W1BLK, sb + MBARS);
        }

        MBAR_WAIT(sb + MBARS + 8, p2); p2 ^= 1;

        // GEMM2: 16 rows x 96 cols (N half), na-groups of 4, term-major
        for (int p = 0; p < 2; p++) {
            unsigned ah0[4], al0[4], ah1[4], al1[4];
            ldsm_x4(ah0, a2addr + p*64);
            ldsm_x4(al0, a2addr + (A2LO - A2HI) + p*64);
            ldsm_x4(ah1, a2addr + p*64 + 32);
            ldsm_x4(al1, a2addr + (A2LO - A2HI) + p*64 + 32);
            #pragma unroll
            for (int grp = 0; grp < 3; grp++) {
                unsigned bf[4][4];
                #pragma unroll
                for (int j = 0; j < 4; j++)
                    ldsm_x4(bf[j], sb + B2S_ + (unsigned)((nh*96 + (grp*4+j)*8 + brow)*144 + p*64 + boff));
                float* Cg = C2 + grp*16;
                #pragma unroll
                for (int j = 0; j < 4; j++) mma16816(Cg + j*4, ah0, bf[j]);
                #pragma unroll
                for (int j = 0; j < 4; j++) mma16816(Cg + j*4, al0, bf[j]);
                #pragma unroll
                for (int j = 0; j < 4; j++) mma16816(Cg + j*4, ah1, bf[j] + 2);
                #pragma unroll
                for (int j = 0; j < 4; j++) mma16816(Cg + j*4, al1, bf[j] + 2);
            }
        }
        __syncthreads();
        if (nt < 11 && tid == 0) {
            MBAR_EXPECT_TX(sb + MBARS + 8, W2BLK);
            BULK_LD(sb + B2S_, g_W2B + (size_t)(nt+1)*W2BLK, W2BLK, sb + MBARS + 8);
        }
    }

    {
        size_t rA = row0 + rg*16 + g;
        size_t rB = rA + 8;
        #pragma unroll
        for (int na = 0; na < 12; na++) {
            int col = nh*96 + na*8 + 2*ti;
            if (col < Cc) {
                float b20 = __ldg(b2 + col), b21 = __ldg(b2 + col + 1);
                out[rA*Cc + col]     = C2[na*4+0] + b20 + g_X2[rA*Cc + col];
                out[rA*Cc + col + 1] = C2[na*4+1] + b21 + g_X2[rA*Cc + col + 1];
                out[rB*Cc + col]     = C2[na*4+2] + b20 + g_X2[rB*Cc + col];
                out[rB*Cc + col + 1] = C2[na*4+3] + b21 + g_X2[rB*Cc + col + 1];
            }
        }
    }
}

// ============================================================================
// Launch
// ============================================================================
extern "C" void kernel_launch(void* const* d_in, const int* in_sizes, int n_in,
                              void* d_out, int out_size) {
    const float* x   = (const float*)d_in[0];
    const float* wq  = (const float*)d_in[1];
    const float* wk  = (const float*)d_in[2];
    const float* wv  = (const float*)d_in[3];
    const float* g1  = (const float*)d_in[4];
    const float* be1 = (const float*)d_in[5];
    const float* g2  = (const float*)d_in[6];
    const float* be2 = (const float*)d_in[7];
    const float* w1  = (const float*)d_in[8];
    const float* b1  = (const float*)d_in[9];
    const float* w2  = (const float*)d_in[10];
    const float* b2  = (const float*)d_in[11];
    float* out = (float*)d_out;

    cudaFuncSetAttribute(ln1qkv_kernel, cudaFuncAttributeMaxDynamicSharedMemorySize, SMQ_TOTAL);
    cudaFuncSetAttribute(attn2_kernel, cudaFuncAttributeMaxDynamicSharedMemorySize,
                         SMH_TOTAL * (int)sizeof(float));
    cudaFuncSetAttribute(mlp_kernel, cudaFuncAttributeMaxDynamicSharedMemorySize, SM2_TOTAL);

    prep_all<<<148, 256>>>(wq, wk, wv, w1, w2);
    ln1qkv_kernel<<<ROWS / 128, NTK, SMQ_TOTAL>>>(x, g1, be1);
    dim3 agrid(Bb, 3);
    attn2_kernel<<<agrid, 64, SMH_TOTAL * sizeof(float)>>>(x);
    mlp_kernel<<<ROWS / 128, NTK, SM2_TOTAL>>>(g2, be2, b1, b2, out);
}

// round 12
// speedup vs baseline: 3.3422x; 1.1495x over previous
#include <cuda_runtime.h>
#include <cuda_fp16.h>
#include <math.h>
#include <stdint.h>

#define Bb 4096
#define Tt 32
#define Cc 180
#define Hh 6
#define HDd 30
#define Ff 720
#define EPS 1e-5f
#define ROWS (Bb*Tt)
#define NQ 576

#define QBLK  25600
#define W1BLK 25600
#define W2BLK 27648

// ============================================================================
// Device scratch
// ============================================================================
__device__ float g_X2[(size_t)ROWS * Cc];
__device__ float g_QKVS[(size_t)ROWS * NQ];
__device__ __align__(16) char g_WQB[9  * QBLK];
__device__ __align__(16) char g_W1B[12 * W1BLK];
__device__ __align__(16) char g_W2B[12 * W2BLK];

// ============================================================================
// helpers
// ============================================================================
__device__ __forceinline__ unsigned smem_u32(const void* p) {
    unsigned a;
    asm("{ .reg .u64 t; cvta.to.shared.u64 t, %1; cvt.u32.u64 %0, t; }" : "=r"(a) : "l"(p));
    return a;
}
__device__ __forceinline__ void ldsm_x4(unsigned* r, unsigned addr) {
    asm volatile("ldmatrix.sync.aligned.m8n8.x4.shared.b16 {%0,%1,%2,%3}, [%4];"
                 : "=r"(r[0]), "=r"(r[1]), "=r"(r[2]), "=r"(r[3]) : "r"(addr));
}
__device__ __forceinline__ void mma16816(float* c, const unsigned* a, const unsigned* b) {
    asm volatile(
        "mma.sync.aligned.m16n8k16.row.col.f32.f16.f16.f32 "
        "{%0,%1,%2,%3}, {%4,%5,%6,%7}, {%8,%9}, {%0,%1,%2,%3};"
        : "+f"(c[0]), "+f"(c[1]), "+f"(c[2]), "+f"(c[3])
        : "r"(a[0]), "r"(a[1]), "r"(a[2]), "r"(a[3]), "r"(b[0]), "r"(b[1]));
}
__device__ __forceinline__ unsigned pack2h(float v0, float v1) {
    __half2 h = __halves2half2(__float2half_rn(v0), __float2half_rn(v1));
    return *reinterpret_cast<unsigned*>(&h);
}
#define MBAR_INIT(mb, c) \
    asm volatile("mbarrier.init.shared.b64 [%0], %1;" :: "r"((unsigned)(mb)), "r"((unsigned)(c)) : "memory")
#define MBAR_EXPECT_TX(mb, tx) \
    asm volatile("mbarrier.arrive.expect_tx.shared.b64 _, [%0], %1;" :: "r"((unsigned)(mb)), "r"((unsigned)(tx)) : "memory")
#define MBAR_WAIT(mb, par) do { \
    unsigned _m = (unsigned)(mb); unsigned _p = (unsigned)(par); unsigned _d; \
    asm volatile("{\n\t.reg .pred p;\n\t" \
        "mbarrier.try_wait.parity.acquire.cta.shared::cta.b64 p, [%1], %2;\n\t" \
        "selp.b32 %0, 1, 0, p;\n\t}" : "=r"(_d) : "r"(_m), "r"(_p) : "memory"); \
    if (!_d) { \
        asm volatile("{\n\t.reg .pred P1;\n\t" \
            "WL_%=:\n\t" \
            "mbarrier.try_wait.parity.acquire.cta.shared::cta.b64 P1, [%0], %1, 0x989680;\n\t" \
            "@P1 bra.uni WD_%=;\n\t" \
            "bra.uni WL_%=;\n\t" \
            "WD_%=:\n\t}" :: "r"(_m), "r"(_p) : "memory"); \
    } } while (0)
#define BULK_LD(dst, src, sz, mb) \
    asm volatile("cp.async.bulk.shared::cluster.global.mbarrier::complete_tx::bytes [%0], [%1], %2, [%3];" \
                 :: "r"((unsigned)(dst)), "l"(src), "r"((unsigned)(sz)), "r"((unsigned)(mb)) : "memory")

// ============================================================================
// Prep
// ============================================================================
__global__ void prep_all(const float* __restrict__ wq, const float* __restrict__ wk,
                         const float* __restrict__ wv, const float* __restrict__ w1,
                         const float* __restrict__ w2) {
    const int NWQ = NQ * 192, NW1 = 768 * 192, NW2 = 192 * 768;
    for (int i = blockIdx.x * blockDim.x + threadIdx.x; i < NWQ + NW1 + NW2;
         i += gridDim.x * blockDim.x) {
        float v = 0.f;
        char* p;
        if (i < NWQ) {
            int n = i / 192, k = i % 192;
            if (n < 540 && k < Cc) {
                int mat = n / Cc, m = n % Cc;
                int hh = m / HDd, d = m % HDd;
                const float* W = (mat == 0 ? wq : (mat == 1 ? wk : wv));
                v = W[(size_t)hh * (Cc*HDd) + (size_t)k * HDd + d];
            }
            p = g_WQB + (n >> 6) * QBLK + (n & 63) * 400 + k * 2;
        } else if (i < NWQ + NW1) {
            int j = i - NWQ;
            int n = j / 192, k = j % 192;
            if (n < Ff && k < Cc) v = w1[(size_t)k * Ff + n];
            p = g_W1B + (n >> 6) * W1BLK + (n & 63) * 400 + k * 2;
        } else {
            int j = i - NWQ - NW1;
            int n = j / 768, k = j % 768;
            if (n < Cc && k < Ff) v = w2[(size_t)k * Cc + n];
            p = g_W2B + (k >> 6) * W2BLK + n * 144 + (k & 63) * 2;
        }
        *(__half*)p = __float2half_rn(v);
    }
}

// ============================================================================
// Kernel 1: LN1 + QKV GEMM — fp16 single, 512 threads, N-split
// ============================================================================
#define NTK 512
#define QA1   0
#define QB0   51200
#define QB1   76800
#define QBAR  102400
#define SMQ_TOTAL 102528

__global__ void __launch_bounds__(NTK, 1) ln1qkv_kernel(
    const float* __restrict__ x,
    const float* __restrict__ g1, const float* __restrict__ be1)
{
    extern __shared__ char sm2[];
    const unsigned sb = smem_u32(sm2);
    const int tid = threadIdx.x;
    const int w   = tid >> 5;
    const int ln  = tid & 31;
    const int g   = ln >> 2;
    const int ti  = ln & 3;
    const int rg  = w & 7;
    const int nh  = w >> 3;
    const size_t row0 = (size_t)blockIdx.x * 128;

    if (tid == 0) { MBAR_INIT(sb + QBAR, 1); MBAR_INIT(sb + QBAR + 8, 1); }
    __syncthreads();
    if (tid == 0) {
        MBAR_EXPECT_TX(sb + QBAR, QBLK);
        BULK_LD(sb + QB0, g_WQB, QBLK, sb + QBAR);
    }

    // ---- LN1 -> fp16 A ----
    for (int r = w; r < 128; r += 16) {
        const float* xr = x + (row0 + r) * Cc;
        float s = 0.f, s2 = 0.f;
        for (int c = ln; c < Cc; c += 32) { float v = xr[c]; s += v; s2 += v*v; }
        #pragma unroll
        for (int o = 16; o; o >>= 1) {
            s  += __shfl_xor_sync(0xffffffffu, s,  o);
            s2 += __shfl_xor_sync(0xffffffffu, s2, o);
        }
        float mu = s * (1.f/Cc);
        float inv = rsqrtf(s2 * (1.f/Cc) - mu*mu + EPS);
        for (int cp = ln; cp < 96; cp += 32) {
            int c0 = cp * 2;
            float v0 = (c0   < Cc) ? (xr[c0]  -mu)*inv*g1[c0]   + be1[c0]   : 0.f;
            float v1 = (c0+1 < Cc) ? (xr[c0+1]-mu)*inv*g1[c0+1] + be1[c0+1] : 0.f;
            *(unsigned*)(sm2 + QA1 + r*400 + c0*2) = pack2h(v0, v1);
        }
    }
    __syncthreads();

    const unsigned a1addr = sb + QA1 + (unsigned)((rg*16 + (ln & 15))*400 + (ln >> 4)*16);
    const int brow = ln & 7;
    const int boff = ((ln >> 3) & 3) * 16;

    int ph0 = 0, ph1 = 0;
    for (int nt = 0; nt < 9; nt++) {
        const int c = nt & 1;
        MBAR_WAIT(sb + QBAR + 8*c, (c ? ph1 : ph0));
        if (c) ph1 ^= 1; else ph0 ^= 1;
        __syncthreads();
        if (nt < 8 && tid == 0) {
            MBAR_EXPECT_TX(sb + QBAR + 8*(c^1), QBLK);
            BULK_LD(sb + (c ? QB0 : QB1), g_WQB + (size_t)(nt+1)*QBLK, QBLK, sb + QBAR + 8*(c^1));
        }

        const unsigned bbase = sb + (c ? QB1 : QB0);
        float C1[16];
        #pragma unroll
        for (int i = 0; i < 16; i++) C1[i] = 0.f;
        for (int p = 0; p < 6; p++) {
            unsigned ah0[4], ah1[4];
            ldsm_x4(ah0, a1addr + p*64);
            ldsm_x4(ah1, a1addr + p*64 + 32);
            unsigned bf[4][4];
            #pragma unroll
            for (int na = 0; na < 4; na++)
                ldsm_x4(bf[na], bbase + (unsigned)((nh*32 + na*8 + brow)*400 + p*64 + boff));
            #pragma unroll
            for (int na = 0; na < 4; na++) mma16816(C1 + na*4, ah0, bf[na]);
            #pragma unroll
            for (int na = 0; na < 4; na++) mma16816(C1 + na*4, ah1, bf[na] + 2);
        }

        {
            size_t rA = row0 + rg*16 + g;
            size_t rB = rA + 8;
            #pragma unroll
            for (int na = 0; na < 4; na++) {
                int col = nt*64 + nh*32 + na*8 + 2*ti;
                *(float2*)(g_QKVS + rA*NQ + col) = make_float2(C1[na*4+0], C1[na*4+1]);
                *(float2*)(g_QKVS + rB*NQ + col) = make_float2(C1[na*4+2], C1[na*4+3]);
            }
        }
    }
}

// ============================================================================
// Kernel 2: softmax + A@V + residual — lane-per-row (R11, proven)
// ============================================================================
#define PD32 32
#define SMH_TOTAL (6*Tt*PD32)

__global__ void __launch_bounds__(64, 8) attn2_kernel(const float* __restrict__ x)
{
    extern __shared__ float sm[];
    const int b   = blockIdx.x;
    const int hp  = blockIdx.y;
    const int tid = threadIdx.x;
    const int wi  = tid >> 5;
    const int ln  = tid & 31;

    const float* base = g_QKVS + (size_t)b * (Tt*NQ);
    #pragma unroll
    for (int m = 0; m < 3; m++) {
        float* dst = sm + m * (2*Tt*PD32);
        for (int e = tid; e < 2*Tt*HDd; e += 64) {
            int hl = e / (Tt*HDd);
            int rem = e - hl*(Tt*HDd);
            int r = rem / HDd, d = rem - r*HDd;
            dst[hl*(Tt*PD32) + r*PD32 + d] = base[(size_t)r*NQ + m*Cc + (hp*2+hl)*HDd + d];
        }
    }
    __syncthreads();

    const float* qsw = sm + 0*(2*Tt*PD32) + wi*(Tt*PD32);
    const float* ksw = sm + 1*(2*Tt*PD32) + wi*(Tt*PD32);
    const float* vsw = sm + 2*(2*Tt*PD32) + wi*(Tt*PD32);

    float q[HDd];
    #pragma unroll
    for (int d = 0; d < HDd; d++) q[d] = qsw[ln*PD32 + d];

    float sc[Tt];
    #pragma unroll 4
    for (int tj = 0; tj < Tt; tj++) {
        const float4* kr = (const float4*)(ksw + tj*PD32);
        float dot = 0.f;
        #pragma unroll
        for (int i = 0; i < 7; i++) {
            float4 kv = kr[i];
            dot += q[4*i+0]*kv.x + q[4*i+1]*kv.y + q[4*i+2]*kv.z + q[4*i+3]*kv.w;
        }
        dot += q[28]*ksw[tj*PD32+28] + q[29]*ksw[tj*PD32+29];
        sc[tj] = dot * 0.18257418583505537f;
    }

    float m = -1e30f;
    #pragma unroll
    for (int tj = 0; tj < Tt; tj++) if (tj <= ln) m = fmaxf(m, sc[tj]);
    float sum = 0.f;
    #pragma unroll
    for (int tj = 0; tj < Tt; tj++) {
        float e = (tj <= ln) ? __expf(sc[tj] - m) : 0.f;
        sc[tj] = e;
        sum += e;
    }
    float inv = 1.f / sum;

    float acc[HDd];
    #pragma unroll
    for (int d = 0; d < HDd; d++) acc[d] = 0.f;
    #pragma unroll 4
    for (int tj = 0; tj < Tt; tj++) {
        float p = sc[tj] * inv;
        const float4* vr = (const float4*)(vsw + tj*PD32);
        #pragma unroll
        for (int i = 0; i < 7; i++) {
            float4 vv = vr[i];
            acc[4*i+0] += p*vv.x; acc[4*i+1] += p*vv.y;
            acc[4*i+2] += p*vv.z; acc[4*i+3] += p*vv.w;
        }
        acc[28] += p*vsw[tj*PD32+28];
        acc[29] += p*vsw[tj*PD32+29];
    }

    {
        size_t off = ((size_t)b*Tt + ln) * Cc + (hp*2 + wi)*HDd;
        const float* xr = x + off;
        float* og = g_X2 + off;
        #pragma unroll
        for (int d = 0; d < HDd; d++) og[d] = xr[d] + acc[d];
    }
}

// ============================================================================
// Kernel 3: LN2 + MLP — fp16 single, 512 threads, N-split, A2 via smem
// ============================================================================
#define A1S   0
#define A2S   51200     // 128 x 144B
#define B1S_  69632     // 25600
#define B2S_  95232     // 27648
#define MBARS 122880
#define BIAS  122896    // float[768]
#define SM2_TOTAL 125968

__global__ void __launch_bounds__(NTK, 1) mlp_kernel(
    const float* __restrict__ g2, const float* __restrict__ be2,
    const float* __restrict__ b1, const float* __restrict__ b2,
    float* __restrict__ out)
{
    extern __shared__ char sm2[];
    const unsigned sb = smem_u32(sm2);
    const int tid = threadIdx.x;
    const int w   = tid >> 5;
    const int ln  = tid & 31;
    const int g   = ln >> 2;
    const int ti  = ln & 3;
    const int rg  = w & 7;
    const int nh  = w >> 3;
    const size_t row0 = (size_t)blockIdx.x * 128;
    float* b1s = (float*)(sm2 + BIAS);

    if (tid == 0) { MBAR_INIT(sb + MBARS, 1); MBAR_INIT(sb + MBARS + 8, 1); }
    __syncthreads();
    if (tid == 0) {
        MBAR_EXPECT_TX(sb + MBARS, W1BLK);
        BULK_LD(sb + B1S_, g_W1B, W1BLK, sb + MBARS);
        MBAR_EXPECT_TX(sb + MBARS + 8, W2BLK);
        BULK_LD(sb + B2S_, g_W2B, W2BLK, sb + MBARS + 8);
    }

    for (int i = tid; i < 768; i += NTK) b1s[i] = (i < Ff) ? b1[i] : 0.f;

    // ---- LN2 -> fp16 A1 ----
    for (int r = w; r < 128; r += 16) {
        const float* xr = g_X2 + (row0 + r) * Cc;
        float s = 0.f, s2 = 0.f;
        for (int c = ln; c < Cc; c += 32) { float v = xr[c]; s += v; s2 += v*v; }
        #pragma unroll
        for (int o = 16; o; o >>= 1) {
            s  += __shfl_xor_sync(0xffffffffu, s,  o);
            s2 += __shfl_xor_sync(0xffffffffu, s2, o);
        }
        float mu = s * (1.f/Cc);
        float inv = rsqrtf(s2 * (1.f/Cc) - mu*mu + EPS);
        for (int cp = ln; cp < 96; cp += 32) {
            int c0 = cp * 2;
            float v0 = (c0   < Cc) ? (xr[c0]  -mu)*inv*g2[c0]   + be2[c0]   : 0.f;
            float v1 = (c0+1 < Cc) ? (xr[c0+1]-mu)*inv*g2[c0+1] + be2[c0+1] : 0.f;
            *(unsigned*)(sm2 + A1S + r*400 + c0*2) = pack2h(v0, v1);
        }
    }
    __syncthreads();

    float C2[48];
    #pragma unroll
    for (int i = 0; i < 48; i++) C2[i] = 0.f;

    const unsigned a1addr = sb + A1S + (unsigned)((rg*16 + (ln & 15))*400 + (ln >> 4)*16);
    const unsigned a2addr = sb + A2S + (unsigned)((rg*16 + (ln & 15))*144 + (ln >> 4)*16);
    const int brow = ln & 7;
    const int boff = ((ln >> 3) & 3) * 16;

    int p1 = 0, p2 = 0;
    for (int nt = 0; nt < 12; nt++) {
        MBAR_WAIT(sb + MBARS, p1); p1 ^= 1;

        float C1[16];
        #pragma unroll
        for (int i = 0; i < 16; i++) C1[i] = 0.f;
        for (int p = 0; p < 6; p++) {
            unsigned ah0[4], ah1[4];
            ldsm_x4(ah0, a1addr + p*64);
            ldsm_x4(ah1, a1addr + p*64 + 32);
            unsigned bf[4][4];
            #pragma unroll
            for (int na = 0; na < 4; na++)
                ldsm_x4(bf[na], sb + B1S_ + (unsigned)((nh*32 + na*8 + brow)*400 + p*64 + boff));
            #pragma unroll
            for (int na = 0; na < 4; na++) mma16816(C1 + na*4, ah0, bf[na]);
            #pragma unroll
            for (int na = 0; na < 4; na++) mma16816(C1 + na*4, ah1, bf[na] + 2);
        }

        // epilogue1: bias + relu -> fp16 A2 smem
        {
            int rA = rg*16 + g;
            #pragma unroll
            for (int na = 0; na < 4; na++) {
                int kc = nh*32 + na*8 + 2*ti;
                int colT = nt*64 + kc;
                float bb0 = b1s[colT], bb1 = b1s[colT+1];
                *(unsigned*)(sm2 + A2S + rA*144 + kc*2) =
                    pack2h(fmaxf(C1[na*4+0]+bb0, 0.f), fmaxf(C1[na*4+1]+bb1, 0.f));
                *(unsigned*)(sm2 + A2S + (rA+8)*144 + kc*2) =
                    pack2h(fmaxf(C1[na*4+2]+bb0, 0.f), fmaxf(C1[na*4+3]+bb1, 0.f));
            }
        }

        __syncthreads();
        if (nt < 11 && tid == 0) {
            MBAR_EXPECT_TX(sb + MBARS, W1BLK);
            BULK_LD(sb + B1S_, g_W1B + (size_t)(nt+1)*W1BLK, W1BLK, sb + MBARS);
        }

        MBAR_WAIT(sb + MBARS + 8, p2); p2 ^= 1;

        // GEMM2: 16 rows x 96 cols (N half)
        for (int p = 0; p < 2; p++) {
            unsigned ah0[4], ah1[4];
            ldsm_x4(ah0, a2addr + p*64);
            ldsm_x4(ah1, a2addr + p*64 + 32);
            #pragma unroll
            for (int grp = 0; grp < 3; grp++) {
                unsigned bf[4][4];
                #pragma unroll
                for (int j = 0; j < 4; j++)
                    ldsm_x4(bf[j], sb + B2S_ + (unsigned)((nh*96 + (grp*4+j)*8 + brow)*144 + p*64 + boff));
                float* Cg = C2 + grp*16;
                #pragma unroll
                for (int j = 0; j < 4; j++) mma16816(Cg + j*4, ah0, bf[j]);
                #pragma unroll
                for (int j = 0; j < 4; j++) mma16816(Cg + j*4, ah1, bf[j] + 2);
            }
        }
        __syncthreads();
        if (nt < 11 && tid == 0) {
            MBAR_EXPECT_TX(sb + MBARS + 8, W2BLK);
            BULK_LD(sb + B2S_, g_W2B + (size_t)(nt+1)*W2BLK, W2BLK, sb + MBARS + 8);
        }
    }

    {
        size_t rA = row0 + rg*16 + g;
        size_t rB = rA + 8;
        #pragma unroll
        for (int na = 0; na < 12; na++) {
            int col = nh*96 + na*8 + 2*ti;
            if (col < Cc) {
                float b20 = __ldg(b2 + col), b21 = __ldg(b2 + col + 1);
                out[rA*Cc + col]     = C2[na*4+0] + b20 + g_X2[rA*Cc + col];
                out[rA*Cc + col + 1] = C2[na*4+1] + b21 + g_X2[rA*Cc + col + 1];
                out[rB*Cc + col]     = C2[na*4+2] + b20 + g_X2[rB*Cc + col];
                out[rB*Cc + col + 1] = C2[na*4+3] + b21 + g_X2[rB*Cc + col + 1];
            }
        }
    }
}

// ============================================================================
// Launch
// ============================================================================
extern "C" void kernel_launch(void* const* d_in, const int* in_sizes, int n_in,
                              void* d_out, int out_size) {
    const float* x   = (const float*)d_in[0];
    const float* wq  = (const float*)d_in[1];
    const float* wk  = (const float*)d_in[2];
    const float* wv  = (const float*)d_in[3];
    const float* g1  = (const float*)d_in[4];
    const float* be1 = (const float*)d_in[5];
    const float* g2  = (const float*)d_in[6];
    const float* be2 = (const float*)d_in[7];
    const float* w1  = (const float*)d_in[8];
    const float* b1  = (const float*)d_in[9];
    const float* w2  = (const float*)d_in[10];
    const float* b2  = (const float*)d_in[11];
    float* out = (float*)d_out;

    cudaFuncSetAttribute(ln1qkv_kernel, cudaFuncAttributeMaxDynamicSharedMemorySize, SMQ_TOTAL);
    cudaFuncSetAttribute(attn2_kernel, cudaFuncAttributeMaxDynamicSharedMemorySize,
                         SMH_TOTAL * (int)sizeof(float));
    cudaFuncSetAttribute(mlp_kernel, cudaFuncAttributeMaxDynamicSharedMemorySize, SM2_TOTAL);

    prep_all<<<148, 256>>>(wq, wk, wv, w1, w2);
    ln1qkv_kernel<<<ROWS / 128, NTK, SMQ_TOTAL>>>(x, g1, be1);
    dim3 agrid(Bb, 3);
    attn2_kernel<<<agrid, 64, SMH_TOTAL * sizeof(float)>>>(x);
    mlp_kernel<<<ROWS / 128, NTK, SM2_TOTAL>>>(g2, be2, b1, b2, out);
}

// round 13
// speedup vs baseline: 3.5356x; 1.0578x over previous
#include <cuda_runtime.h>
#include <cuda_fp16.h>
#include <math.h>
#include <stdint.h>

#define Bb 4096
#define Tt 32
#define Cc 180
#define Hh 6
#define HDd 30
#define Ff 720
#define EPS 1e-5f
#define ROWS (Bb*Tt)
#define NQ 576

#define QBLK  25600
#define W1BLK 25600
#define W2BLK 27648

// ============================================================================
// Device scratch
// ============================================================================
__device__ float g_X2[(size_t)ROWS * Cc];
__device__ float g_QKVS[(size_t)ROWS * NQ];
__device__ __align__(16) char g_WQB[9  * QBLK];
__device__ __align__(16) char g_W1B[12 * W1BLK];
__device__ __align__(16) char g_W2B[12 * W2BLK];

// ============================================================================
// helpers
// ============================================================================
__device__ __forceinline__ unsigned smem_u32(const void* p) {
    unsigned a;
    asm("{ .reg .u64 t; cvta.to.shared.u64 t, %1; cvt.u32.u64 %0, t; }" : "=r"(a) : "l"(p));
    return a;
}
__device__ __forceinline__ void ldsm_x4(unsigned* r, unsigned addr) {
    asm volatile("ldmatrix.sync.aligned.m8n8.x4.shared.b16 {%0,%1,%2,%3}, [%4];"
                 : "=r"(r[0]), "=r"(r[1]), "=r"(r[2]), "=r"(r[3]) : "r"(addr));
}
__device__ __forceinline__ void mma16816(float* c, const unsigned* a, const unsigned* b) {
    asm volatile(
        "mma.sync.aligned.m16n8k16.row.col.f32.f16.f16.f32 "
        "{%0,%1,%2,%3}, {%4,%5,%6,%7}, {%8,%9}, {%0,%1,%2,%3};"
        : "+f"(c[0]), "+f"(c[1]), "+f"(c[2]), "+f"(c[3])
        : "r"(a[0]), "r"(a[1]), "r"(a[2]), "r"(a[3]), "r"(b[0]), "r"(b[1]));
}
__device__ __forceinline__ unsigned pack2h(float v0, float v1) {
    __half2 h = __halves2half2(__float2half_rn(v0), __float2half_rn(v1));
    return *reinterpret_cast<unsigned*>(&h);
}
#define MBAR_INIT(mb, c) \
    asm volatile("mbarrier.init.shared.b64 [%0], %1;" :: "r"((unsigned)(mb)), "r"((unsigned)(c)) : "memory")
#define MBAR_EXPECT_TX(mb, tx) \
    asm volatile("mbarrier.arrive.expect_tx.shared.b64 _, [%0], %1;" :: "r"((unsigned)(mb)), "r"((unsigned)(tx)) : "memory")
#define MBAR_WAIT(mb, par) do { \
    unsigned _m = (unsigned)(mb); unsigned _p = (unsigned)(par); unsigned _d; \
    asm volatile("{\n\t.reg .pred p;\n\t" \
        "mbarrier.try_wait.parity.acquire.cta.shared::cta.b64 p, [%1], %2;\n\t" \
        "selp.b32 %0, 1, 0, p;\n\t}" : "=r"(_d) : "r"(_m), "r"(_p) : "memory"); \
    if (!_d) { \
        asm volatile("{\n\t.reg .pred P1;\n\t" \
            "WL_%=:\n\t" \
            "mbarrier.try_wait.parity.acquire.cta.shared::cta.b64 P1, [%0], %1, 0x989680;\n\t" \
            "@P1 bra.uni WD_%=;\n\t" \
            "bra.uni WL_%=;\n\t" \
            "WD_%=:\n\t}" :: "r"(_m), "r"(_p) : "memory"); \
    } } while (0)
#define BULK_LD(dst, src, sz, mb) \
    asm volatile("cp.async.bulk.shared::cluster.global.mbarrier::complete_tx::bytes [%0], [%1], %2, [%3];" \
                 :: "r"((unsigned)(dst)), "l"(src), "r"((unsigned)(sz)), "r"((unsigned)(mb)) : "memory")

// ============================================================================
// Prep
// ============================================================================
__global__ void prep_all(const float* __restrict__ wq, const float* __restrict__ wk,
                         const float* __restrict__ wv, const float* __restrict__ w1,
                         const float* __restrict__ w2) {
    const int NWQ = NQ * 192, NW1 = 768 * 192, NW2 = 192 * 768;
    for (int i = blockIdx.x * blockDim.x + threadIdx.x; i < NWQ + NW1 + NW2;
         i += gridDim.x * blockDim.x) {
        float v = 0.f;
        char* p;
        if (i < NWQ) {
            int n = i / 192, k = i % 192;
            if (n < 540 && k < Cc) {
                int mat = n / Cc, m = n % Cc;
                int hh = m / HDd, d = m % HDd;
                const float* W = (mat == 0 ? wq : (mat == 1 ? wk : wv));
                v = W[(size_t)hh * (Cc*HDd) + (size_t)k * HDd + d];
            }
            p = g_WQB + (n >> 6) * QBLK + (n & 63) * 400 + k * 2;
        } else if (i < NWQ + NW1) {
            int j = i - NWQ;
            int n = j / 192, k = j % 192;
            if (n < Ff && k < Cc) v = w1[(size_t)k * Ff + n];
            p = g_W1B + (n >> 6) * W1BLK + (n & 63) * 400 + k * 2;
        } else {
            int j = i - NWQ - NW1;
            int n = j / 768, k = j % 768;
            if (n < Cc && k < Ff) v = w2[(size_t)k * Cc + n];
            p = g_W2B + (k >> 6) * W2BLK + n * 144 + (k & 63) * 2;
        }
        *(__half*)p = __float2half_rn(v);
    }
}

// ============================================================================
// Kernel 1: LN1 + QKV GEMM — 64 rows/CTA, 256 thr, 2 CTAs/SM
// ============================================================================
#define NTK 256
#define QA1   0
#define QB0   25600
#define QB1   51200
#define QBAR  76800
#define SMQ_TOTAL 76928

__global__ void __launch_bounds__(NTK, 2) ln1qkv_kernel(
    const float* __restrict__ x,
    const float* __restrict__ g1, const float* __restrict__ be1)
{
    extern __shared__ char sm2[];
    const unsigned sb = smem_u32(sm2);
    const int tid = threadIdx.x;
    const int w   = tid >> 5;
    const int ln  = tid & 31;
    const int g   = ln >> 2;
    const int ti  = ln & 3;
    const int rg  = w & 3;          // row group (16 rows of 64)
    const int nh  = w >> 2;         // N half
    const size_t row0 = (size_t)blockIdx.x * 64;

    if (tid == 0) { MBAR_INIT(sb + QBAR, 1); MBAR_INIT(sb + QBAR + 8, 1); }
    __syncthreads();
    if (tid == 0) {
        MBAR_EXPECT_TX(sb + QBAR, QBLK);
        BULK_LD(sb + QB0, g_WQB, QBLK, sb + QBAR);
    }

    // ---- LN1 -> fp16 A ----
    for (int r = w; r < 64; r += 8) {
        const float* xr = x + (row0 + r) * Cc;
        float s = 0.f, s2 = 0.f;
        for (int c = ln; c < Cc; c += 32) { float v = xr[c]; s += v; s2 += v*v; }
        #pragma unroll
        for (int o = 16; o; o >>= 1) {
            s  += __shfl_xor_sync(0xffffffffu, s,  o);
            s2 += __shfl_xor_sync(0xffffffffu, s2, o);
        }
        float mu = s * (1.f/Cc);
        float inv = rsqrtf(s2 * (1.f/Cc) - mu*mu + EPS);
        for (int cp = ln; cp < 96; cp += 32) {
            int c0 = cp * 2;
            float v0 = (c0   < Cc) ? (xr[c0]  -mu)*inv*g1[c0]   + be1[c0]   : 0.f;
            float v1 = (c0+1 < Cc) ? (xr[c0+1]-mu)*inv*g1[c0+1] + be1[c0+1] : 0.f;
            *(unsigned*)(sm2 + QA1 + r*400 + c0*2) = pack2h(v0, v1);
        }
    }
    __syncthreads();

    const unsigned a1addr = sb + QA1 + (unsigned)((rg*16 + (ln & 15))*400 + (ln >> 4)*16);
    const int brow = ln & 7;
    const int boff = ((ln >> 3) & 3) * 16;

    int ph0 = 0, ph1 = 0;
    for (int nt = 0; nt < 9; nt++) {
        const int c = nt & 1;
        MBAR_WAIT(sb + QBAR + 8*c, (c ? ph1 : ph0));
        if (c) ph1 ^= 1; else ph0 ^= 1;
        __syncthreads();
        if (nt < 8 && tid == 0) {
            MBAR_EXPECT_TX(sb + QBAR + 8*(c^1), QBLK);
            BULK_LD(sb + (c ? QB0 : QB1), g_WQB + (size_t)(nt+1)*QBLK, QBLK, sb + QBAR + 8*(c^1));
        }

        const unsigned bbase = sb + (c ? QB1 : QB0);
        float C1[16];
        #pragma unroll
        for (int i = 0; i < 16; i++) C1[i] = 0.f;
        for (int p = 0; p < 6; p++) {
            unsigned ah0[4], ah1[4];
            ldsm_x4(ah0, a1addr + p*64);
            ldsm_x4(ah1, a1addr + p*64 + 32);
            unsigned bf[4][4];
            #pragma unroll
            for (int na = 0; na < 4; na++)
                ldsm_x4(bf[na], bbase + (unsigned)((nh*32 + na*8 + brow)*400 + p*64 + boff));
            #pragma unroll
            for (int na = 0; na < 4; na++) mma16816(C1 + na*4, ah0, bf[na]);
            #pragma unroll
            for (int na = 0; na < 4; na++) mma16816(C1 + na*4, ah1, bf[na] + 2);
        }

        {
            size_t rA = row0 + rg*16 + g;
            size_t rB = rA + 8;
            #pragma unroll
            for (int na = 0; na < 4; na++) {
                int col = nt*64 + nh*32 + na*8 + 2*ti;
                *(float2*)(g_QKVS + rA*NQ + col) = make_float2(C1[na*4+0], C1[na*4+1]);
                *(float2*)(g_QKVS + rB*NQ + col) = make_float2(C1[na*4+2], C1[na*4+3]);
            }
        }
    }
}

// ============================================================================
// Kernel 2: softmax + A@V + residual — lane-per-row (R11, proven)
// ============================================================================
#define PD32 32
#define SMH_TOTAL (6*Tt*PD32)

__global__ void __launch_bounds__(64, 8) attn2_kernel(const float* __restrict__ x)
{
    extern __shared__ float sm[];
    const int b   = blockIdx.x;
    const int hp  = blockIdx.y;
    const int tid = threadIdx.x;
    const int wi  = tid >> 5;
    const int ln  = tid & 31;

    const float* base = g_QKVS + (size_t)b * (Tt*NQ);
    #pragma unroll
    for (int m = 0; m < 3; m++) {
        float* dst = sm + m * (2*Tt*PD32);
        for (int e = tid; e < 2*Tt*HDd; e += 64) {
            int hl = e / (Tt*HDd);
            int rem = e - hl*(Tt*HDd);
            int r = rem / HDd, d = rem - r*HDd;
            dst[hl*(Tt*PD32) + r*PD32 + d] = base[(size_t)r*NQ + m*Cc + (hp*2+hl)*HDd + d];
        }
    }
    __syncthreads();

    const float* qsw = sm + 0*(2*Tt*PD32) + wi*(Tt*PD32);
    const float* ksw = sm + 1*(2*Tt*PD32) + wi*(Tt*PD32);
    const float* vsw = sm + 2*(2*Tt*PD32) + wi*(Tt*PD32);

    float q[HDd];
    #pragma unroll
    for (int d = 0; d < HDd; d++) q[d] = qsw[ln*PD32 + d];

    float sc[Tt];
    #pragma unroll 4
    for (int tj = 0; tj < Tt; tj++) {
        const float4* kr = (const float4*)(ksw + tj*PD32);
        float dot = 0.f;
        #pragma unroll
        for (int i = 0; i < 7; i++) {
            float4 kv = kr[i];
            dot += q[4*i+0]*kv.x + q[4*i+1]*kv.y + q[4*i+2]*kv.z + q[4*i+3]*kv.w;
        }
        dot += q[28]*ksw[tj*PD32+28] + q[29]*ksw[tj*PD32+29];
        sc[tj] = dot * 0.18257418583505537f;
    }

    float m = -1e30f;
    #pragma unroll
    for (int tj = 0; tj < Tt; tj++) if (tj <= ln) m = fmaxf(m, sc[tj]);
    float sum = 0.f;
    #pragma unroll
    for (int tj = 0; tj < Tt; tj++) {
        float e = (tj <= ln) ? __expf(sc[tj] - m) : 0.f;
        sc[tj] = e;
        sum += e;
    }
    float inv = 1.f / sum;

    float acc[HDd];
    #pragma unroll
    for (int d = 0; d < HDd; d++) acc[d] = 0.f;
    #pragma unroll 4
    for (int tj = 0; tj < Tt; tj++) {
        float p = sc[tj] * inv;
        const float4* vr = (const float4*)(vsw + tj*PD32);
        #pragma unroll
        for (int i = 0; i < 7; i++) {
            float4 vv = vr[i];
            acc[4*i+0] += p*vv.x; acc[4*i+1] += p*vv.y;
            acc[4*i+2] += p*vv.z; acc[4*i+3] += p*vv.w;
        }
        acc[28] += p*vsw[tj*PD32+28];
        acc[29] += p*vsw[tj*PD32+29];
    }

    {
        size_t off = ((size_t)b*Tt + ln) * Cc + (hp*2 + wi)*HDd;
        const float* xr = x + off;
        float* og = g_X2 + off;
        #pragma unroll
        for (int d = 0; d < HDd; d++) og[d] = xr[d] + acc[d];
    }
}

// ============================================================================
// Kernel 3: LN2 + MLP — 64 rows/CTA, 256 thr, 2 CTAs/SM
// ============================================================================
#define A1S   0
#define A2S   25600     // 64 x 144B = 9216
#define B1S_  34816     // 25600
#define B2S_  60416     // 27648
#define MBARS 88064
#define BIAS  88080     // float[768]
#define SM2_TOTAL 91152

__global__ void __launch_bounds__(NTK, 2) mlp_kernel(
    const float* __restrict__ g2, const float* __restrict__ be2,
    const float* __restrict__ b1, const float* __restrict__ b2,
    float* __restrict__ out)
{
    extern __shared__ char sm2[];
    const unsigned sb = smem_u32(sm2);
    const int tid = threadIdx.x;
    const int w   = tid >> 5;
    const int ln  = tid & 31;
    const int g   = ln >> 2;
    const int ti  = ln & 3;
    const int rg  = w & 3;
    const int nh  = w >> 2;
    const size_t row0 = (size_t)blockIdx.x * 64;
    float* b1s = (float*)(sm2 + BIAS);

    if (tid == 0) { MBAR_INIT(sb + MBARS, 1); MBAR_INIT(sb + MBARS + 8, 1); }
    __syncthreads();
    if (tid == 0) {
        MBAR_EXPECT_TX(sb + MBARS, W1BLK);
        BULK_LD(sb + B1S_, g_W1B, W1BLK, sb + MBARS);
        MBAR_EXPECT_TX(sb + MBARS + 8, W2BLK);
        BULK_LD(sb + B2S_, g_W2B, W2BLK, sb + MBARS + 8);
    }

    for (int i = tid; i < 768; i += NTK) b1s[i] = (i < Ff) ? b1[i] : 0.f;

    // ---- LN2 -> fp16 A1 ----
    for (int r = w; r < 64; r += 8) {
        const float* xr = g_X2 + (row0 + r) * Cc;
        float s = 0.f, s2 = 0.f;
        for (int c = ln; c < Cc; c += 32) { float v = xr[c]; s += v; s2 += v*v; }
        #pragma unroll
        for (int o = 16; o; o >>= 1) {
            s  += __shfl_xor_sync(0xffffffffu, s,  o);
            s2 += __shfl_xor_sync(0xffffffffu, s2, o);
        }
        float mu = s * (1.f/Cc);
        float inv = rsqrtf(s2 * (1.f/Cc) - mu*mu + EPS);
        for (int cp = ln; cp < 96; cp += 32) {
            int c0 = cp * 2;
            float v0 = (c0   < Cc) ? (xr[c0]  -mu)*inv*g2[c0]   + be2[c0]   : 0.f;
            float v1 = (c0+1 < Cc) ? (xr[c0+1]-mu)*inv*g2[c0+1] + be2[c0+1] : 0.f;
            *(unsigned*)(sm2 + A1S + r*400 + c0*2) = pack2h(v0, v1);
        }
    }
    __syncthreads();

    float C2[48];
    #pragma unroll
    for (int i = 0; i < 48; i++) C2[i] = 0.f;

    const unsigned a1addr = sb + A1S + (unsigned)((rg*16 + (ln & 15))*400 + (ln >> 4)*16);
    const unsigned a2addr = sb + A2S + (unsigned)((rg*16 + (ln & 15))*144 + (ln >> 4)*16);
    const int brow = ln & 7;
    const int boff = ((ln >> 3) & 3) * 16;

    int p1 = 0, p2 = 0;
    for (int nt = 0; nt < 12; nt++) {
        MBAR_WAIT(sb + MBARS, p1); p1 ^= 1;

        float C1[16];
        #pragma unroll
        for (int i = 0; i < 16; i++) C1[i] = 0.f;
        for (int p = 0; p < 6; p++) {
            unsigned ah0[4], ah1[4];
            ldsm_x4(ah0, a1addr + p*64);
            ldsm_x4(ah1, a1addr + p*64 + 32);
            unsigned bf[4][4];
            #pragma unroll
            for (int na = 0; na < 4; na++)
                ldsm_x4(bf[na], sb + B1S_ + (unsigned)((nh*32 + na*8 + brow)*400 + p*64 + boff));
            #pragma unroll
            for (int na = 0; na < 4; na++) mma16816(C1 + na*4, ah0, bf[na]);
            #pragma unroll
            for (int na = 0; na < 4; na++) mma16816(C1 + na*4, ah1, bf[na] + 2);
        }

        // epilogue1: bias + relu -> fp16 A2 smem
        {
            int rA = rg*16 + g;
            #pragma unroll
            for (int na = 0; na < 4; na++) {
                int kc = nh*32 + na*8 + 2*ti;
                int colT = nt*64 + kc;
                float bb0 = b1s[colT], bb1 = b1s[colT+1];
                *(unsigned*)(sm2 + A2S + rA*144 + kc*2) =
                    pack2h(fmaxf(C1[na*4+0]+bb0, 0.f), fmaxf(C1[na*4+1]+bb1, 0.f));
                *(unsigned*)(sm2 + A2S + (rA+8)*144 + kc*2) =
                    pack2h(fmaxf(C1[na*4+2]+bb0, 0.f), fmaxf(C1[na*4+3]+bb1, 0.f));
            }
        }

        __syncthreads();
        if (nt < 11 && tid == 0) {
            MBAR_EXPECT_TX(sb + MBARS, W1BLK);
            BULK_LD(sb + B1S_, g_W1B + (size_t)(nt+1)*W1BLK, W1BLK, sb + MBARS);
        }

        MBAR_WAIT(sb + MBARS + 8, p2); p2 ^= 1;

        // GEMM2: 16 rows x 96 cols (N half)
        for (int p = 0; p < 2; p++) {
            unsigned ah0[4], ah1[4];
            ldsm_x4(ah0, a2addr + p*64);
            ldsm_x4(ah1, a2addr + p*64 + 32);
            #pragma unroll
            for (int grp = 0; grp < 3; grp++) {
                unsigned bf[4][4];
                #pragma unroll
                for (int j = 0; j < 4; j++)
                    ldsm_x4(bf[j], sb + B2S_ + (unsigned)((nh*96 + (grp*4+j)*8 + brow)*144 + p*64 + boff));
                float* Cg = C2 + grp*16;
                #pragma unroll
                for (int j = 0; j < 4; j++) mma16816(Cg + j*4, ah0, bf[j]);
                #pragma unroll
                for (int j = 0; j < 4; j++) mma16816(Cg + j*4, ah1, bf[j] + 2);
            }
        }
        __syncthreads();
        if (nt < 11 && tid == 0) {
            MBAR_EXPECT_TX(sb + MBARS + 8, W2BLK);
            BULK_LD(sb + B2S_, g_W2B + (size_t)(nt+1)*W2BLK, W2BLK, sb + MBARS + 8);
        }
    }

    {
        size_t rA = row0 + rg*16 + g;
        size_t rB = rA + 8;
        #pragma unroll
        for (int na = 0; na < 12; na++) {
            int col = nh*96 + na*8 + 2*ti;
            if (col < Cc) {
                float b20 = __ldg(b2 + col), b21 = __ldg(b2 + col + 1);
                out[rA*Cc + col]     = C2[na*4+0] + b20 + g_X2[rA*Cc + col];
                out[rA*Cc + col + 1] = C2[na*4+1] + b21 + g_X2[rA*Cc + col + 1];
                out[rB*Cc + col]     = C2[na*4+2] + b20 + g_X2[rB*Cc + col];
                out[rB*Cc + col + 1] = C2[na*4+3] + b21 + g_X2[rB*Cc + col + 1];
            }
        }
    }
}

// ============================================================================
// Launch
// ============================================================================
extern "C" void kernel_launch(void* const* d_in, const int* in_sizes, int n_in,
                              void* d_out, int out_size) {
    const float* x   = (const float*)d_in[0];
    const float* wq  = (const float*)d_in[1];
    const float* wk  = (const float*)d_in[2];
    const float* wv  = (const float*)d_in[3];
    const float* g1  = (const float*)d_in[4];
    const float* be1 = (const float*)d_in[5];
    const float* g2  = (const float*)d_in[6];
    const float* be2 = (const float*)d_in[7];
    const float* w1  = (const float*)d_in[8];
    const float* b1  = (const float*)d_in[9];
    const float* w2  = (const float*)d_in[10];
    const float* b2  = (const float*)d_in[11];
    float* out = (float*)d_out;

    cudaFuncSetAttribute(ln1qkv_kernel, cudaFuncAttributeMaxDynamicSharedMemorySize, SMQ_TOTAL);
    cudaFuncSetAttribute(attn2_kernel, cudaFuncAttributeMaxDynamicSharedMemorySize,
                         SMH_TOTAL * (int)sizeof(float));
    cudaFuncSetAttribute(mlp_kernel, cudaFuncAttributeMaxDynamicSharedMemorySize, SM2_TOTAL);

    prep_all<<<148, 256>>>(wq, wk, wv, w1, w2);
    ln1qkv_kernel<<<ROWS / 64, NTK, SMQ_TOTAL>>>(x, g1, be1);
    dim3 agrid(Bb, 3);
    attn2_kernel<<<agrid, 64, SMH_TOTAL * sizeof(float)>>>(x);
    mlp_kernel<<<ROWS / 64, NTK, SM2_TOTAL>>>(g2, be2, b1, b2, out);
}